// round 1
// baseline (speedup 1.0000x reference)
#include <cuda_runtime.h>
#include <math.h>
#include <stdint.h>

#define B_   4
#define H_   8
#define L_   4096
#define D_   64
#define DM_  512
#define NS_  27
#define BH_  (B_*H_)
#define BL_  (B_*L_)

// ---------------- scratch (device globals; no runtime alloc) ----------------
__device__ float g_Q[BH_*L_*D_];
__device__ float g_K[BH_*L_*D_];
__device__ float g_V[BH_*L_*D_];
__device__ float g_ctx[(size_t)BL_*DM_];
__device__ float g_x1[(size_t)BL_*DM_];   // xp2
__device__ float g_x2[(size_t)BL_*DM_];   // xd2
__device__ float g_M[BH_*L_];
__device__ float g_S[(size_t)BH_*NS_*L_];
__device__ float g_outtop[BH_*NS_*D_];
__device__ float g_meanV[BH_*D_];
__device__ int   g_idxA[L_*NS_];
__device__ int   g_idxB[L_*NS_];
__device__ int   g_topidx[BH_*NS_];

// ---------------- Threefry-2x32 (JAX-exact) ----------------
__host__ __device__ inline void tf2x32(unsigned k0, unsigned k1,
                                       unsigned x0, unsigned x1,
                                       unsigned* o0, unsigned* o1) {
    unsigned ks0 = k0, ks1 = k1, ks2 = 0x1BD11BDAu ^ k0 ^ k1;
    x0 += ks0; x1 += ks1;
#define TF_RND(r) { x0 += x1; x1 = (x1 << (r)) | (x1 >> (32 - (r))); x1 ^= x0; }
    TF_RND(13) TF_RND(15) TF_RND(26) TF_RND(6)   x0 += ks1; x1 += ks2 + 1u;
    TF_RND(17) TF_RND(29) TF_RND(16) TF_RND(24)  x0 += ks2; x1 += ks0 + 2u;
    TF_RND(13) TF_RND(15) TF_RND(26) TF_RND(6)   x0 += ks0; x1 += ks1 + 3u;
    TF_RND(17) TF_RND(29) TF_RND(16) TF_RND(24)  x0 += ks1; x1 += ks2 + 4u;
    TF_RND(13) TF_RND(15) TF_RND(26) TF_RND(6)   x0 += ks2; x1 += ks0 + 5u;
#undef TF_RND
    *o0 = x0; *o1 = x1;
}

// idx[i] = (o0^o1) % 4096 for counter (0, i)  [partitionable random_bits]
__global__ void idx_kernel(unsigned k0, unsigned k1, int* __restrict__ out) {
    int i = blockIdx.x * blockDim.x + threadIdx.x;
    if (i >= L_*NS_) return;
    unsigned o0, o1;
    tf2x32(k0, k1, 0u, (unsigned)i, &o0, &o1);
    out[i] = (int)((o0 ^ o1) & 4095u);
}

// ---------------- SGEMM with bias: C = A(MxK) @ W(KxN) + b ----------------
// mode 0: scatter into (b,h,l,d) head-major QKV layout. mode 1: plain row-major.
#define BM 128
#define BN 128
#define BKK 16
__global__ __launch_bounds__(256)
void sgemm_bias(const float* __restrict__ A, const float* __restrict__ W,
                const float* __restrict__ bias, float* __restrict__ C, int mode) {
    const int K = DM_, N = DM_;
    __shared__ float As[BKK][BM];
    __shared__ float Bs[BKK][BN];
    int tid = threadIdx.x;
    int tx = tid & 15, ty = tid >> 4;
    int row0 = blockIdx.y * BM, col0 = blockIdx.x * BN;
    float acc[8][8];
#pragma unroll
    for (int i = 0; i < 8; i++)
#pragma unroll
        for (int j = 0; j < 8; j++) acc[i][j] = 0.f;

    for (int kt = 0; kt < K; kt += BKK) {
#pragma unroll
        for (int it = 0; it < 2; it++) {
            int fid = tid + it * 256;          // 0..511
            int r = fid >> 2, c4 = fid & 3;    // A tile: 128 rows x 4 float4
            float4 v = *(const float4*)(A + (size_t)(row0 + r) * K + kt + c4 * 4);
            As[c4*4+0][r] = v.x; As[c4*4+1][r] = v.y;
            As[c4*4+2][r] = v.z; As[c4*4+3][r] = v.w;
        }
#pragma unroll
        for (int it = 0; it < 2; it++) {
            int fid = tid + it * 256;
            int r = fid >> 5, c4 = fid & 31;   // B tile: 16 rows x 32 float4
            float4 v = *(const float4*)(W + (size_t)(kt + r) * N + col0 + c4 * 4);
            *(float4*)&Bs[r][c4 * 4] = v;
        }
        __syncthreads();
#pragma unroll
        for (int k = 0; k < BKK; k++) {
            float a[8], b[8];
            *(float4*)&a[0] = *(float4*)&As[k][ty*8];
            *(float4*)&a[4] = *(float4*)&As[k][ty*8+4];
            *(float4*)&b[0] = *(float4*)&Bs[k][tx*8];
            *(float4*)&b[4] = *(float4*)&Bs[k][tx*8+4];
#pragma unroll
            for (int i = 0; i < 8; i++)
#pragma unroll
                for (int j = 0; j < 8; j++) acc[i][j] += a[i] * b[j];
        }
        __syncthreads();
    }

    int n0 = col0 + tx * 8;
    float bb[8];
#pragma unroll
    for (int j = 0; j < 8; j++) bb[j] = bias[n0 + j];

#pragma unroll
    for (int i = 0; i < 8; i++) {
        int m = row0 + ty * 8 + i;
        float4 v0 = make_float4(acc[i][0]+bb[0], acc[i][1]+bb[1], acc[i][2]+bb[2], acc[i][3]+bb[3]);
        float4 v1 = make_float4(acc[i][4]+bb[4], acc[i][5]+bb[5], acc[i][6]+bb[6], acc[i][7]+bb[7]);
        if (mode == 0) {
            int b = m >> 12, l = m & 4095;
            int h = n0 >> 6, d0 = n0 & 63;      // 8 | 64 so h constant over j
            float* dst = C + (((size_t)(b * H_ + h) * L_) + l) * D_ + d0;
            *(float4*)dst = v0; *(float4*)(dst + 4) = v1;
        } else {
            float* dst = C + (size_t)m * DM_ + n0;
            *(float4*)dst = v0; *(float4*)(dst + 4) = v1;
        }
    }
}

// ---------------- M[bh][l] = max_s(q·k_s) - sum_s(q·k_s)/L ----------------
__global__ __launch_bounds__(256)
void sample_m_kernel(const int* __restrict__ idx) {
    int gw = (blockIdx.x * blockDim.x + threadIdx.x) >> 5;
    int lane = threadIdx.x & 31;
    if (gw >= BH_ * L_) return;
    int bh = gw >> 12, l = gw & 4095;
    const float4* qrow = (const float4*)(g_Q + ((size_t)bh * L_ + l) * D_);
    float val = 0.f;
    bool active = lane < NS_;
    if (active) {
        int kk = idx[l * NS_ + lane];
        const float4* krow = (const float4*)(g_K + ((size_t)bh * L_ + kk) * D_);
        float s = 0.f;
#pragma unroll
        for (int d4 = 0; d4 < 16; d4++) {
            float4 q = qrow[d4], k = krow[d4];
            s += q.x*k.x + q.y*k.y + q.z*k.z + q.w*k.w;
        }
        val = s;
    }
    float mx = active ? val : -__int_as_float(0x7f800000);
    float sm = active ? val : 0.f;
#pragma unroll
    for (int off = 16; off > 0; off >>= 1) {
        mx = fmaxf(mx, __shfl_down_sync(0xffffffffu, mx, off));
        sm += __shfl_down_sync(0xffffffffu, sm, off);
    }
    if (lane == 0) g_M[gw] = mx - sm * (1.f / (float)L_);
}

// ---------------- top-27 (descending, lower-index tiebreak) ----------------
__global__ __launch_bounds__(256)
void topk_kernel() {
    int bh = blockIdx.x, t = threadIdx.x;
    __shared__ float sm[L_];
    __shared__ float rv[256];
    __shared__ int   ri[256];
    for (int i = t; i < L_; i += 256) sm[i] = g_M[(size_t)bh * L_ + i];
    __syncthreads();
    for (int it = 0; it < NS_; it++) {
        float best = -__int_as_float(0x7f800000);
        int bi = 0x7fffffff;
        for (int i = t; i < L_; i += 256) {
            float v = sm[i];
            if (v > best) { best = v; bi = i; }
        }
        rv[t] = best; ri[t] = bi;
        __syncthreads();
        for (int s = 128; s > 0; s >>= 1) {
            if (t < s) {
                if (rv[t+s] > rv[t] || (rv[t+s] == rv[t] && ri[t+s] < ri[t])) {
                    rv[t] = rv[t+s]; ri[t] = ri[t+s];
                }
            }
            __syncthreads();
        }
        if (t == 0) { g_topidx[bh * NS_ + it] = ri[0]; sm[ri[0]] = -__int_as_float(0x7f800000); }
        __syncthreads();
    }
}

// ---------------- meanV[bh][d] ----------------
__global__ __launch_bounds__(256)
void meanv_kernel() {
    int bh = blockIdx.x, t = threadIdx.x;
    int d = t & 63, c = t >> 6;
    float s = 0.f;
    for (int l = c; l < L_; l += 4) s += g_V[((size_t)bh * L_ + l) * D_ + d];
    __shared__ float red[256];
    red[t] = s; __syncthreads();
    if (c == 0) g_meanV[bh * D_ + d] = (red[d] + red[64+d] + red[128+d] + red[192+d]) * (1.f / (float)L_);
}

// ---------------- scores S[bh][u][k] = 0.125 * Q[top_u]·K[k] ----------------
__global__ __launch_bounds__(128)
void scores_kernel() {
    int bh = blockIdx.x, kt = blockIdx.y, t = threadIdx.x;
    __shared__ float Qs[NS_][64];
    __shared__ float KsT[64][129];
    for (int f = t; f < NS_ * 16; f += 128) {
        int u = f >> 4, d4 = f & 15;
        int l = g_topidx[bh * NS_ + u];
        *(float4*)&Qs[u][d4 * 4] = *(const float4*)(g_Q + ((size_t)bh * L_ + l) * D_ + d4 * 4);
    }
    for (int f = t; f < 128 * 16; f += 128) {
        int kk = f >> 4, d4 = f & 15;
        float4 v = *(const float4*)(g_K + ((size_t)bh * L_ + kt * 128 + kk) * D_ + d4 * 4);
        KsT[d4*4+0][kk] = v.x; KsT[d4*4+1][kk] = v.y;
        KsT[d4*4+2][kk] = v.z; KsT[d4*4+3][kk] = v.w;
    }
    __syncthreads();
    float acc[NS_];
#pragma unroll
    for (int u = 0; u < NS_; u++) acc[u] = 0.f;
    int kk = t;
#pragma unroll
    for (int d0 = 0; d0 < 64; d0 += 4) {
        float k0 = KsT[d0][kk], k1 = KsT[d0+1][kk], k2 = KsT[d0+2][kk], k3 = KsT[d0+3][kk];
#pragma unroll
        for (int u = 0; u < NS_; u++) {
            float4 q = *(const float4*)&Qs[u][d0];
            acc[u] += q.x*k0 + q.y*k1 + q.z*k2 + q.w*k3;
        }
    }
#pragma unroll
    for (int u = 0; u < NS_; u++)
        g_S[((size_t)bh * NS_ + u) * L_ + kt * 128 + kk] = acc[u] * 0.125f;
}

// ---------------- softmax over each S row (in place) ----------------
__global__ __launch_bounds__(256)
void softmax_kernel() {
    int row = blockIdx.x, t = threadIdx.x;
    float* p = g_S + (size_t)row * L_;
    __shared__ float sm[L_];
    __shared__ float red[256];
    float mx = -__int_as_float(0x7f800000);
    for (int i = t; i < L_; i += 256) { float v = p[i]; sm[i] = v; mx = fmaxf(mx, v); }
    red[t] = mx; __syncthreads();
    for (int s = 128; s > 0; s >>= 1) { if (t < s) red[t] = fmaxf(red[t], red[t+s]); __syncthreads(); }
    float m = red[0];
    __syncthreads();
    float ss = 0.f;
    for (int i = t; i < L_; i += 256) { float e = expf(sm[i] - m); sm[i] = e; ss += e; }
    red[t] = ss; __syncthreads();
    for (int s = 128; s > 0; s >>= 1) { if (t < s) red[t] += red[t+s]; __syncthreads(); }
    float inv = 1.f / red[0];
    for (int i = t; i < L_; i += 256) p[i] = sm[i] * inv;
}

// ---------------- out_top[bh][u][d] += P[u][k] * V[k][d] (split-k) ---------
__global__ __launch_bounds__(256)
void pv_kernel() {
    int bh = blockIdx.x, kc = blockIdx.y, t = threadIdx.x;
    int d = t & 63, ug = t >> 6;
    float acc[7];
#pragma unroll
    for (int j = 0; j < 7; j++) acc[j] = 0.f;
    int k0 = kc * 512;
    for (int k = k0; k < k0 + 512; k += 4) {
        float v0 = g_V[((size_t)bh * L_ + k + 0) * D_ + d];
        float v1 = g_V[((size_t)bh * L_ + k + 1) * D_ + d];
        float v2 = g_V[((size_t)bh * L_ + k + 2) * D_ + d];
        float v3 = g_V[((size_t)bh * L_ + k + 3) * D_ + d];
#pragma unroll
        for (int j = 0; j < 7; j++) {
            int u = ug + j * 4;
            if (u < NS_) {
                float4 pv = *(const float4*)(g_S + ((size_t)bh * NS_ + u) * L_ + k);
                acc[j] += pv.x*v0 + pv.y*v1 + pv.z*v2 + pv.w*v3;
            }
        }
    }
#pragma unroll
    for (int j = 0; j < 7; j++) {
        int u = ug + j * 4;
        if (u < NS_) atomicAdd(&g_outtop[(bh * NS_ + u) * D_ + d], acc[j]);
    }
}

// ---------------- ctx fill (mean) + scatter (top rows) ----------------
__global__ __launch_bounds__(256)
void ctx_fill_kernel() {
    int i4 = blockIdx.x * blockDim.x + threadIdx.x;   // over float4
    if (i4 >= BL_ * DM_ / 4) return;
    int n4 = i4 & 127;                 // column /4 within 512
    int b = i4 / (L_ * 128);
    ((float4*)g_ctx)[i4] = ((const float4*)g_meanV)[b * 128 + n4];
}

__global__ __launch_bounds__(256)
void ctx_scatter_kernel() {
    int i = blockIdx.x * blockDim.x + threadIdx.x;
    if (i >= BH_ * NS_ * D_) return;
    int d = i & 63;
    int u = (i >> 6) % NS_;
    int bh = i / (NS_ * D_);
    int b = bh >> 3, h = bh & 7;
    int l = g_topidx[bh * NS_ + u];
    g_ctx[((size_t)(b * L_) + l) * DM_ + h * D_ + d] = g_outtop[i];
}

// ---------------- final: out = xs + concat(xd2, xp2) ----------------
__global__ __launch_bounds__(256)
void final_add_kernel(const float* __restrict__ xs, float* __restrict__ out) {
    int i4 = blockIdx.x * blockDim.x + threadIdx.x;   // over float4, 4*8192*512/4
    int c4 = i4 & 127;
    int l = (i4 >> 7) & 8191;
    int b = i4 >> 20;                                  // /(8192*128)
    float4 a = ((const float4*)xs)[i4];
    float4 s;
    if (l < L_) s = ((const float4*)g_x2)[((size_t)b * L_ + l) * 128 + c4];
    else        s = ((const float4*)g_x1)[((size_t)b * L_ + (l - L_)) * 128 + c4];
    a.x += s.x; a.y += s.y; a.z += s.z; a.w += s.w;
    ((float4*)out)[i4] = a;
}

// ---------------- host orchestration ----------------
struct Ptrs {
    float *Q, *K, *V, *ctx, *x1, *x2, *outtop;
    int *idxA, *idxB;
};

static void run_layer(const float* xq, const float* xkv,
                      const float* wq, const float* wk, const float* wv, const float* wo,
                      const float* bq, const float* bk, const float* bv, const float* bo,
                      const int* idx, float* dst, const Ptrs& p) {
    dim3 ggrid(DM_ / BN, BL_ / BM);
    sgemm_bias<<<ggrid, 256>>>(xq,  wq, bq, p.Q, 0);
    sgemm_bias<<<ggrid, 256>>>(xkv, wk, bk, p.K, 0);
    sgemm_bias<<<ggrid, 256>>>(xkv, wv, bv, p.V, 0);
    sample_m_kernel<<<(BH_ * L_) / 8, 256>>>(idx);
    topk_kernel<<<BH_, 256>>>();
    meanv_kernel<<<BH_, 256>>>();
    cudaMemsetAsync(p.outtop, 0, (size_t)BH_ * NS_ * D_ * sizeof(float));
    scores_kernel<<<dim3(BH_, L_ / 128), 128>>>();
    softmax_kernel<<<BH_ * NS_, 256>>>();
    pv_kernel<<<dim3(BH_, 8), 256>>>();
    ctx_fill_kernel<<<(BL_ * DM_ / 4) / 256, 256>>>();
    ctx_scatter_kernel<<<(BH_ * NS_ * D_) / 256, 256>>>();
    sgemm_bias<<<ggrid, 256>>>(p.ctx, wo, bo, dst, 1);
}

extern "C" void kernel_launch(void* const* d_in, const int* in_sizes, int n_in,
                              void* d_out, int out_size) {
    const float* xs  = (const float*)d_in[0];
    const float* xd  = (const float*)d_in[1];
    const float* xp  = (const float*)d_in[2];
    const float* w0q = (const float*)d_in[3];
    const float* w0k = (const float*)d_in[4];
    const float* w0v = (const float*)d_in[5];
    const float* w0o = (const float*)d_in[6];
    const float* b0q = (const float*)d_in[7];
    const float* b0k = (const float*)d_in[8];
    const float* b0v = (const float*)d_in[9];
    const float* b0o = (const float*)d_in[10];
    const float* w1q = (const float*)d_in[11];
    const float* w1k = (const float*)d_in[12];
    const float* w1v = (const float*)d_in[13];
    const float* w1o = (const float*)d_in[14];
    const float* b1q = (const float*)d_in[15];
    const float* b1k = (const float*)d_in[16];
    const float* b1v = (const float*)d_in[17];
    const float* b1o = (const float*)d_in[18];
    float* out = (float*)d_out;

    Ptrs p;
    cudaGetSymbolAddress((void**)&p.Q, g_Q);
    cudaGetSymbolAddress((void**)&p.K, g_K);
    cudaGetSymbolAddress((void**)&p.V, g_V);
    cudaGetSymbolAddress((void**)&p.ctx, g_ctx);
    cudaGetSymbolAddress((void**)&p.x1, g_x1);
    cudaGetSymbolAddress((void**)&p.x2, g_x2);
    cudaGetSymbolAddress((void**)&p.outtop, g_outtop);
    cudaGetSymbolAddress((void**)&p.idxA, g_idxA);
    cudaGetSymbolAddress((void**)&p.idxB, g_idxB);

    // k2 of jax.random.split(key(seed))[1] under foldlike split: threefry((0,seed),(0,1))
    unsigned a42, b42, a43, b43;
    tf2x32(0u, 42u, 0u, 1u, &a42, &b42);
    tf2x32(0u, 43u, 0u, 1u, &a43, &b43);
    idx_kernel<<<(L_ * NS_ + 255) / 256, 256>>>(a42, b42, p.idxA);
    idx_kernel<<<(L_ * NS_ + 255) / 256, 256>>>(a43, b43, p.idxB);

    // layer 0: xp2 = attn(xp; xd, xd) -> g_x1
    run_layer(xp, xd, w0q, w0k, w0v, w0o, b0q, b0k, b0v, b0o, p.idxA, p.x1, p);
    // layer 1: xd2 = attn(xd; xp2, xp2) -> g_x2
    run_layer(xd, p.x1, w1q, w1k, w1v, w1o, b1q, b1k, b1v, b1o, p.idxB, p.x2, p);

    final_add_kernel<<<(B_ * 8192 * DM_ / 4) / 256, 256>>>(xs, out);
}

// round 2
// speedup vs baseline: 1.1688x; 1.1688x over previous
#include <cuda_runtime.h>
#include <math.h>
#include <stdint.h>

#define B_   4
#define H_   8
#define L_   4096
#define D_   64
#define DM_  512
#define NS_  27
#define BH_  (B_*H_)
#define BL_  (B_*L_)

// ---------------- scratch (device globals; no runtime alloc) ----------------
__device__ float g_Q[BH_*L_*D_];
__device__ float g_K[BH_*L_*D_];
__device__ float g_V[BH_*L_*D_];
__device__ float g_x1[(size_t)BL_*DM_];   // xp2
__device__ float g_M[BH_*L_];
__device__ float g_S[(size_t)BH_*NS_*L_];
__device__ float g_outtop[BH_*NS_*D_];
__device__ float g_meanV[BH_*D_];
__device__ float g_base[B_*DM_];
__device__ int   g_idxA[L_*NS_];
__device__ int   g_idxB[L_*NS_];
__device__ int   g_topidx[BH_*NS_];

// ---------------- Threefry-2x32 (JAX-exact) ----------------
__host__ __device__ inline void tf2x32(unsigned k0, unsigned k1,
                                       unsigned x0, unsigned x1,
                                       unsigned* o0, unsigned* o1) {
    unsigned ks0 = k0, ks1 = k1, ks2 = 0x1BD11BDAu ^ k0 ^ k1;
    x0 += ks0; x1 += ks1;
#define TF_RND(r) { x0 += x1; x1 = (x1 << (r)) | (x1 >> (32 - (r))); x1 ^= x0; }
    TF_RND(13) TF_RND(15) TF_RND(26) TF_RND(6)   x0 += ks1; x1 += ks2 + 1u;
    TF_RND(17) TF_RND(29) TF_RND(16) TF_RND(24)  x0 += ks2; x1 += ks0 + 2u;
    TF_RND(13) TF_RND(15) TF_RND(26) TF_RND(6)   x0 += ks0; x1 += ks1 + 3u;
    TF_RND(17) TF_RND(29) TF_RND(16) TF_RND(24)  x0 += ks1; x1 += ks2 + 4u;
    TF_RND(13) TF_RND(15) TF_RND(26) TF_RND(6)   x0 += ks2; x1 += ks0 + 5u;
#undef TF_RND
    *o0 = x0; *o1 = x1;
}

__global__ void idx_kernel(unsigned k0, unsigned k1, int* __restrict__ out) {
    int i = blockIdx.x * blockDim.x + threadIdx.x;
    if (i >= L_*NS_) return;
    unsigned o0, o1;
    tf2x32(k0, k1, 0u, (unsigned)i, &o0, &o1);
    out[i] = (int)((o0 ^ o1) & 4095u);
}

// ---------------- cp.async helpers ----------------
__device__ __forceinline__ void cp16(void* smem, const void* g) {
    uint32_t s = (uint32_t)__cvta_generic_to_shared(smem);
    asm volatile("cp.async.cg.shared.global [%0], [%1], 16;\n" :: "r"(s), "l"(g));
}
#define CP_COMMIT() asm volatile("cp.async.commit_group;\n" ::: "memory")
#define CP_WAIT(n)  asm volatile("cp.async.wait_group %0;\n" :: "n"(n) : "memory")

// ---------------- SGEMM with bias (cp.async double-buffered) ----------------
// C = A(Mx512) @ W(512x512) + b.   mode 0: scatter to (b,h,l,d). mode 1: row-major.
#define BM 128
#define BN 128
#define BKK 16
__global__ __launch_bounds__(256, 2)
void sgemm_bias(const float* __restrict__ A, const float* __restrict__ W,
                const float* __restrict__ bias, float* __restrict__ C, int mode) {
    __shared__ __align__(16) float As[2][BM][BKK];   // [m][k]
    __shared__ __align__(16) float Bs[2][BKK][BN];
    const int tid = threadIdx.x;
    const int tx = tid & 15, ty = tid >> 4;
    const int row0 = blockIdx.y * BM, col0 = blockIdx.x * BN;

    // copy-index precompute
    const int a_kc0 = (tid)       & 3,  a_r0 = (tid)       >> 2;   // rows 0..63
    const int a_kc1 = (tid + 256) & 3,  a_r1 = (tid + 256) >> 2;   // rows 64..127
    const int b_nc0 = (tid)       & 31, b_r0 = (tid)       >> 5;   // rows 0..7
    const int b_nc1 = (tid + 256) & 31, b_r1 = (tid + 256) >> 5;   // rows 8..15

    float acc[8][8];
#pragma unroll
    for (int i = 0; i < 8; i++)
#pragma unroll
        for (int j = 0; j < 8; j++) acc[i][j] = 0.f;

#define LOAD_TILE(kt, st) {                                                         \
    cp16(&As[st][a_r0][a_kc0*4], A + (size_t)(row0 + a_r0) * DM_ + (kt) + a_kc0*4); \
    cp16(&As[st][a_r1][a_kc1*4], A + (size_t)(row0 + a_r1) * DM_ + (kt) + a_kc1*4); \
    cp16(&Bs[st][b_r0][b_nc0*4], W + (size_t)((kt) + b_r0) * DM_ + col0 + b_nc0*4); \
    cp16(&Bs[st][b_r1][b_nc1*4], W + (size_t)((kt) + b_r1) * DM_ + col0 + b_nc1*4); \
    CP_COMMIT(); }

#define COMPUTE(st) {                                                         \
    _Pragma("unroll")                                                         \
    for (int k4 = 0; k4 < BKK/4; k4++) {                                      \
        float4 a4[8];                                                         \
        _Pragma("unroll")                                                     \
        for (int i = 0; i < 8; i++)                                           \
            a4[i] = *(const float4*)&As[st][ty*8+i][k4*4];                    \
        _Pragma("unroll")                                                     \
        for (int kk = 0; kk < 4; kk++) {                                      \
            float b0[8];                                                      \
            *(float4*)&b0[0] = *(const float4*)&Bs[st][k4*4+kk][tx*8];        \
            *(float4*)&b0[4] = *(const float4*)&Bs[st][k4*4+kk][tx*8+4];      \
            _Pragma("unroll")                                                 \
            for (int i = 0; i < 8; i++) {                                     \
                float av = (&a4[i].x)[kk];                                    \
                _Pragma("unroll")                                             \
                for (int j = 0; j < 8; j++) acc[i][j] += av * b0[j];          \
            }                                                                 \
        }                                                                     \
    } }

    LOAD_TILE(0, 0);
    const int nIter = DM_ / BKK;       // 32
#pragma unroll 1
    for (int it = 0; it < nIter - 1; it++) {
        LOAD_TILE((it + 1) * BKK, (it + 1) & 1);
        CP_WAIT(1);
        __syncthreads();
        COMPUTE(it & 1);
        __syncthreads();
    }
    CP_WAIT(0);
    __syncthreads();
    COMPUTE((nIter - 1) & 1);

    const int n0 = col0 + tx * 8;
    float bb[8];
#pragma unroll
    for (int j = 0; j < 8; j++) bb[j] = bias[n0 + j];

#pragma unroll
    for (int i = 0; i < 8; i++) {
        int m = row0 + ty * 8 + i;
        float4 v0 = make_float4(acc[i][0]+bb[0], acc[i][1]+bb[1], acc[i][2]+bb[2], acc[i][3]+bb[3]);
        float4 v1 = make_float4(acc[i][4]+bb[4], acc[i][5]+bb[5], acc[i][6]+bb[6], acc[i][7]+bb[7]);
        if (mode == 0) {
            int b = m >> 12, l = m & 4095;
            int h = n0 >> 6, d0 = n0 & 63;
            float* dst = C + (((size_t)(b * H_ + h) * L_) + l) * D_ + d0;
            *(float4*)dst = v0; *(float4*)(dst + 4) = v1;
        } else {
            float* dst = C + (size_t)m * DM_ + n0;
            *(float4*)dst = v0; *(float4*)(dst + 4) = v1;
        }
    }
#undef LOAD_TILE
#undef COMPUTE
}

// ---------------- M[bh][l] = max_s(q·k_s) - sum_s(q·k_s)/L ----------------
__global__ __launch_bounds__(256)
void sample_m_kernel(const int* __restrict__ idx) {
    int gw = (blockIdx.x * blockDim.x + threadIdx.x) >> 5;
    int lane = threadIdx.x & 31;
    if (gw >= BH_ * L_) return;
    int bh = gw >> 12, l = gw & 4095;
    const float4* qrow = (const float4*)(g_Q + ((size_t)bh * L_ + l) * D_);
    float val = 0.f;
    bool active = lane < NS_;
    if (active) {
        int kk = idx[l * NS_ + lane];
        const float4* krow = (const float4*)(g_K + ((size_t)bh * L_ + kk) * D_);
        float s = 0.f;
#pragma unroll
        for (int d4 = 0; d4 < 16; d4++) {
            float4 q = qrow[d4], k = krow[d4];
            s += q.x*k.x + q.y*k.y + q.z*k.z + q.w*k.w;
        }
        val = s;
    }
    float mx = active ? val : -__int_as_float(0x7f800000);
    float sm = active ? val : 0.f;
#pragma unroll
    for (int off = 16; off > 0; off >>= 1) {
        mx = fmaxf(mx, __shfl_down_sync(0xffffffffu, mx, off));
        sm += __shfl_down_sync(0xffffffffu, sm, off);
    }
    if (lane == 0) g_M[gw] = mx - sm * (1.f / (float)L_);
}

// ---------------- top-27 ----------------
__global__ __launch_bounds__(256)
void topk_kernel() {
    int bh = blockIdx.x, t = threadIdx.x;
    __shared__ float sm[L_];
    __shared__ float rv[256];
    __shared__ int   ri[256];
    for (int i = t; i < L_; i += 256) sm[i] = g_M[(size_t)bh * L_ + i];
    __syncthreads();
    for (int it = 0; it < NS_; it++) {
        float best = -__int_as_float(0x7f800000);
        int bi = 0x7fffffff;
        for (int i = t; i < L_; i += 256) {
            float v = sm[i];
            if (v > best) { best = v; bi = i; }
        }
        rv[t] = best; ri[t] = bi;
        __syncthreads();
        for (int s = 128; s > 0; s >>= 1) {
            if (t < s) {
                if (rv[t+s] > rv[t] || (rv[t+s] == rv[t] && ri[t+s] < ri[t])) {
                    rv[t] = rv[t+s]; ri[t] = ri[t+s];
                }
            }
            __syncthreads();
        }
        if (t == 0) { g_topidx[bh * NS_ + it] = ri[0]; sm[ri[0]] = -__int_as_float(0x7f800000); }
        __syncthreads();
    }
}

// ---------------- meanV[bh][d] ----------------
__global__ __launch_bounds__(256)
void meanv_kernel() {
    int bh = blockIdx.x, t = threadIdx.x;
    int d = t & 63, c = t >> 6;
    float s = 0.f;
    for (int l = c; l < L_; l += 4) s += g_V[((size_t)bh * L_ + l) * D_ + d];
    __shared__ float red[256];
    red[t] = s; __syncthreads();
    if (c == 0) g_meanV[bh * D_ + d] = (red[d] + red[64+d] + red[128+d] + red[192+d]) * (1.f / (float)L_);
}

// ---------------- scores S[bh][u][k] = 0.125 * Q[top_u]·K[k] ----------------
__global__ __launch_bounds__(128)
void scores_kernel() {
    int bh = blockIdx.x, kt = blockIdx.y, t = threadIdx.x;
    __shared__ float Qs[NS_][64];
    __shared__ float KsT[64][129];
    for (int f = t; f < NS_ * 16; f += 128) {
        int u = f >> 4, d4 = f & 15;
        int l = g_topidx[bh * NS_ + u];
        *(float4*)&Qs[u][d4 * 4] = *(const float4*)(g_Q + ((size_t)bh * L_ + l) * D_ + d4 * 4);
    }
    for (int f = t; f < 128 * 16; f += 128) {
        int kk = f >> 4, d4 = f & 15;
        float4 v = *(const float4*)(g_K + ((size_t)bh * L_ + kt * 128 + kk) * D_ + d4 * 4);
        KsT[d4*4+0][kk] = v.x; KsT[d4*4+1][kk] = v.y;
        KsT[d4*4+2][kk] = v.z; KsT[d4*4+3][kk] = v.w;
    }
    __syncthreads();
    float acc[NS_];
#pragma unroll
    for (int u = 0; u < NS_; u++) acc[u] = 0.f;
    int kk = t;
#pragma unroll
    for (int d0 = 0; d0 < 64; d0 += 4) {
        float k0 = KsT[d0][kk], k1 = KsT[d0+1][kk], k2 = KsT[d0+2][kk], k3 = KsT[d0+3][kk];
#pragma unroll
        for (int u = 0; u < NS_; u++) {
            float4 q = *(const float4*)&Qs[u][d0];
            acc[u] += q.x*k0 + q.y*k1 + q.z*k2 + q.w*k3;
        }
    }
#pragma unroll
    for (int u = 0; u < NS_; u++)
        g_S[((size_t)bh * NS_ + u) * L_ + kt * 128 + kk] = acc[u] * 0.125f;
}

// ---------------- softmax over each S row (in place) ----------------
__global__ __launch_bounds__(256)
void softmax_kernel() {
    int row = blockIdx.x, t = threadIdx.x;
    float* p = g_S + (size_t)row * L_;
    __shared__ float sm[L_];
    __shared__ float red[256];
    float mx = -__int_as_float(0x7f800000);
    for (int i = t; i < L_; i += 256) { float v = p[i]; sm[i] = v; mx = fmaxf(mx, v); }
    red[t] = mx; __syncthreads();
    for (int s = 128; s > 0; s >>= 1) { if (t < s) red[t] = fmaxf(red[t], red[t+s]); __syncthreads(); }
    float m = red[0];
    __syncthreads();
    float ss = 0.f;
    for (int i = t; i < L_; i += 256) { float e = expf(sm[i] - m); sm[i] = e; ss += e; }
    red[t] = ss; __syncthreads();
    for (int s = 128; s > 0; s >>= 1) { if (t < s) red[t] += red[t+s]; __syncthreads(); }
    float inv = 1.f / red[0];
    for (int i = t; i < L_; i += 256) p[i] = sm[i] * inv;
}

// ---------------- out_top[bh][u][d] += P[u][k] * V[k][d] (split-k) ---------
__global__ __launch_bounds__(256)
void pv_kernel() {
    int bh = blockIdx.x, kc = blockIdx.y, t = threadIdx.x;
    int d = t & 63, ug = t >> 6;
    float acc[7];
#pragma unroll
    for (int j = 0; j < 7; j++) acc[j] = 0.f;
    int k0 = kc * 512;
    for (int k = k0; k < k0 + 512; k += 4) {
        float v0 = g_V[((size_t)bh * L_ + k + 0) * D_ + d];
        float v1 = g_V[((size_t)bh * L_ + k + 1) * D_ + d];
        float v2 = g_V[((size_t)bh * L_ + k + 2) * D_ + d];
        float v3 = g_V[((size_t)bh * L_ + k + 3) * D_ + d];
#pragma unroll
        for (int j = 0; j < 7; j++) {
            int u = ug + j * 4;
            if (u < NS_) {
                float4 pv = *(const float4*)(g_S + ((size_t)bh * NS_ + u) * L_ + k);
                acc[j] += pv.x*v0 + pv.y*v1 + pv.z*v2 + pv.w*v3;
            }
        }
    }
#pragma unroll
    for (int j = 0; j < 7; j++) {
        int u = ug + j * 4;
        if (u < NS_) atomicAdd(&g_outtop[(bh * NS_ + u) * D_ + d], acc[j]);
    }
}

// ---------------- O-projection: algebraic decomposition ----------------
// base[b] = concat_h(meanV[b,h]) @ Wo + bo      (4 x 512x512 GEMV)
__global__ __launch_bounds__(512)
void base_kernel(const float* __restrict__ wo, const float* __restrict__ bo) {
    int b = blockIdx.x, n = threadIdx.x;
    __shared__ float mc[DM_];
    mc[n] = g_meanV[b * DM_ + n];   // meanV laid out (b,h,d) = b*512 + h*64 + d  == concat
    __syncthreads();
    float s = bo[n];
#pragma unroll 8
    for (int k = 0; k < DM_; k++) s += mc[k] * wo[(size_t)k * DM_ + n];
    g_base[b * DM_ + n] = s;
}

// broadcast base into layer-0 output g_x1 (stride 4096 rows/b)
__global__ __launch_bounds__(256)
void bcast0_kernel() {
    int i4 = blockIdx.x * 256 + threadIdx.x;       // over float4 of BL_*DM_
    int n4 = i4 & 127;
    int b = i4 / (L_ * 128);
    ((float4*)g_x1)[i4] = ((const float4*)g_base)[b * 128 + n4];
}

// broadcast base + xs into out lower half (xd2 region, stride 8192 rows/b)
__global__ __launch_bounds__(256)
void bcast1_kernel(const float* __restrict__ xs, float* __restrict__ out) {
    int i4 = blockIdx.x * 256 + threadIdx.x;       // over B_*L_*128
    int n4 = i4 & 127;
    int l = (i4 >> 7) & 4095;
    int b = i4 / (L_ * 128);
    size_t oi = ((size_t)(b * 8192 + l)) * 128 + n4;
    float4 a = ((const float4*)xs)[oi];
    float4 s = ((const float4*)g_base)[b * 128 + n4];
    a.x += s.x; a.y += s.y; a.z += s.z; a.w += s.w;
    ((float4*)out)[oi] = a;
}

// corrections: dst[b, topidx] += (outtop - meanV) @ Wo[h*64:,:]
__global__ __launch_bounds__(128)
void corr_kernel(const float* __restrict__ wo, float* __restrict__ dst, int rows_per_b) {
    int blk = blockIdx.x;                 // 864 = BH_*NS_
    int bh = blk / NS_, u = blk % NS_;
    int b = bh >> 3, h = bh & 7;
    int t = threadIdx.x;
    __shared__ float qv[64];
    if (t < 64) qv[t] = g_outtop[(bh * NS_ + u) * 64 + t] - g_meanV[bh * 64 + t];
    __syncthreads();
    int l = g_topidx[bh * NS_ + u];
    float a0 = 0.f, a1 = 0.f, a2 = 0.f, a3 = 0.f;
#pragma unroll 8
    for (int k = 0; k < 64; k++) {
        float q = qv[k];
        float4 w = *(const float4*)(wo + (size_t)(h * 64 + k) * DM_ + t * 4);
        a0 += q * w.x; a1 += q * w.y; a2 += q * w.z; a3 += q * w.w;
    }
    float* d = dst + ((size_t)b * rows_per_b + l) * DM_ + t * 4;
    atomicAdd(d + 0, a0); atomicAdd(d + 1, a1);
    atomicAdd(d + 2, a2); atomicAdd(d + 3, a3);
}

// out upper half (xp2 region): out = xs + g_x1
__global__ __launch_bounds__(256)
void upper_add_kernel(const float* __restrict__ xs, float* __restrict__ out) {
    int i4 = blockIdx.x * 256 + threadIdx.x;       // over B_*L_*128
    int n4 = i4 & 127;
    int l = (i4 >> 7) & 4095;
    int b = i4 / (L_ * 128);
    size_t oi = ((size_t)(b * 8192 + 4096 + l)) * 128 + n4;
    float4 a = ((const float4*)xs)[oi];
    float4 s = ((const float4*)g_x1)[((size_t)b * L_ + l) * 128 + n4];
    a.x += s.x; a.y += s.y; a.z += s.z; a.w += s.w;
    ((float4*)out)[oi] = a;
}

// ---------------- host orchestration ----------------
extern "C" void kernel_launch(void* const* d_in, const int* in_sizes, int n_in,
                              void* d_out, int out_size) {
    const float* xs  = (const float*)d_in[0];
    const float* xd  = (const float*)d_in[1];
    const float* xp  = (const float*)d_in[2];
    const float* w0q = (const float*)d_in[3];
    const float* w0k = (const float*)d_in[4];
    const float* w0v = (const float*)d_in[5];
    const float* w0o = (const float*)d_in[6];
    const float* b0q = (const float*)d_in[7];
    const float* b0k = (const float*)d_in[8];
    const float* b0v = (const float*)d_in[9];
    const float* b0o = (const float*)d_in[10];
    const float* w1q = (const float*)d_in[11];
    const float* w1k = (const float*)d_in[12];
    const float* w1v = (const float*)d_in[13];
    const float* w1o = (const float*)d_in[14];
    const float* b1q = (const float*)d_in[15];
    const float* b1k = (const float*)d_in[16];
    const float* b1v = (const float*)d_in[17];
    const float* b1o = (const float*)d_in[18];
    float* out = (float*)d_out;

    float *pQ, *pK, *pV, *px1, *pouttop;
    int *pidxA, *pidxB;
    cudaGetSymbolAddress((void**)&pQ, g_Q);
    cudaGetSymbolAddress((void**)&pK, g_K);
    cudaGetSymbolAddress((void**)&pV, g_V);
    cudaGetSymbolAddress((void**)&px1, g_x1);
    cudaGetSymbolAddress((void**)&pouttop, g_outtop);
    cudaGetSymbolAddress((void**)&pidxA, g_idxA);
    cudaGetSymbolAddress((void**)&pidxB, g_idxB);

    unsigned a42, b42, a43, b43;
    tf2x32(0u, 42u, 0u, 1u, &a42, &b42);
    tf2x32(0u, 43u, 0u, 1u, &a43, &b43);
    idx_kernel<<<(L_ * NS_ + 255) / 256, 256>>>(a42, b42, pidxA);
    idx_kernel<<<(L_ * NS_ + 255) / 256, 256>>>(a43, b43, pidxB);

    dim3 ggrid(DM_ / BN, BL_ / BM);

    // ---- layer 0: xp2 = attn(xp; xd, xd) -> g_x1 ----
    sgemm_bias<<<ggrid, 256>>>(xp,  w0q, b0q, pQ, 0);
    sgemm_bias<<<ggrid, 256>>>(xd,  w0k, b0k, pK, 0);
    sgemm_bias<<<ggrid, 256>>>(xd,  w0v, b0v, pV, 0);
    sample_m_kernel<<<(BH_ * L_) / 8, 256>>>(pidxA);
    topk_kernel<<<BH_, 256>>>();
    meanv_kernel<<<BH_, 256>>>();
    cudaMemsetAsync(pouttop, 0, (size_t)BH_ * NS_ * D_ * sizeof(float));
    scores_kernel<<<dim3(BH_, L_ / 128), 128>>>();
    softmax_kernel<<<BH_ * NS_, 256>>>();
    pv_kernel<<<dim3(BH_, 8), 256>>>();
    base_kernel<<<B_, 512>>>(w0o, b0o);
    bcast0_kernel<<<(BL_ * DM_ / 4) / 256, 256>>>();
    corr_kernel<<<BH_ * NS_, 128>>>(w0o, px1, L_);

    // ---- layer 1: xd2 = attn(xd; xp2, xp2) -> out lower half (with xs) ----
    sgemm_bias<<<ggrid, 256>>>(xd,  w1q, b1q, pQ, 0);
    sgemm_bias<<<ggrid, 256>>>(px1, w1k, b1k, pK, 0);
    sgemm_bias<<<ggrid, 256>>>(px1, w1v, b1v, pV, 0);
    sample_m_kernel<<<(BH_ * L_) / 8, 256>>>(pidxB);
    topk_kernel<<<BH_, 256>>>();
    meanv_kernel<<<BH_, 256>>>();
    cudaMemsetAsync(pouttop, 0, (size_t)BH_ * NS_ * D_ * sizeof(float));
    scores_kernel<<<dim3(BH_, L_ / 128), 128>>>();
    softmax_kernel<<<BH_ * NS_, 256>>>();
    pv_kernel<<<dim3(BH_, 8), 256>>>();
    base_kernel<<<B_, 512>>>(w1o, b1o);
    bcast1_kernel<<<(B_ * L_ * 128) / 256, 256>>>(xs, out);
    corr_kernel<<<BH_ * NS_, 128>>>(w1o, out, 2 * L_);

    // ---- xp2 half of output ----
    upper_add_kernel<<<(B_ * L_ * 128) / 256, 256>>>(xs, out);
}

// round 4
// speedup vs baseline: 1.6517x; 1.4132x over previous
#include <cuda_runtime.h>
#include <cuda_bf16.h>
#include <math.h>
#include <stdint.h>

#define B_   4
#define H_   8
#define L_   4096
#define D_   64
#define DM_  512
#define NS_  27
#define BH_  (B_*H_)
#define BL_  (B_*L_)

// ---------------- scratch (device globals; no runtime alloc) ----------------
__device__ float g_Q[BH_*L_*D_];
__device__ float g_K[BH_*L_*D_];
__device__ float g_V[BH_*L_*D_];
__device__ float g_x1[(size_t)BL_*DM_];   // xp2
__device__ float g_M[BH_*L_];
__device__ float g_S[(size_t)BH_*NS_*L_];
__device__ float g_outtop[BH_*NS_*D_];
__device__ float g_meanV[BH_*D_];
__device__ float g_base[B_*DM_];
__device__ int   g_idxA[L_*NS_];
__device__ int   g_idxB[L_*NS_];
__device__ int   g_topidx[BH_*NS_];

// bf16-split operand buffers
__device__ __nv_bfloat16 g_Axd_hi[(size_t)BL_*DM_];
__device__ __nv_bfloat16 g_Axd_lo[(size_t)BL_*DM_];
__device__ __nv_bfloat16 g_Axp_hi[(size_t)BL_*DM_];   // xp, then reused for x1
__device__ __nv_bfloat16 g_Axp_lo[(size_t)BL_*DM_];
__device__ __nv_bfloat16 g_Wt_hi[6*DM_*DM_];          // Wt[n][k] transposed, split
__device__ __nv_bfloat16 g_Wt_lo[6*DM_*DM_];

// ---------------- Threefry-2x32 (JAX-exact) ----------------
__host__ __device__ inline void tf2x32(unsigned k0, unsigned k1,
                                       unsigned x0, unsigned x1,
                                       unsigned* o0, unsigned* o1) {
    unsigned ks0 = k0, ks1 = k1, ks2 = 0x1BD11BDAu ^ k0 ^ k1;
    x0 += ks0; x1 += ks1;
#define TF_RND(r) { x0 += x1; x1 = (x1 << (r)) | (x1 >> (32 - (r))); x1 ^= x0; }
    TF_RND(13) TF_RND(15) TF_RND(26) TF_RND(6)   x0 += ks1; x1 += ks2 + 1u;
    TF_RND(17) TF_RND(29) TF_RND(16) TF_RND(24)  x0 += ks2; x1 += ks0 + 2u;
    TF_RND(13) TF_RND(15) TF_RND(26) TF_RND(6)   x0 += ks0; x1 += ks1 + 3u;
    TF_RND(17) TF_RND(29) TF_RND(16) TF_RND(24)  x0 += ks1; x1 += ks2 + 4u;
    TF_RND(13) TF_RND(15) TF_RND(26) TF_RND(6)   x0 += ks2; x1 += ks0 + 5u;
#undef TF_RND
    *o0 = x0; *o1 = x1;
}

__global__ void idx_kernel(unsigned k0, unsigned k1, int* __restrict__ out) {
    int i = blockIdx.x * blockDim.x + threadIdx.x;
    if (i >= L_*NS_) return;
    unsigned o0, o1;
    tf2x32(k0, k1, 0u, (unsigned)i, &o0, &o1);
    out[i] = (int)((o0 ^ o1) & 4095u);
}

// ---------------- bf16-split conversion kernels ----------------
__global__ __launch_bounds__(256)
void cvt_pair_kernel(const float4* __restrict__ src,
                     __nv_bfloat162* __restrict__ hi, __nv_bfloat162* __restrict__ lo,
                     int n4) {
    int i = blockIdx.x * 256 + threadIdx.x;
    if (i >= n4) return;
    float4 v = src[i];
    __nv_bfloat16 h0 = __float2bfloat16(v.x), h1 = __float2bfloat16(v.y);
    __nv_bfloat16 h2 = __float2bfloat16(v.z), h3 = __float2bfloat16(v.w);
    __nv_bfloat16 l0 = __float2bfloat16(v.x - __bfloat162float(h0));
    __nv_bfloat16 l1 = __float2bfloat16(v.y - __bfloat162float(h1));
    __nv_bfloat16 l2 = __float2bfloat16(v.z - __bfloat162float(h2));
    __nv_bfloat16 l3 = __float2bfloat16(v.w - __bfloat162float(h3));
    hi[i*2]   = __nv_bfloat162(h0, h1);
    hi[i*2+1] = __nv_bfloat162(h2, h3);
    lo[i*2]   = __nv_bfloat162(l0, l1);
    lo[i*2+1] = __nv_bfloat162(l2, l3);
}

// Wt[n][k] = W[k][n], split into bf16 hi/lo
__global__ __launch_bounds__(1024)
void wt_cvt_kernel(const float* __restrict__ W,
                   __nv_bfloat16* __restrict__ hi, __nv_bfloat16* __restrict__ lo) {
    __shared__ float t[32][33];
    int tx = threadIdx.x, ty = threadIdx.y;
    int n0 = blockIdx.x * 32, k0 = blockIdx.y * 32;
    t[ty][tx] = W[(size_t)(k0 + ty) * DM_ + n0 + tx];
    __syncthreads();
    float v = t[tx][ty];          // = W[k0+tx][n0+ty]
    int n = n0 + ty, k = k0 + tx;
    __nv_bfloat16 h = __float2bfloat16(v);
    hi[(size_t)n * DM_ + k] = h;
    lo[(size_t)n * DM_ + k] = __float2bfloat16(v - __bfloat162float(h));
}

// ---------------- PTX helpers ----------------
__device__ __forceinline__ void cp16s(uint32_t saddr, const void* g) {
    asm volatile("cp.async.cg.shared.global [%0], [%1], 16;\n" :: "r"(saddr), "l"(g));
}
#define CP_COMMIT() asm volatile("cp.async.commit_group;\n" ::: "memory")
#define CP_WAIT(n)  asm volatile("cp.async.wait_group %0;\n" :: "n"(n) : "memory")

__device__ __forceinline__ void ldsm4(uint32_t& r0, uint32_t& r1, uint32_t& r2, uint32_t& r3,
                                      uint32_t saddr) {
    asm volatile("ldmatrix.sync.aligned.m8n8.x4.shared.b16 {%0,%1,%2,%3}, [%4];"
                 : "=r"(r0), "=r"(r1), "=r"(r2), "=r"(r3) : "r"(saddr));
}

__device__ __forceinline__ void mma_bf16(float* c, const uint32_t* a, const uint32_t* b) {
    asm volatile("mma.sync.aligned.m16n8k16.row.col.f32.bf16.bf16.f32 "
                 "{%0,%1,%2,%3}, {%4,%5,%6,%7}, {%8,%9}, {%0,%1,%2,%3};"
                 : "+f"(c[0]), "+f"(c[1]), "+f"(c[2]), "+f"(c[3])
                 : "r"(a[0]), "r"(a[1]), "r"(a[2]), "r"(a[3]), "r"(b[0]), "r"(b[1]));
}

// ---------------- mma.sync bf16-split GEMM ----------------
// C[(b,h,l,d) scatter] = A(16384x512 fp32 via hi/lo) @ Wt^T + bias
// CTA 128x128, BK=32, 8 warps (2x4), warp tile 64x32, 3 passes (hh, hl, lh).
// smem stage: Ahi/Alo/Bhi/Blo each 128 rows x 40 bf16 (80B padded) = 10240B -> 40960B/stage
#define GST    40960
#define GSMEM  (2048 + 2*GST)

__global__ __launch_bounds__(256, 1)
void gemm_mma(const __nv_bfloat16* __restrict__ Ahi, const __nv_bfloat16* __restrict__ Alo,
              const __nv_bfloat16* __restrict__ Bhi, const __nv_bfloat16* __restrict__ Blo,
              const float* __restrict__ bias, float* __restrict__ C) {
    extern __shared__ char smem[];
    const uint32_t sb = (uint32_t)__cvta_generic_to_shared(smem);
    const int tid = threadIdx.x;
    const int lane = tid & 31, wid = tid >> 5;
    const int warpM = wid >> 2, warpN = wid & 3;
    const int row0 = blockIdx.y * 128, col0 = blockIdx.x * 128;

    float* sbias = (float*)smem;
    if (tid < 128) sbias[tid] = bias[col0 + tid];

    float acc[4][4][4];
#pragma unroll
    for (int i = 0; i < 4; i++)
#pragma unroll
        for (int j = 0; j < 4; j++)
#pragma unroll
            for (int r = 0; r < 4; r++) acc[i][j][r] = 0.f;

    // ldmatrix per-lane offsets (bytes within a tile)
    const int a_row = warpM * 64 + (lane & 15);         // + i*16
    const int a_kb  = ((lane >> 4) * 8) * 2;            // + k16*32
    const int b_row = warpN * 32 + (lane & 7) + ((lane >> 4) & 1) * 8;  // + n16*16
    const int b_kb  = (((lane >> 3) & 1) * 8) * 2;      // + k16*32

#define LOAD_CHUNK(c, s) {                                                     \
    uint32_t stb = sb + 2048 + (uint32_t)(s) * GST;                            \
    int k0 = (c) * 32;                                                         \
    _Pragma("unroll")                                                          \
    for (int j = 0; j < 8; j++) {                                              \
        int idx = tid + j * 256;                                               \
        int tile = idx >> 9, w = idx & 511;                                    \
        int r = w >> 2, cc = w & 3;                                            \
        uint32_t so = stb + (uint32_t)tile * 10240u + (uint32_t)(r * 80 + cc * 16); \
        const __nv_bfloat16* gp;                                               \
        if      (tile == 0) gp = Ahi + (size_t)(row0 + r) * DM_ + k0 + cc * 8; \
        else if (tile == 1) gp = Alo + (size_t)(row0 + r) * DM_ + k0 + cc * 8; \
        else if (tile == 2) gp = Bhi + (size_t)(col0 + r) * DM_ + k0 + cc * 8; \
        else                gp = Blo + (size_t)(col0 + r) * DM_ + k0 + cc * 8; \
        cp16s(so, gp);                                                         \
    }                                                                          \
    CP_COMMIT(); }

#define COMPUTE(s) {                                                                 \
    uint32_t stb = sb + 2048 + (uint32_t)(s) * GST;                                  \
    _Pragma("unroll")                                                                \
    for (int k16 = 0; k16 < 2; k16++) {                                             \
        uint32_t ah[4][4], al[4][4], bh[4][2], bl[4][2];                             \
        _Pragma("unroll")                                                            \
        for (int i = 0; i < 4; i++)                                                  \
            ldsm4(ah[i][0], ah[i][1], ah[i][2], ah[i][3],                            \
                  stb + (uint32_t)((a_row + i*16) * 80 + k16*32 + a_kb));            \
        _Pragma("unroll")                                                            \
        for (int n16 = 0; n16 < 2; n16++)                                            \
            ldsm4(bh[n16*2][0], bh[n16*2][1], bh[n16*2+1][0], bh[n16*2+1][1],        \
                  stb + 20480u + (uint32_t)((b_row + n16*16) * 80 + k16*32 + b_kb)); \
        _Pragma("unroll")                                                            \
        for (int i = 0; i < 4; i++)                                                  \
            _Pragma("unroll")                                                        \
            for (int j = 0; j < 4; j++) mma_bf16(acc[i][j], ah[i], bh[j]);           \
        _Pragma("unroll")                                                            \
        for (int n16 = 0; n16 < 2; n16++)                                            \
            ldsm4(bl[n16*2][0], bl[n16*2][1], bl[n16*2+1][0], bl[n16*2+1][1],        \
                  stb + 30720u + (uint32_t)((b_row + n16*16) * 80 + k16*32 + b_kb)); \
        _Pragma("unroll")                                                            \
        for (int i = 0; i < 4; i++)                                                  \
            _Pragma("unroll")                                                        \
            for (int j = 0; j < 4; j++) mma_bf16(acc[i][j], ah[i], bl[j]);           \
        _Pragma("unroll")                                                            \
        for (int i = 0; i < 4; i++)                                                  \
            ldsm4(al[i][0], al[i][1], al[i][2], al[i][3],                            \
                  stb + 10240u + (uint32_t)((a_row + i*16) * 80 + k16*32 + a_kb));   \
        _Pragma("unroll")                                                            \
        for (int i = 0; i < 4; i++)                                                  \
            _Pragma("unroll")                                                        \
            for (int j = 0; j < 4; j++) mma_bf16(acc[i][j], al[i], bh[j]);           \
    } }

    LOAD_CHUNK(0, 0);
    LOAD_CHUNK(1, 1);

    const int nIter = DM_ / 32;   // 16
#pragma unroll 1
    for (int c = 0; c < nIter; c++) {
        int s = c & 1;
        if (c == nIter - 1) { CP_WAIT(0); } else { CP_WAIT(1); }
        __syncthreads();
        COMPUTE(s);
        __syncthreads();
        if (c + 2 < nIter) LOAD_CHUNK(c + 2, s);
    }

    // epilogue: bias add + scatter to (b,h,l,d)
    __syncthreads();
#pragma unroll
    for (int i = 0; i < 4; i++) {
#pragma unroll
        for (int j = 0; j < 4; j++) {
            int colg = col0 + warpN * 32 + j * 8 + (lane & 3) * 2;
            int hh = colg >> 6, d0 = colg & 63;
            float b0v = sbias[colg - col0], b1v = sbias[colg - col0 + 1];
#pragma unroll
            for (int half = 0; half < 2; half++) {
                int m = row0 + warpM * 64 + i * 16 + (lane >> 2) + half * 8;
                int b = m >> 12, l = m & 4095;
                float2 v;
                v.x = acc[i][j][half*2 + 0] + b0v;
                v.y = acc[i][j][half*2 + 1] + b1v;
                *(float2*)(C + (((size_t)(b * H_ + hh) * L_) + l) * D_ + d0) = v;
            }
        }
    }
#undef LOAD_CHUNK
#undef COMPUTE
}

// ---------------- M[bh][l] = max_s(q·k_s) - sum_s(q·k_s)/L ----------------
__global__ __launch_bounds__(256)
void sample_m_kernel(const int* __restrict__ idx) {
    int gw = (blockIdx.x * blockDim.x + threadIdx.x) >> 5;
    int lane = threadIdx.x & 31;
    if (gw >= BH_ * L_) return;
    int bh = gw >> 12, l = gw & 4095;
    const float4* qrow = (const float4*)(g_Q + ((size_t)bh * L_ + l) * D_);
    float val = 0.f;
    bool active = lane < NS_;
    if (active) {
        int kk = idx[l * NS_ + lane];
        const float4* krow = (const float4*)(g_K + ((size_t)bh * L_ + kk) * D_);
        float s = 0.f;
#pragma unroll
        for (int d4 = 0; d4 < 16; d4++) {
            float4 q = qrow[d4], k = krow[d4];
            s += q.x*k.x + q.y*k.y + q.z*k.z + q.w*k.w;
        }
        val = s;
    }
    float mx = active ? val : -__int_as_float(0x7f800000);
    float sm = active ? val : 0.f;
#pragma unroll
    for (int off = 16; off > 0; off >>= 1) {
        mx = fmaxf(mx, __shfl_down_sync(0xffffffffu, mx, off));
        sm += __shfl_down_sync(0xffffffffu, sm, off);
    }
    if (lane == 0) g_M[gw] = mx - sm * (1.f / (float)L_);
}

// ---------------- top-27 ----------------
__global__ __launch_bounds__(256)
void topk_kernel() {
    int bh = blockIdx.x, t = threadIdx.x;
    __shared__ float sm[L_];
    __shared__ float rv[256];
    __shared__ int   ri[256];
    for (int i = t; i < L_; i += 256) sm[i] = g_M[(size_t)bh * L_ + i];
    __syncthreads();
    for (int it = 0; it < NS_; it++) {
        float best = -__int_as_float(0x7f800000);
        int bi = 0x7fffffff;
        for (int i = t; i < L_; i += 256) {
            float v = sm[i];
            if (v > best) { best = v; bi = i; }
        }
        rv[t] = best; ri[t] = bi;
        __syncthreads();
        for (int s = 128; s > 0; s >>= 1) {
            if (t < s) {
                if (rv[t+s] > rv[t] || (rv[t+s] == rv[t] && ri[t+s] < ri[t])) {
                    rv[t] = rv[t+s]; ri[t] = ri[t+s];
                }
            }
            __syncthreads();
        }
        if (t == 0) { g_topidx[bh * NS_ + it] = ri[0]; sm[ri[0]] = -__int_as_float(0x7f800000); }
        __syncthreads();
    }
}

// ---------------- meanV[bh][d] ----------------
__global__ __launch_bounds__(256)
void meanv_kernel() {
    int bh = blockIdx.x, t = threadIdx.x;
    int d = t & 63, c = t >> 6;
    float s = 0.f;
    for (int l = c; l < L_; l += 4) s += g_V[((size_t)bh * L_ + l) * D_ + d];
    __shared__ float red[256];
    red[t] = s; __syncthreads();
    if (c == 0) g_meanV[bh * D_ + d] = (red[d] + red[64+d] + red[128+d] + red[192+d]) * (1.f / (float)L_);
}

// ---------------- scores S[bh][u][k] = 0.125 * Q[top_u]·K[k] ----------------
__global__ __launch_bounds__(128)
void scores_kernel() {
    int bh = blockIdx.x, kt = blockIdx.y, t = threadIdx.x;
    __shared__ float Qs[NS_][64];
    __shared__ float KsT[64][129];
    for (int f = t; f < NS_ * 16; f += 128) {
        int u = f >> 4, d4 = f & 15;
        int l = g_topidx[bh * NS_ + u];
        *(float4*)&Qs[u][d4 * 4] = *(const float4*)(g_Q + ((size_t)bh * L_ + l) * D_ + d4 * 4);
    }
    for (int f = t; f < 128 * 16; f += 128) {
        int kk = f >> 4, d4 = f & 15;
        float4 v = *(const float4*)(g_K + ((size_t)bh * L_ + kt * 128 + kk) * D_ + d4 * 4);
        KsT[d4*4+0][kk] = v.x; KsT[d4*4+1][kk] = v.y;
        KsT[d4*4+2][kk] = v.z; KsT[d4*4+3][kk] = v.w;
    }
    __syncthreads();
    float acc[NS_];
#pragma unroll
    for (int u = 0; u < NS_; u++) acc[u] = 0.f;
    int kk = t;
#pragma unroll
    for (int d0 = 0; d0 < 64; d0 += 4) {
        float k0 = KsT[d0][kk], k1 = KsT[d0+1][kk], k2 = KsT[d0+2][kk], k3 = KsT[d0+3][kk];
#pragma unroll
        for (int u = 0; u < NS_; u++) {
            float4 q = *(const float4*)&Qs[u][d0];
            acc[u] += q.x*k0 + q.y*k1 + q.z*k2 + q.w*k3;
        }
    }
#pragma unroll
    for (int u = 0; u < NS_; u++)
        g_S[((size_t)bh * NS_ + u) * L_ + kt * 128 + kk] = acc[u] * 0.125f;
}

// ---------------- softmax over each S row (in place) ----------------
__global__ __launch_bounds__(256)
void softmax_kernel() {
    int row = blockIdx.x, t = threadIdx.x;
    float* p = g_S + (size_t)row * L_;
    __shared__ float sm[L_];
    __shared__ float red[256];
    float mx = -__int_as_float(0x7f800000);
    for (int i = t; i < L_; i += 256) { float v = p[i]; sm[i] = v; mx = fmaxf(mx, v); }
    red[t] = mx; __syncthreads();
    for (int s = 128; s > 0; s >>= 1) { if (t < s) red[t] = fmaxf(red[t], red[t+s]); __syncthreads(); }
    float m = red[0];
    __syncthreads();
    float ss = 0.f;
    for (int i = t; i < L_; i += 256) { float e = expf(sm[i] - m); sm[i] = e; ss += e; }
    red[t] = ss; __syncthreads();
    for (int s = 128; s > 0; s >>= 1) { if (t < s) red[t] += red[t+s]; __syncthreads(); }
    float inv = 1.f / red[0];
    for (int i = t; i < L_; i += 256) p[i] = sm[i] * inv;
}

// ---------------- out_top[bh][u][d] += P[u][k] * V[k][d] (split-k) ---------
__global__ __launch_bounds__(256)
void pv_kernel() {
    int bh = blockIdx.x, kc = blockIdx.y, t = threadIdx.x;
    int d = t & 63, ug = t >> 6;
    float acc[7];
#pragma unroll
    for (int j = 0; j < 7; j++) acc[j] = 0.f;
    int k0 = kc * 512;
    for (int k = k0; k < k0 + 512; k += 4) {
        float v0 = g_V[((size_t)bh * L_ + k + 0) * D_ + d];
        float v1 = g_V[((size_t)bh * L_ + k + 1) * D_ + d];
        float v2 = g_V[((size_t)bh * L_ + k + 2) * D_ + d];
        float v3 = g_V[((size_t)bh * L_ + k + 3) * D_ + d];
#pragma unroll
        for (int j = 0; j < 7; j++) {
            int u = ug + j * 4;
            if (u < NS_) {
                float4 pv = *(const float4*)(g_S + ((size_t)bh * NS_ + u) * L_ + k);
                acc[j] += pv.x*v0 + pv.y*v1 + pv.z*v2 + pv.w*v3;
            }
        }
    }
#pragma unroll
    for (int j = 0; j < 7; j++) {
        int u = ug + j * 4;
        if (u < NS_) atomicAdd(&g_outtop[(bh * NS_ + u) * D_ + d], acc[j]);
    }
}

// ---------------- O-projection: algebraic decomposition ----------------
__global__ __launch_bounds__(512)
void base_kernel(const float* __restrict__ wo, const float* __restrict__ bo) {
    int b = blockIdx.x, n = threadIdx.x;
    __shared__ float mc[DM_];
    mc[n] = g_meanV[b * DM_ + n];
    __syncthreads();
    float s = bo[n];
#pragma unroll 8
    for (int k = 0; k < DM_; k++) s += mc[k] * wo[(size_t)k * DM_ + n];
    g_base[b * DM_ + n] = s;
}

__global__ __launch_bounds__(256)
void bcast0_kernel() {
    int i4 = blockIdx.x * 256 + threadIdx.x;
    int n4 = i4 & 127;
    int b = i4 / (L_ * 128);
    ((float4*)g_x1)[i4] = ((const float4*)g_base)[b * 128 + n4];
}

__global__ __launch_bounds__(256)
void bcast1_kernel(const float* __restrict__ xs, float* __restrict__ out) {
    int i4 = blockIdx.x * 256 + threadIdx.x;
    int n4 = i4 & 127;
    int l = (i4 >> 7) & 4095;
    int b = i4 / (L_ * 128);
    size_t oi = ((size_t)(b * 8192 + l)) * 128 + n4;
    float4 a = ((const float4*)xs)[oi];
    float4 s = ((const float4*)g_base)[b * 128 + n4];
    a.x += s.x; a.y += s.y; a.z += s.z; a.w += s.w;
    ((float4*)out)[oi] = a;
}

__global__ __launch_bounds__(128)
void corr_kernel(const float* __restrict__ wo, float* __restrict__ dst, int rows_per_b) {
    int blk = blockIdx.x;
    int bh = blk / NS_, u = blk % NS_;
    int b = bh >> 3, h = bh & 7;
    int t = threadIdx.x;
    __shared__ float qv[64];
    if (t < 64) qv[t] = g_outtop[(bh * NS_ + u) * 64 + t] - g_meanV[bh * 64 + t];
    __syncthreads();
    int l = g_topidx[bh * NS_ + u];
    float a0 = 0.f, a1 = 0.f, a2 = 0.f, a3 = 0.f;
#pragma unroll 8
    for (int k = 0; k < 64; k++) {
        float q = qv[k];
        float4 w = *(const float4*)(wo + (size_t)(h * 64 + k) * DM_ + t * 4);
        a0 += q * w.x; a1 += q * w.y; a2 += q * w.z; a3 += q * w.w;
    }
    float* d = dst + ((size_t)b * rows_per_b + l) * DM_ + t * 4;
    atomicAdd(d + 0, a0); atomicAdd(d + 1, a1);
    atomicAdd(d + 2, a2); atomicAdd(d + 3, a3);
}

__global__ __launch_bounds__(256)
void upper_add_kernel(const float* __restrict__ xs, float* __restrict__ out) {
    int i4 = blockIdx.x * 256 + threadIdx.x;
    int n4 = i4 & 127;
    int l = (i4 >> 7) & 4095;
    int b = i4 / (L_ * 128);
    size_t oi = ((size_t)(b * 8192 + 4096 + l)) * 128 + n4;
    float4 a = ((const float4*)xs)[oi];
    float4 s = ((const float4*)g_x1)[((size_t)b * L_ + l) * 128 + n4];
    a.x += s.x; a.y += s.y; a.z += s.z; a.w += s.w;
    ((float4*)out)[oi] = a;
}

// ---------------- host orchestration ----------------
extern "C" void kernel_launch(void* const* d_in, const int* in_sizes, int n_in,
                              void* d_out, int out_size) {
    const float* xs  = (const float*)d_in[0];
    const float* xd  = (const float*)d_in[1];
    const float* xp  = (const float*)d_in[2];
    const float* w0q = (const float*)d_in[3];
    const float* w0k = (const float*)d_in[4];
    const float* w0v = (const float*)d_in[5];
    const float* w0o = (const float*)d_in[6];
    const float* b0q = (const float*)d_in[7];
    const float* b0k = (const float*)d_in[8];
    const float* b0v = (const float*)d_in[9];
    const float* b0o = (const float*)d_in[10];
    const float* w1q = (const float*)d_in[11];
    const float* w1k = (const float*)d_in[12];
    const float* w1v = (const float*)d_in[13];
    const float* w1o = (const float*)d_in[14];
    const float* b1q = (const float*)d_in[15];
    const float* b1k = (const float*)d_in[16];
    const float* b1v = (const float*)d_in[17];
    const float* b1o = (const float*)d_in[18];
    float* out = (float*)d_out;

    float *pQ, *pK, *pV, *px1, *pouttop;
    int *pidxA, *pidxB;
    __nv_bfloat16 *pAxdH, *pAxdL, *pAxpH, *pAxpL, *pWtH, *pWtL;
    cudaGetSymbolAddress((void**)&pQ, g_Q);
    cudaGetSymbolAddress((void**)&pK, g_K);
    cudaGetSymbolAddress((void**)&pV, g_V);
    cudaGetSymbolAddress((void**)&px1, g_x1);
    cudaGetSymbolAddress((void**)&pouttop, g_outtop);
    cudaGetSymbolAddress((void**)&pidxA, g_idxA);
    cudaGetSymbolAddress((void**)&pidxB, g_idxB);
    cudaGetSymbolAddress((void**)&pAxdH, g_Axd_hi);
    cudaGetSymbolAddress((void**)&pAxdL, g_Axd_lo);
    cudaGetSymbolAddress((void**)&pAxpH, g_Axp_hi);
    cudaGetSymbolAddress((void**)&pAxpL, g_Axp_lo);
    cudaGetSymbolAddress((void**)&pWtH, g_Wt_hi);
    cudaGetSymbolAddress((void**)&pWtL, g_Wt_lo);

    cudaFuncSetAttribute(gemm_mma, cudaFuncAttributeMaxDynamicSharedMemorySize, GSMEM);

    unsigned a42, b42, a43, b43;
    tf2x32(0u, 42u, 0u, 1u, &a42, &b42);
    tf2x32(0u, 43u, 0u, 1u, &a43, &b43);
    idx_kernel<<<(L_ * NS_ + 255) / 256, 256>>>(a42, b42, pidxA);
    idx_kernel<<<(L_ * NS_ + 255) / 256, 256>>>(a43, b43, pidxB);

    // weight transpose+split (6 QKV weight matrices)
    dim3 wtg(16, 16), wtb(32, 32);
    const float* Ws[6] = { w0q, w0k, w0v, w1q, w1k, w1v };
    for (int i = 0; i < 6; i++)
        wt_cvt_kernel<<<wtg, wtb>>>(Ws[i], pWtH + (size_t)i * DM_ * DM_, pWtL + (size_t)i * DM_ * DM_);

    const int N4 = BL_ * DM_ / 4;
    cvt_pair_kernel<<<(N4 + 255) / 256, 256>>>((const float4*)xd,
        (__nv_bfloat162*)pAxdH, (__nv_bfloat162*)pAxdL, N4);
    cvt_pair_kernel<<<(N4 + 255) / 256, 256>>>((const float4*)xp,
        (__nv_bfloat162*)pAxpH, (__nv_bfloat162*)pAxpL, N4);

    dim3 ggrid(DM_ / 128, BL_ / 128);   // (4, 128)

    // ---- layer 0: xp2 = attn(xp; xd, xd) -> g_x1 ----
    gemm_mma<<<ggrid, 256, GSMEM>>>(pAxpH, pAxpL, pWtH + 0*(size_t)DM_*DM_, pWtL + 0*(size_t)DM_*DM_, b0q, pQ);
    gemm_mma<<<ggrid, 256, GSMEM>>>(pAxdH, pAxdL, pWtH + 1*(size_t)DM_*DM_, pWtL + 1*(size_t)DM_*DM_, b0k, pK);
    gemm_mma<<<ggrid, 256, GSMEM>>>(pAxdH, pAxdL, pWtH + 2*(size_t)DM_*DM_, pWtL + 2*(size_t)DM_*DM_, b0v, pV);
    sample_m_kernel<<<(BH_ * L_) / 8, 256>>>(pidxA);
    topk_kernel<<<BH_, 256>>>();
    meanv_kernel<<<BH_, 256>>>();
    cudaMemsetAsync(pouttop, 0, (size_t)BH_ * NS_ * D_ * sizeof(float));
    scores_kernel<<<dim3(BH_, L_ / 128), 128>>>();
    softmax_kernel<<<BH_ * NS_, 256>>>();
    pv_kernel<<<dim3(BH_, 8), 256>>>();
    base_kernel<<<B_, 512>>>(w0o, b0o);
    bcast0_kernel<<<(BL_ * DM_ / 4) / 256, 256>>>();
    corr_kernel<<<BH_ * NS_, 128>>>(w0o, px1, L_);

    // split x1 for layer-1 K/V GEMMs (reuse xp pair buffers)
    cvt_pair_kernel<<<(N4 + 255) / 256, 256>>>((const float4*)px1,
        (__nv_bfloat162*)pAxpH, (__nv_bfloat162*)pAxpL, N4);

    // ---- layer 1: xd2 = attn(xd; xp2, xp2) -> out lower half (with xs) ----
    gemm_mma<<<ggrid, 256, GSMEM>>>(pAxdH, pAxdL, pWtH + 3*(size_t)DM_*DM_, pWtL + 3*(size_t)DM_*DM_, b1q, pQ);
    gemm_mma<<<ggrid, 256, GSMEM>>>(pAxpH, pAxpL, pWtH + 4*(size_t)DM_*DM_, pWtL + 4*(size_t)DM_*DM_, b1k, pK);
    gemm_mma<<<ggrid, 256, GSMEM>>>(pAxpH, pAxpL, pWtH + 5*(size_t)DM_*DM_, pWtL + 5*(size_t)DM_*DM_, b1v, pV);
    sample_m_kernel<<<(BH_ * L_) / 8, 256>>>(pidxB);
    topk_kernel<<<BH_, 256>>>();
    meanv_kernel<<<BH_, 256>>>();
    cudaMemsetAsync(pouttop, 0, (size_t)BH_ * NS_ * D_ * sizeof(float));
    scores_kernel<<<dim3(BH_, L_ / 128), 128>>>();
    softmax_kernel<<<BH_ * NS_, 256>>>();
    pv_kernel<<<dim3(BH_, 8), 256>>>();
    base_kernel<<<B_, 512>>>(w1o, b1o);
    bcast1_kernel<<<(B_ * L_ * 128) / 256, 256>>>(xs, out);
    corr_kernel<<<BH_ * NS_, 128>>>(w1o, out, 2 * L_);

    // ---- xp2 half of output ----
    upper_add_kernel<<<(B_ * L_ * 128) / 256, 256>>>(xs, out);
}

// round 5
// speedup vs baseline: 1.8745x; 1.1349x over previous
#include <cuda_runtime.h>
#include <cuda_bf16.h>
#include <math.h>
#include <stdint.h>

#define B_   4
#define H_   8
#define L_   4096
#define D_   64
#define DM_  512
#define NS_  27
#define BH_  (B_*H_)
#define BL_  (B_*L_)

// ---------------- scratch (device globals; no runtime alloc) ----------------
__device__ float g_Q[BH_*L_*D_];
__device__ float g_K[BH_*L_*D_];
__device__ float g_V[BH_*L_*D_];
__device__ float g_x1[(size_t)BL_*DM_];   // xp2
__device__ float g_M[BH_*L_];
__device__ float g_S[(size_t)BH_*NS_*L_];
__device__ float g_outtop[BH_*NS_*D_];
__device__ float g_meanV[BH_*D_];
__device__ float g_vpart[BH_*16*D_];
__device__ float g_base[B_*DM_];
__device__ float g_basep[B_*8*DM_];
__device__ int   g_idxA[L_*NS_];
__device__ int   g_idxB[L_*NS_];
__device__ int   g_topidx[BH_*NS_];

// bf16-split operand buffers
__device__ __nv_bfloat16 g_Axd_hi[(size_t)BL_*DM_];
__device__ __nv_bfloat16 g_Axd_lo[(size_t)BL_*DM_];
__device__ __nv_bfloat16 g_Axp_hi[(size_t)BL_*DM_];
__device__ __nv_bfloat16 g_Axp_lo[(size_t)BL_*DM_];
__device__ __nv_bfloat16 g_Wt_hi[6*DM_*DM_];
__device__ __nv_bfloat16 g_Wt_lo[6*DM_*DM_];

// ---------------- Threefry-2x32 (JAX-exact) ----------------
__host__ __device__ inline void tf2x32(unsigned k0, unsigned k1,
                                       unsigned x0, unsigned x1,
                                       unsigned* o0, unsigned* o1) {
    unsigned ks0 = k0, ks1 = k1, ks2 = 0x1BD11BDAu ^ k0 ^ k1;
    x0 += ks0; x1 += ks1;
#define TF_RND(r) { x0 += x1; x1 = (x1 << (r)) | (x1 >> (32 - (r))); x1 ^= x0; }
    TF_RND(13) TF_RND(15) TF_RND(26) TF_RND(6)   x0 += ks1; x1 += ks2 + 1u;
    TF_RND(17) TF_RND(29) TF_RND(16) TF_RND(24)  x0 += ks2; x1 += ks0 + 2u;
    TF_RND(13) TF_RND(15) TF_RND(26) TF_RND(6)   x0 += ks0; x1 += ks1 + 3u;
    TF_RND(17) TF_RND(29) TF_RND(16) TF_RND(24)  x0 += ks1; x1 += ks2 + 4u;
    TF_RND(13) TF_RND(15) TF_RND(26) TF_RND(6)   x0 += ks2; x1 += ks0 + 5u;
#undef TF_RND
    *o0 = x0; *o1 = x1;
}

__global__ void idx_kernel(unsigned k0, unsigned k1, int* __restrict__ out) {
    int i = blockIdx.x * blockDim.x + threadIdx.x;
    if (i >= L_*NS_) return;
    unsigned o0, o1;
    tf2x32(k0, k1, 0u, (unsigned)i, &o0, &o1);
    out[i] = (int)((o0 ^ o1) & 4095u);
}

// ---------------- bf16-split conversion kernels ----------------
__global__ __launch_bounds__(256)
void cvt_pair_kernel(const float4* __restrict__ src,
                     __nv_bfloat162* __restrict__ hi, __nv_bfloat162* __restrict__ lo,
                     int n4) {
    int i = blockIdx.x * 256 + threadIdx.x;
    if (i >= n4) return;
    float4 v = src[i];
    __nv_bfloat16 h0 = __float2bfloat16(v.x), h1 = __float2bfloat16(v.y);
    __nv_bfloat16 h2 = __float2bfloat16(v.z), h3 = __float2bfloat16(v.w);
    __nv_bfloat16 l0 = __float2bfloat16(v.x - __bfloat162float(h0));
    __nv_bfloat16 l1 = __float2bfloat16(v.y - __bfloat162float(h1));
    __nv_bfloat16 l2 = __float2bfloat16(v.z - __bfloat162float(h2));
    __nv_bfloat16 l3 = __float2bfloat16(v.w - __bfloat162float(h3));
    hi[i*2]   = __nv_bfloat162(h0, h1);
    hi[i*2+1] = __nv_bfloat162(h2, h3);
    lo[i*2]   = __nv_bfloat162(l0, l1);
    lo[i*2+1] = __nv_bfloat162(l2, l3);
}

// all 6 weights: Wt[n][k] = W[k][n], split hi/lo; z = weight index
struct W6 { const float* w[6]; };
__global__ __launch_bounds__(1024)
void wt_cvt_all_kernel(W6 ws, __nv_bfloat16* __restrict__ hi, __nv_bfloat16* __restrict__ lo) {
    __shared__ float t[32][33];
    int tx = threadIdx.x, ty = threadIdx.y;
    int n0 = blockIdx.x * 32, k0 = blockIdx.y * 32;
    int z = blockIdx.z;
    const float* W = ws.w[z];
    size_t off = (size_t)z * DM_ * DM_;
    t[ty][tx] = W[(size_t)(k0 + ty) * DM_ + n0 + tx];
    __syncthreads();
    float v = t[tx][ty];
    int n = n0 + ty, k = k0 + tx;
    __nv_bfloat16 h = __float2bfloat16(v);
    hi[off + (size_t)n * DM_ + k] = h;
    lo[off + (size_t)n * DM_ + k] = __float2bfloat16(v - __bfloat162float(h));
}

// ---------------- PTX helpers ----------------
__device__ __forceinline__ void cp16s(uint32_t saddr, const void* g) {
    asm volatile("cp.async.cg.shared.global [%0], [%1], 16;\n" :: "r"(saddr), "l"(g));
}
#define CP_COMMIT() asm volatile("cp.async.commit_group;\n" ::: "memory")
#define CP_WAIT(n)  asm volatile("cp.async.wait_group %0;\n" :: "n"(n) : "memory")

__device__ __forceinline__ void ldsm4(uint32_t& r0, uint32_t& r1, uint32_t& r2, uint32_t& r3,
                                      uint32_t saddr) {
    asm volatile("ldmatrix.sync.aligned.m8n8.x4.shared.b16 {%0,%1,%2,%3}, [%4];"
                 : "=r"(r0), "=r"(r1), "=r"(r2), "=r"(r3) : "r"(saddr));
}

__device__ __forceinline__ void mma_bf16(float* c, const uint32_t* a, const uint32_t* b) {
    asm volatile("mma.sync.aligned.m16n8k16.row.col.f32.bf16.bf16.f32 "
                 "{%0,%1,%2,%3}, {%4,%5,%6,%7}, {%8,%9}, {%0,%1,%2,%3};"
                 : "+f"(c[0]), "+f"(c[1]), "+f"(c[2]), "+f"(c[3])
                 : "r"(a[0]), "r"(a[1]), "r"(a[2]), "r"(a[3]), "r"(b[0]), "r"(b[1]));
}

// ---------------- mma.sync bf16-split GEMM (4-stage pipeline) ----------------
#define GST    40960
#define NSTG   4
#define GSMEM  (2048 + NSTG*GST)

__global__ __launch_bounds__(256, 1)
void gemm_mma(const __nv_bfloat16* __restrict__ Ahi, const __nv_bfloat16* __restrict__ Alo,
              const __nv_bfloat16* __restrict__ Bhi, const __nv_bfloat16* __restrict__ Blo,
              const float* __restrict__ bias, float* __restrict__ C) {
    extern __shared__ char smem[];
    const uint32_t sb = (uint32_t)__cvta_generic_to_shared(smem);
    const int tid = threadIdx.x;
    const int lane = tid & 31, wid = tid >> 5;
    const int warpM = wid >> 2, warpN = wid & 3;
    const int row0 = blockIdx.y * 128, col0 = blockIdx.x * 128;

    float* sbias = (float*)smem;
    if (tid < 128) sbias[tid] = bias[col0 + tid];

    float acc[4][4][4];
#pragma unroll
    for (int i = 0; i < 4; i++)
#pragma unroll
        for (int j = 0; j < 4; j++)
#pragma unroll
            for (int r = 0; r < 4; r++) acc[i][j][r] = 0.f;

    const int a_row = warpM * 64 + (lane & 15);
    const int a_kb  = ((lane >> 4) * 8) * 2;
    const int b_row = warpN * 32 + (lane & 7) + ((lane >> 4) & 1) * 8;
    const int b_kb  = (((lane >> 3) & 1) * 8) * 2;

#define LOAD_CHUNK(c, s) {                                                     \
    uint32_t stb = sb + 2048 + (uint32_t)(s) * GST;                            \
    int k0 = (c) * 32;                                                         \
    _Pragma("unroll")                                                          \
    for (int j = 0; j < 8; j++) {                                              \
        int idx = tid + j * 256;                                               \
        int tile = idx >> 9, w = idx & 511;                                    \
        int r = w >> 2, cc = w & 3;                                            \
        uint32_t so = stb + (uint32_t)tile * 10240u + (uint32_t)(r * 80 + cc * 16); \
        const __nv_bfloat16* gp;                                               \
        if      (tile == 0) gp = Ahi + (size_t)(row0 + r) * DM_ + k0 + cc * 8; \
        else if (tile == 1) gp = Alo + (size_t)(row0 + r) * DM_ + k0 + cc * 8; \
        else if (tile == 2) gp = Bhi + (size_t)(col0 + r) * DM_ + k0 + cc * 8; \
        else                gp = Blo + (size_t)(col0 + r) * DM_ + k0 + cc * 8; \
        cp16s(so, gp);                                                         \
    }                                                                          \
    CP_COMMIT(); }

#define COMPUTE(s) {                                                                 \
    uint32_t stb = sb + 2048 + (uint32_t)(s) * GST;                                  \
    _Pragma("unroll")                                                                \
    for (int k16 = 0; k16 < 2; k16++) {                                             \
        uint32_t ah[4][4], al[4][4], bh[4][2], bl[4][2];                             \
        _Pragma("unroll")                                                            \
        for (int i = 0; i < 4; i++)                                                  \
            ldsm4(ah[i][0], ah[i][1], ah[i][2], ah[i][3],                            \
                  stb + (uint32_t)((a_row + i*16) * 80 + k16*32 + a_kb));            \
        _Pragma("unroll")                                                            \
        for (int n16 = 0; n16 < 2; n16++)                                            \
            ldsm4(bh[n16*2][0], bh[n16*2][1], bh[n16*2+1][0], bh[n16*2+1][1],        \
                  stb + 20480u + (uint32_t)((b_row + n16*16) * 80 + k16*32 + b_kb)); \
        _Pragma("unroll")                                                            \
        for (int i = 0; i < 4; i++)                                                  \
            _Pragma("unroll")                                                        \
            for (int j = 0; j < 4; j++) mma_bf16(acc[i][j], ah[i], bh[j]);           \
        _Pragma("unroll")                                                            \
        for (int n16 = 0; n16 < 2; n16++)                                            \
            ldsm4(bl[n16*2][0], bl[n16*2][1], bl[n16*2+1][0], bl[n16*2+1][1],        \
                  stb + 30720u + (uint32_t)((b_row + n16*16) * 80 + k16*32 + b_kb)); \
        _Pragma("unroll")                                                            \
        for (int i = 0; i < 4; i++)                                                  \
            _Pragma("unroll")                                                        \
            for (int j = 0; j < 4; j++) mma_bf16(acc[i][j], ah[i], bl[j]);           \
        _Pragma("unroll")                                                            \
        for (int i = 0; i < 4; i++)                                                  \
            ldsm4(al[i][0], al[i][1], al[i][2], al[i][3],                            \
                  stb + 10240u + (uint32_t)((a_row + i*16) * 80 + k16*32 + a_kb));   \
        _Pragma("unroll")                                                            \
        for (int i = 0; i < 4; i++)                                                  \
            _Pragma("unroll")                                                        \
            for (int j = 0; j < 4; j++) mma_bf16(acc[i][j], al[i], bh[j]);           \
    } }

    LOAD_CHUNK(0, 0);
    LOAD_CHUNK(1, 1);
    LOAD_CHUNK(2, 2);

    const int nIter = DM_ / 32;   // 16
#pragma unroll 1
    for (int c = 0; c < nIter; c++) {
        if (c < nIter - 2)      { CP_WAIT(2); }
        else if (c == nIter - 2){ CP_WAIT(1); }
        else                    { CP_WAIT(0); }
        __syncthreads();
        if (c + 3 < nIter) LOAD_CHUNK(c + 3, (c + 3) & 3);
        COMPUTE(c & 3);
    }

    // epilogue: bias add + scatter to (b,h,l,d)
    __syncthreads();
#pragma unroll
    for (int i = 0; i < 4; i++) {
#pragma unroll
        for (int j = 0; j < 4; j++) {
            int colg = col0 + warpN * 32 + j * 8 + (lane & 3) * 2;
            int hh = colg >> 6, d0 = colg & 63;
            float b0v = sbias[colg - col0], b1v = sbias[colg - col0 + 1];
#pragma unroll
            for (int half = 0; half < 2; half++) {
                int m = row0 + warpM * 64 + i * 16 + (lane >> 2) + half * 8;
                int b = m >> 12, l = m & 4095;
                float2 v;
                v.x = acc[i][j][half*2 + 0] + b0v;
                v.y = acc[i][j][half*2 + 1] + b1v;
                *(float2*)(C + (((size_t)(b * H_ + hh) * L_) + l) * D_ + d0) = v;
            }
        }
    }
#undef LOAD_CHUNK
#undef COMPUTE
}

// ---------------- M[bh][l] = max_s(q·k_s) - sum_s(q·k_s)/L ----------------
__global__ __launch_bounds__(256)
void sample_m_kernel(const int* __restrict__ idx) {
    int gw = (blockIdx.x * blockDim.x + threadIdx.x) >> 5;
    int lane = threadIdx.x & 31;
    if (gw >= BH_ * L_) return;
    int bh = gw >> 12, l = gw & 4095;
    const float4* qrow = (const float4*)(g_Q + ((size_t)bh * L_ + l) * D_);
    float val = 0.f;
    bool active = lane < NS_;
    if (active) {
        int kk = idx[l * NS_ + lane];
        const float4* krow = (const float4*)(g_K + ((size_t)bh * L_ + kk) * D_);
        float s = 0.f;
#pragma unroll
        for (int d4 = 0; d4 < 16; d4++) {
            float4 q = qrow[d4], k = krow[d4];
            s += q.x*k.x + q.y*k.y + q.z*k.z + q.w*k.w;
        }
        val = s;
    }
    float mx = active ? val : -__int_as_float(0x7f800000);
    float sm = active ? val : 0.f;
#pragma unroll
    for (int off = 16; off > 0; off >>= 1) {
        mx = fmaxf(mx, __shfl_down_sync(0xffffffffu, mx, off));
        sm += __shfl_down_sync(0xffffffffu, sm, off);
    }
    if (lane == 0) g_M[gw] = mx - sm * (1.f / (float)L_);
}

// ---------------- top-27 via packed-key shfl reduce ----------------
__device__ __forceinline__ unsigned ordf(float v) {
    unsigned u = __float_as_uint(v);
    return (u & 0x80000000u) ? ~u : (u | 0x80000000u);
}

__global__ __launch_bounds__(256)
void topk_kernel() {
    int bh = blockIdx.x, t = threadIdx.x;
    int lane = t & 31, wid = t >> 5;
    __shared__ float sm[L_];
    __shared__ unsigned long long wred[8];
    for (int i = t; i < L_; i += 256) sm[i] = g_M[(size_t)bh * L_ + i];
    __syncthreads();
    for (int it = 0; it < NS_; it++) {
        unsigned long long best = 0ull;
#pragma unroll
        for (int jj = 0; jj < L_ / 256; jj++) {
            int i = t + jj * 256;
            unsigned long long key = ((unsigned long long)ordf(sm[i]) << 32)
                                   | (unsigned)(L_ - 1 - i);
            if (key > best) best = key;
        }
#pragma unroll
        for (int off = 16; off > 0; off >>= 1) {
            unsigned long long o = __shfl_down_sync(0xffffffffu, best, off);
            if (o > best) best = o;
        }
        if (lane == 0) wred[wid] = best;
        __syncthreads();
        if (t == 0) {
            unsigned long long b2 = wred[0];
#pragma unroll
            for (int w = 1; w < 8; w++) if (wred[w] > b2) b2 = wred[w];
            int idx = L_ - 1 - (int)(b2 & 0xFFFFFFFFull);
            g_topidx[bh * NS_ + it] = idx;
            sm[idx] = -__int_as_float(0x7f800000);
        }
        __syncthreads();
    }
}

// ---------------- meanV: two-stage deterministic reduce ----------------
__global__ __launch_bounds__(256)
void meanv1_kernel() {
    int bh = blockIdx.x, c = blockIdx.y, t = threadIdx.x;
    int d = t & 63, r = t >> 6;
    float s = 0.f;
    int base = c * 256;
    for (int l = base + r; l < base + 256; l += 4)
        s += g_V[((size_t)bh * L_ + l) * D_ + d];
    __shared__ float red[256];
    red[t] = s; __syncthreads();
    if (t < 64)
        g_vpart[(bh * 16 + c) * D_ + d] = red[d] + red[64+d] + red[128+d] + red[192+d];
}

__global__ __launch_bounds__(64)
void meanv2_kernel() {
    int bh = blockIdx.x, d = threadIdx.x;
    float s = 0.f;
#pragma unroll
    for (int c = 0; c < 16; c++) s += g_vpart[(bh * 16 + c) * D_ + d];
    g_meanV[bh * D_ + d] = s * (1.f / (float)L_);
}

// ---------------- scores S[bh][u][k] = 0.125 * Q[top_u]·K[k] ----------------
__global__ __launch_bounds__(128)
void scores_kernel() {
    int bh = blockIdx.x, kt = blockIdx.y, t = threadIdx.x;
    __shared__ float Qs[NS_][64];
    __shared__ float KsT[64][129];
    for (int f = t; f < NS_ * 16; f += 128) {
        int u = f >> 4, d4 = f & 15;
        int l = g_topidx[bh * NS_ + u];
        *(float4*)&Qs[u][d4 * 4] = *(const float4*)(g_Q + ((size_t)bh * L_ + l) * D_ + d4 * 4);
    }
    for (int f = t; f < 128 * 16; f += 128) {
        int kk = f >> 4, d4 = f & 15;
        float4 v = *(const float4*)(g_K + ((size_t)bh * L_ + kt * 128 + kk) * D_ + d4 * 4);
        KsT[d4*4+0][kk] = v.x; KsT[d4*4+1][kk] = v.y;
        KsT[d4*4+2][kk] = v.z; KsT[d4*4+3][kk] = v.w;
    }
    __syncthreads();
    float acc[NS_];
#pragma unroll
    for (int u = 0; u < NS_; u++) acc[u] = 0.f;
    int kk = t;
#pragma unroll
    for (int d0 = 0; d0 < 64; d0 += 4) {
        float k0 = KsT[d0][kk], k1 = KsT[d0+1][kk], k2 = KsT[d0+2][kk], k3 = KsT[d0+3][kk];
#pragma unroll
        for (int u = 0; u < NS_; u++) {
            float4 q = *(const float4*)&Qs[u][d0];
            acc[u] += q.x*k0 + q.y*k1 + q.z*k2 + q.w*k3;
        }
    }
#pragma unroll
    for (int u = 0; u < NS_; u++)
        g_S[((size_t)bh * NS_ + u) * L_ + kt * 128 + kk] = acc[u] * 0.125f;
}

// ---------------- softmax over each S row (in place) ----------------
__global__ __launch_bounds__(256)
void softmax_kernel() {
    int row = blockIdx.x, t = threadIdx.x;
    float* p = g_S + (size_t)row * L_;
    __shared__ float sm[L_];
    __shared__ float red[256];
    float mx = -__int_as_float(0x7f800000);
    for (int i = t; i < L_; i += 256) { float v = p[i]; sm[i] = v; mx = fmaxf(mx, v); }
    red[t] = mx; __syncthreads();
    for (int s = 128; s > 0; s >>= 1) { if (t < s) red[t] = fmaxf(red[t], red[t+s]); __syncthreads(); }
    float m = red[0];
    __syncthreads();
    float ss = 0.f;
    for (int i = t; i < L_; i += 256) { float e = expf(sm[i] - m); sm[i] = e; ss += e; }
    red[t] = ss; __syncthreads();
    for (int s = 128; s > 0; s >>= 1) { if (t < s) red[t] += red[t+s]; __syncthreads(); }
    float inv = 1.f / red[0];
    for (int i = t; i < L_; i += 256) p[i] = sm[i] * inv;
}

// ---------------- out_top[bh][u][d] += P[u][k] * V[k][d] (split-k) ---------
__global__ __launch_bounds__(256)
void pv_kernel() {
    int bh = blockIdx.x, kc = blockIdx.y, t = threadIdx.x;
    int d = t & 63, ug = t >> 6;
    float acc[7];
#pragma unroll
    for (int j = 0; j < 7; j++) acc[j] = 0.f;
    int k0 = kc * 512;
    for (int k = k0; k < k0 + 512; k += 4) {
        float v0 = g_V[((size_t)bh * L_ + k + 0) * D_ + d];
        float v1 = g_V[((size_t)bh * L_ + k + 1) * D_ + d];
        float v2 = g_V[((size_t)bh * L_ + k + 2) * D_ + d];
        float v3 = g_V[((size_t)bh * L_ + k + 3) * D_ + d];
#pragma unroll
        for (int j = 0; j < 7; j++) {
            int u = ug + j * 4;
            if (u < NS_) {
                float4 pv = *(const float4*)(g_S + ((size_t)bh * NS_ + u) * L_ + k);
                acc[j] += pv.x*v0 + pv.y*v1 + pv.z*v2 + pv.w*v3;
            }
        }
    }
#pragma unroll
    for (int j = 0; j < 7; j++) {
        int u = ug + j * 4;
        if (u < NS_) atomicAdd(&g_outtop[(bh * NS_ + u) * D_ + d], acc[j]);
    }
}

// ---------------- O-projection: algebraic decomposition ----------------
// base partials: basep[b][kc][n] = sum_{k in kc} meanctx[b][k] * Wo[k][n]
__global__ __launch_bounds__(512)
void base1_kernel(const float* __restrict__ wo) {
    int b = blockIdx.x, kc = blockIdx.y, n = threadIdx.x;
    __shared__ float mc[64];
    if (n < 64) mc[n] = g_meanV[b * DM_ + kc * 64 + n];
    __syncthreads();
    float s = 0.f;
#pragma unroll 8
    for (int k = 0; k < 64; k++) s += mc[k] * wo[(size_t)(kc * 64 + k) * DM_ + n];
    g_basep[(b * 8 + kc) * DM_ + n] = s;
}

__global__ __launch_bounds__(512)
void base2_kernel(const float* __restrict__ bo) {
    int b = blockIdx.x, n = threadIdx.x;
    float s = bo[n];
#pragma unroll
    for (int p = 0; p < 8; p++) s += g_basep[(b * 8 + p) * DM_ + n];
    g_base[b * DM_ + n] = s;
}

__global__ __launch_bounds__(256)
void bcast0_kernel() {
    int i4 = blockIdx.x * 256 + threadIdx.x;
    int n4 = i4 & 127;
    int b = i4 / (L_ * 128);
    ((float4*)g_x1)[i4] = ((const float4*)g_base)[b * 128 + n4];
}

__global__ __launch_bounds__(256)
void bcast1_kernel(const float* __restrict__ xs, float* __restrict__ out) {
    int i4 = blockIdx.x * 256 + threadIdx.x;
    int n4 = i4 & 127;
    int l = (i4 >> 7) & 4095;
    int b = i4 / (L_ * 128);
    size_t oi = ((size_t)(b * 8192 + l)) * 128 + n4;
    float4 a = ((const float4*)xs)[oi];
    float4 s = ((const float4*)g_base)[b * 128 + n4];
    a.x += s.x; a.y += s.y; a.z += s.z; a.w += s.w;
    ((float4*)out)[oi] = a;
}

__global__ __launch_bounds__(128)
void corr_kernel(const float* __restrict__ wo, float* __restrict__ dst, int rows_per_b) {
    int blk = blockIdx.x;
    int bh = blk / NS_, u = blk % NS_;
    int b = bh >> 3, h = bh & 7;
    int t = threadIdx.x;
    __shared__ float qv[64];
    if (t < 64) qv[t] = g_outtop[(bh * NS_ + u) * 64 + t] - g_meanV[bh * 64 + t];
    __syncthreads();
    int l = g_topidx[bh * NS_ + u];
    float a0 = 0.f, a1 = 0.f, a2 = 0.f, a3 = 0.f;
#pragma unroll 8
    for (int k = 0; k < 64; k++) {
        float q = qv[k];
        float4 w = *(const float4*)(wo + (size_t)(h * 64 + k) * DM_ + t * 4);
        a0 += q * w.x; a1 += q * w.y; a2 += q * w.z; a3 += q * w.w;
    }
    float* d = dst + ((size_t)b * rows_per_b + l) * DM_ + t * 4;
    atomicAdd(d + 0, a0); atomicAdd(d + 1, a1);
    atomicAdd(d + 2, a2); atomicAdd(d + 3, a3);
}

__global__ __launch_bounds__(256)
void upper_add_kernel(const float* __restrict__ xs, float* __restrict__ out) {
    int i4 = blockIdx.x * 256 + threadIdx.x;
    int n4 = i4 & 127;
    int l = (i4 >> 7) & 4095;
    int b = i4 / (L_ * 128);
    size_t oi = ((size_t)(b * 8192 + 4096 + l)) * 128 + n4;
    float4 a = ((const float4*)xs)[oi];
    float4 s = ((const float4*)g_x1)[((size_t)b * L_ + l) * 128 + n4];
    a.x += s.x; a.y += s.y; a.z += s.z; a.w += s.w;
    ((float4*)out)[oi] = a;
}

// ---------------- host orchestration ----------------
extern "C" void kernel_launch(void* const* d_in, const int* in_sizes, int n_in,
                              void* d_out, int out_size) {
    const float* xs  = (const float*)d_in[0];
    const float* xd  = (const float*)d_in[1];
    const float* xp  = (const float*)d_in[2];
    const float* w0q = (const float*)d_in[3];
    const float* w0k = (const float*)d_in[4];
    const float* w0v = (const float*)d_in[5];
    const float* w0o = (const float*)d_in[6];
    const float* b0q = (const float*)d_in[7];
    const float* b0k = (const float*)d_in[8];
    const float* b0v = (const float*)d_in[9];
    const float* b0o = (const float*)d_in[10];
    const float* w1q = (const float*)d_in[11];
    const float* w1k = (const float*)d_in[12];
    const float* w1v = (const float*)d_in[13];
    const float* w1o = (const float*)d_in[14];
    const float* b1q = (const float*)d_in[15];
    const float* b1k = (const float*)d_in[16];
    const float* b1v = (const float*)d_in[17];
    const float* b1o = (const float*)d_in[18];
    float* out = (float*)d_out;

    float *pQ, *pK, *pV, *px1, *pouttop;
    int *pidxA, *pidxB;
    __nv_bfloat16 *pAxdH, *pAxdL, *pAxpH, *pAxpL, *pWtH, *pWtL;
    cudaGetSymbolAddress((void**)&pQ, g_Q);
    cudaGetSymbolAddress((void**)&pK, g_K);
    cudaGetSymbolAddress((void**)&pV, g_V);
    cudaGetSymbolAddress((void**)&px1, g_x1);
    cudaGetSymbolAddress((void**)&pouttop, g_outtop);
    cudaGetSymbolAddress((void**)&pidxA, g_idxA);
    cudaGetSymbolAddress((void**)&pidxB, g_idxB);
    cudaGetSymbolAddress((void**)&pAxdH, g_Axd_hi);
    cudaGetSymbolAddress((void**)&pAxdL, g_Axd_lo);
    cudaGetSymbolAddress((void**)&pAxpH, g_Axp_hi);
    cudaGetSymbolAddress((void**)&pAxpL, g_Axp_lo);
    cudaGetSymbolAddress((void**)&pWtH, g_Wt_hi);
    cudaGetSymbolAddress((void**)&pWtL, g_Wt_lo);

    cudaFuncSetAttribute(gemm_mma, cudaFuncAttributeMaxDynamicSharedMemorySize, GSMEM);

    unsigned a42, b42, a43, b43;
    tf2x32(0u, 42u, 0u, 1u, &a42, &b42);
    tf2x32(0u, 43u, 0u, 1u, &a43, &b43);
    idx_kernel<<<(L_ * NS_ + 255) / 256, 256>>>(a42, b42, pidxA);
    idx_kernel<<<(L_ * NS_ + 255) / 256, 256>>>(a43, b43, pidxB);

    // all 6 weight transposes+splits in one launch
    W6 ws;
    ws.w[0] = w0q; ws.w[1] = w0k; ws.w[2] = w0v;
    ws.w[3] = w1q; ws.w[4] = w1k; ws.w[5] = w1v;
    wt_cvt_all_kernel<<<dim3(16, 16, 6), dim3(32, 32)>>>(ws, pWtH, pWtL);

    const int N4 = BL_ * DM_ / 4;
    cvt_pair_kernel<<<(N4 + 255) / 256, 256>>>((const float4*)xd,
        (__nv_bfloat162*)pAxdH, (__nv_bfloat162*)pAxdL, N4);
    cvt_pair_kernel<<<(N4 + 255) / 256, 256>>>((const float4*)xp,
        (__nv_bfloat162*)pAxpH, (__nv_bfloat162*)pAxpL, N4);

    dim3 ggrid(DM_ / 128, BL_ / 128);   // (4, 128)

    // ---- layer 0: xp2 = attn(xp; xd, xd) -> g_x1 ----
    gemm_mma<<<ggrid, 256, GSMEM>>>(pAxpH, pAxpL, pWtH + 0*(size_t)DM_*DM_, pWtL + 0*(size_t)DM_*DM_, b0q, pQ);
    gemm_mma<<<ggrid, 256, GSMEM>>>(pAxdH, pAxdL, pWtH + 1*(size_t)DM_*DM_, pWtL + 1*(size_t)DM_*DM_, b0k, pK);
    gemm_mma<<<ggrid, 256, GSMEM>>>(pAxdH, pAxdL, pWtH + 2*(size_t)DM_*DM_, pWtL + 2*(size_t)DM_*DM_, b0v, pV);
    sample_m_kernel<<<(BH_ * L_) / 8, 256>>>(pidxA);
    topk_kernel<<<BH_, 256>>>();
    meanv1_kernel<<<dim3(BH_, 16), 256>>>();
    meanv2_kernel<<<BH_, 64>>>();
    cudaMemsetAsync(pouttop, 0, (size_t)BH_ * NS_ * D_ * sizeof(float));
    scores_kernel<<<dim3(BH_, L_ / 128), 128>>>();
    softmax_kernel<<<BH_ * NS_, 256>>>();
    pv_kernel<<<dim3(BH_, 8), 256>>>();
    base1_kernel<<<dim3(B_, 8), 512>>>(w0o);
    base2_kernel<<<B_, 512>>>(b0o);
    bcast0_kernel<<<(BL_ * DM_ / 4) / 256, 256>>>();
    corr_kernel<<<BH_ * NS_, 128>>>(w0o, px1, L_);

    // split x1 for layer-1 K/V GEMMs (reuse xp pair buffers)
    cvt_pair_kernel<<<(N4 + 255) / 256, 256>>>((const float4*)px1,
        (__nv_bfloat162*)pAxpH, (__nv_bfloat162*)pAxpL, N4);

    // ---- layer 1: xd2 = attn(xd; xp2, xp2) -> out lower half (with xs) ----
    gemm_mma<<<ggrid, 256, GSMEM>>>(pAxdH, pAxdL, pWtH + 3*(size_t)DM_*DM_, pWtL + 3*(size_t)DM_*DM_, b1q, pQ);
    gemm_mma<<<ggrid, 256, GSMEM>>>(pAxpH, pAxpL, pWtH + 4*(size_t)DM_*DM_, pWtL + 4*(size_t)DM_*DM_, b1k, pK);
    gemm_mma<<<ggrid, 256, GSMEM>>>(pAxpH, pAxpL, pWtH + 5*(size_t)DM_*DM_, pWtL + 5*(size_t)DM_*DM_, b1v, pV);
    sample_m_kernel<<<(BH_ * L_) / 8, 256>>>(pidxB);
    topk_kernel<<<BH_, 256>>>();
    meanv1_kernel<<<dim3(BH_, 16), 256>>>();
    meanv2_kernel<<<BH_, 64>>>();
    cudaMemsetAsync(pouttop, 0, (size_t)BH_ * NS_ * D_ * sizeof(float));
    scores_kernel<<<dim3(BH_, L_ / 128), 128>>>();
    softmax_kernel<<<BH_ * NS_, 256>>>();
    pv_kernel<<<dim3(BH_, 8), 256>>>();
    base1_kernel<<<dim3(B_, 8), 512>>>(w1o);
    base2_kernel<<<B_, 512>>>(b1o);
    bcast1_kernel<<<(B_ * L_ * 128) / 256, 256>>>(xs, out);
    corr_kernel<<<BH_ * NS_, 128>>>(w1o, out, 2 * L_);

    // ---- xp2 half of output ----
    upper_add_kernel<<<(B_ * L_ * 128) / 256, 256>>>(xs, out);
}

// round 6
// speedup vs baseline: 2.0062x; 1.0702x over previous
#include <cuda_runtime.h>
#include <cuda_bf16.h>
#include <math.h>
#include <stdint.h>

#define B_   4
#define H_   8
#define L_   4096
#define D_   64
#define DM_  512
#define NS_  27
#define BH_  (B_*H_)
#define BL_  (B_*L_)

// ---------------- scratch (device globals; no runtime alloc) ----------------
__device__ float g_Q[BH_*L_*D_];
__device__ float g_K[BH_*L_*D_];
__device__ float g_V[BH_*L_*D_];
__device__ float g_M[BH_*L_];
__device__ float g_S[(size_t)BH_*NS_*L_];
__device__ float g_outtop[BH_*NS_*D_];
__device__ float g_meanV[BH_*D_];
__device__ float g_vpart[BH_*16*D_];
__device__ float g_base0[B_*DM_];
__device__ float g_base1[B_*DM_];
__device__ float g_basek[B_*DM_];
__device__ float g_basev[B_*DM_];
__device__ float g_basep[B_*8*DM_];
__device__ float g_Tk[DM_*DM_];
__device__ float g_Tv[DM_*DM_];
__device__ int   g_idxA[L_*NS_];
__device__ int   g_idxB[L_*NS_];
__device__ int   g_topidx[BH_*NS_];

// bf16-split operand buffers
__device__ __nv_bfloat16 g_Axd_hi[(size_t)BL_*DM_];
__device__ __nv_bfloat16 g_Axd_lo[(size_t)BL_*DM_];
__device__ __nv_bfloat16 g_Axp_hi[(size_t)BL_*DM_];
__device__ __nv_bfloat16 g_Axp_lo[(size_t)BL_*DM_];
__device__ __nv_bfloat16 g_Wt_hi[4*DM_*DM_];   // w0q, w0k, w0v, w1q
__device__ __nv_bfloat16 g_Wt_lo[4*DM_*DM_];

// ---------------- Threefry-2x32 (JAX-exact) ----------------
__host__ __device__ inline void tf2x32(unsigned k0, unsigned k1,
                                       unsigned x0, unsigned x1,
                                       unsigned* o0, unsigned* o1) {
    unsigned ks0 = k0, ks1 = k1, ks2 = 0x1BD11BDAu ^ k0 ^ k1;
    x0 += ks0; x1 += ks1;
#define TF_RND(r) { x0 += x1; x1 = (x1 << (r)) | (x1 >> (32 - (r))); x1 ^= x0; }
    TF_RND(13) TF_RND(15) TF_RND(26) TF_RND(6)   x0 += ks1; x1 += ks2 + 1u;
    TF_RND(17) TF_RND(29) TF_RND(16) TF_RND(24)  x0 += ks2; x1 += ks0 + 2u;
    TF_RND(13) TF_RND(15) TF_RND(26) TF_RND(6)   x0 += ks0; x1 += ks1 + 3u;
    TF_RND(17) TF_RND(29) TF_RND(16) TF_RND(24)  x0 += ks1; x1 += ks2 + 4u;
    TF_RND(13) TF_RND(15) TF_RND(26) TF_RND(6)   x0 += ks2; x1 += ks0 + 5u;
#undef TF_RND
    *o0 = x0; *o1 = x1;
}

__global__ void idx_kernel(unsigned k0, unsigned k1, int* __restrict__ out) {
    int i = blockIdx.x * blockDim.x + threadIdx.x;
    if (i >= L_*NS_) return;
    unsigned o0, o1;
    tf2x32(k0, k1, 0u, (unsigned)i, &o0, &o1);
    out[i] = (int)((o0 ^ o1) & 4095u);
}

// ---------------- bf16-split conversion kernels ----------------
__global__ __launch_bounds__(256)
void cvt_pair_kernel(const float4* __restrict__ src,
                     __nv_bfloat162* __restrict__ hi, __nv_bfloat162* __restrict__ lo,
                     int n4) {
    int i = blockIdx.x * 256 + threadIdx.x;
    if (i >= n4) return;
    float4 v = src[i];
    __nv_bfloat16 h0 = __float2bfloat16(v.x), h1 = __float2bfloat16(v.y);
    __nv_bfloat16 h2 = __float2bfloat16(v.z), h3 = __float2bfloat16(v.w);
    __nv_bfloat16 l0 = __float2bfloat16(v.x - __bfloat162float(h0));
    __nv_bfloat16 l1 = __float2bfloat16(v.y - __bfloat162float(h1));
    __nv_bfloat16 l2 = __float2bfloat16(v.z - __bfloat162float(h2));
    __nv_bfloat16 l3 = __float2bfloat16(v.w - __bfloat162float(h3));
    hi[i*2]   = __nv_bfloat162(h0, h1);
    hi[i*2+1] = __nv_bfloat162(h2, h3);
    lo[i*2]   = __nv_bfloat162(l0, l1);
    lo[i*2+1] = __nv_bfloat162(l2, l3);
}

struct W4 { const float* w[4]; };
__global__ __launch_bounds__(1024)
void wt_cvt_all_kernel(W4 ws, __nv_bfloat16* __restrict__ hi, __nv_bfloat16* __restrict__ lo) {
    __shared__ float t[32][33];
    int tx = threadIdx.x, ty = threadIdx.y;
    int n0 = blockIdx.x * 32, k0 = blockIdx.y * 32;
    int z = blockIdx.z;
    const float* W = ws.w[z];
    size_t off = (size_t)z * DM_ * DM_;
    t[ty][tx] = W[(size_t)(k0 + ty) * DM_ + n0 + tx];
    __syncthreads();
    float v = t[tx][ty];
    int n = n0 + ty, k = k0 + tx;
    __nv_bfloat16 h = __float2bfloat16(v);
    hi[off + (size_t)n * DM_ + k] = h;
    lo[off + (size_t)n * DM_ + k] = __float2bfloat16(v - __bfloat162float(h));
}

// ---------------- PTX helpers ----------------
__device__ __forceinline__ void cp16s(uint32_t saddr, const void* g) {
    asm volatile("cp.async.cg.shared.global [%0], [%1], 16;\n" :: "r"(saddr), "l"(g));
}
#define CP_COMMIT() asm volatile("cp.async.commit_group;\n" ::: "memory")
#define CP_WAIT(n)  asm volatile("cp.async.wait_group %0;\n" :: "n"(n) : "memory")

__device__ __forceinline__ void ldsm4(uint32_t& r0, uint32_t& r1, uint32_t& r2, uint32_t& r3,
                                      uint32_t saddr) {
    asm volatile("ldmatrix.sync.aligned.m8n8.x4.shared.b16 {%0,%1,%2,%3}, [%4];"
                 : "=r"(r0), "=r"(r1), "=r"(r2), "=r"(r3) : "r"(saddr));
}

__device__ __forceinline__ void mma_bf16(float* c, const uint32_t* a, const uint32_t* b) {
    asm volatile("mma.sync.aligned.m16n8k16.row.col.f32.bf16.bf16.f32 "
                 "{%0,%1,%2,%3}, {%4,%5,%6,%7}, {%8,%9}, {%0,%1,%2,%3};"
                 : "+f"(c[0]), "+f"(c[1]), "+f"(c[2]), "+f"(c[3])
                 : "r"(a[0]), "r"(a[1]), "r"(a[2]), "r"(a[3]), "r"(b[0]), "r"(b[1]));
}

// ---------------- mma.sync bf16-split GEMM (4-stage pipeline) ----------------
#define GST    40960
#define NSTG   4
#define GSMEM  (2048 + NSTG*GST)

__global__ __launch_bounds__(256, 1)
void gemm_mma(const __nv_bfloat16* __restrict__ Ahi, const __nv_bfloat16* __restrict__ Alo,
              const __nv_bfloat16* __restrict__ Bhi, const __nv_bfloat16* __restrict__ Blo,
              const float* __restrict__ bias, float* __restrict__ C) {
    extern __shared__ char smem[];
    const uint32_t sb = (uint32_t)__cvta_generic_to_shared(smem);
    const int tid = threadIdx.x;
    const int lane = tid & 31, wid = tid >> 5;
    const int warpM = wid >> 2, warpN = wid & 3;
    const int row0 = blockIdx.y * 128, col0 = blockIdx.x * 128;

    float* sbias = (float*)smem;
    if (tid < 128) sbias[tid] = bias[col0 + tid];

    float acc[4][4][4];
#pragma unroll
    for (int i = 0; i < 4; i++)
#pragma unroll
        for (int j = 0; j < 4; j++)
#pragma unroll
            for (int r = 0; r < 4; r++) acc[i][j][r] = 0.f;

    const int a_row = warpM * 64 + (lane & 15);
    const int a_kb  = ((lane >> 4) * 8) * 2;
    const int b_row = warpN * 32 + (lane & 7) + ((lane >> 4) & 1) * 8;
    const int b_kb  = (((lane >> 3) & 1) * 8) * 2;

#define LOAD_CHUNK(c, s) {                                                     \
    uint32_t stb = sb + 2048 + (uint32_t)(s) * GST;                            \
    int k0 = (c) * 32;                                                         \
    _Pragma("unroll")                                                          \
    for (int j = 0; j < 8; j++) {                                              \
        int idx = tid + j * 256;                                               \
        int tile = idx >> 9, w = idx & 511;                                    \
        int r = w >> 2, cc = w & 3;                                            \
        uint32_t so = stb + (uint32_t)tile * 10240u + (uint32_t)(r * 80 + cc * 16); \
        const __nv_bfloat16* gp;                                               \
        if      (tile == 0) gp = Ahi + (size_t)(row0 + r) * DM_ + k0 + cc * 8; \
        else if (tile == 1) gp = Alo + (size_t)(row0 + r) * DM_ + k0 + cc * 8; \
        else if (tile == 2) gp = Bhi + (size_t)(col0 + r) * DM_ + k0 + cc * 8; \
        else                gp = Blo + (size_t)(col0 + r) * DM_ + k0 + cc * 8; \
        cp16s(so, gp);                                                         \
    }                                                                          \
    CP_COMMIT(); }

#define COMPUTE(s) {                                                                 \
    uint32_t stb = sb + 2048 + (uint32_t)(s) * GST;                                  \
    _Pragma("unroll")                                                                \
    for (int k16 = 0; k16 < 2; k16++) {                                             \
        uint32_t ah[4][4], al[4][4], bh[4][2], bl[4][2];                             \
        _Pragma("unroll")                                                            \
        for (int i = 0; i < 4; i++)                                                  \
            ldsm4(ah[i][0], ah[i][1], ah[i][2], ah[i][3],                            \
                  stb + (uint32_t)((a_row + i*16) * 80 + k16*32 + a_kb));            \
        _Pragma("unroll")                                                            \
        for (int n16 = 0; n16 < 2; n16++)                                            \
            ldsm4(bh[n16*2][0], bh[n16*2][1], bh[n16*2+1][0], bh[n16*2+1][1],        \
                  stb + 20480u + (uint32_t)((b_row + n16*16) * 80 + k16*32 + b_kb)); \
        _Pragma("unroll")                                                            \
        for (int i = 0; i < 4; i++)                                                  \
            _Pragma("unroll")                                                        \
            for (int j = 0; j < 4; j++) mma_bf16(acc[i][j], ah[i], bh[j]);           \
        _Pragma("unroll")                                                            \
        for (int n16 = 0; n16 < 2; n16++)                                            \
            ldsm4(bl[n16*2][0], bl[n16*2][1], bl[n16*2+1][0], bl[n16*2+1][1],        \
                  stb + 30720u + (uint32_t)((b_row + n16*16) * 80 + k16*32 + b_kb)); \
        _Pragma("unroll")                                                            \
        for (int i = 0; i < 4; i++)                                                  \
            _Pragma("unroll")                                                        \
            for (int j = 0; j < 4; j++) mma_bf16(acc[i][j], ah[i], bl[j]);           \
        _Pragma("unroll")                                                            \
        for (int i = 0; i < 4; i++)                                                  \
            ldsm4(al[i][0], al[i][1], al[i][2], al[i][3],                            \
                  stb + 10240u + (uint32_t)((a_row + i*16) * 80 + k16*32 + a_kb));   \
        _Pragma("unroll")                                                            \
        for (int i = 0; i < 4; i++)                                                  \
            _Pragma("unroll")                                                        \
            for (int j = 0; j < 4; j++) mma_bf16(acc[i][j], al[i], bh[j]);           \
    } }

    LOAD_CHUNK(0, 0);
    LOAD_CHUNK(1, 1);
    LOAD_CHUNK(2, 2);

    const int nIter = DM_ / 32;   // 16
#pragma unroll 1
    for (int c = 0; c < nIter; c++) {
        if (c < nIter - 2)      { CP_WAIT(2); }
        else if (c == nIter - 2){ CP_WAIT(1); }
        else                    { CP_WAIT(0); }
        __syncthreads();
        if (c + 3 < nIter) LOAD_CHUNK(c + 3, (c + 3) & 3);
        COMPUTE(c & 3);
    }

    __syncthreads();
#pragma unroll
    for (int i = 0; i < 4; i++) {
#pragma unroll
        for (int j = 0; j < 4; j++) {
            int colg = col0 + warpN * 32 + j * 8 + (lane & 3) * 2;
            int hh = colg >> 6, d0 = colg & 63;
            float b0v = sbias[colg - col0], b1v = sbias[colg - col0 + 1];
#pragma unroll
            for (int half = 0; half < 2; half++) {
                int m = row0 + warpM * 64 + i * 16 + (lane >> 2) + half * 8;
                int b = m >> 12, l = m & 4095;
                float2 v;
                v.x = acc[i][j][half*2 + 0] + b0v;
                v.y = acc[i][j][half*2 + 1] + b1v;
                *(float2*)(C + (((size_t)(b * H_ + hh) * L_) + l) * D_ + d0) = v;
            }
        }
    }
#undef LOAD_CHUNK
#undef COMPUTE
}

// ---------------- small fp32 GEMM: C(512x512) = A @ B ----------------
__global__ __launch_bounds__(256)
void sgemm_T(const float* __restrict__ A, const float* __restrict__ Bm,
             float* __restrict__ C) {
    __shared__ float As[16][68];
    __shared__ float Bs[16][64];
    int tid = threadIdx.x, tx = tid & 15, ty = tid >> 4;
    int r0 = blockIdx.y * 64, c0 = blockIdx.x * 64;
    float acc[4][4];
#pragma unroll
    for (int i = 0; i < 4; i++)
#pragma unroll
        for (int j = 0; j < 4; j++) acc[i][j] = 0.f;

    for (int kt = 0; kt < DM_; kt += 16) {
        int m = tid >> 2, k4 = tid & 3;
        float4 av = *(const float4*)(A + (size_t)(r0 + m) * DM_ + kt + k4 * 4);
        As[k4*4+0][m] = av.x; As[k4*4+1][m] = av.y;
        As[k4*4+2][m] = av.z; As[k4*4+3][m] = av.w;
        int kk = tid >> 4, n4 = tid & 15;
        *(float4*)&Bs[kk][n4 * 4] = *(const float4*)(Bm + (size_t)(kt + kk) * DM_ + c0 + n4 * 4);
        __syncthreads();
#pragma unroll
        for (int k = 0; k < 16; k++) {
            float a[4], b[4];
            *(float4*)a = *(const float4*)&As[k][ty * 4];
            *(float4*)b = *(const float4*)&Bs[k][tx * 4];
#pragma unroll
            for (int i = 0; i < 4; i++)
#pragma unroll
                for (int j = 0; j < 4; j++) acc[i][j] += a[i] * b[j];
        }
        __syncthreads();
    }
#pragma unroll
    for (int i = 0; i < 4; i++) {
        float4 v = make_float4(acc[i][0], acc[i][1], acc[i][2], acc[i][3]);
        *(float4*)(C + (size_t)(r0 + ty * 4 + i) * DM_ + c0 + tx * 4) = v;
    }
}

// ---------------- M[bh][l] = max_s(q·k_s) - sum_s(q·k_s)/L ----------------
__global__ __launch_bounds__(256)
void sample_m_kernel(const int* __restrict__ idx) {
    int gw = (blockIdx.x * blockDim.x + threadIdx.x) >> 5;
    int lane = threadIdx.x & 31;
    if (gw >= BH_ * L_) return;
    int bh = gw >> 12, l = gw & 4095;
    const float4* qrow = (const float4*)(g_Q + ((size_t)bh * L_ + l) * D_);
    float val = 0.f;
    bool active = lane < NS_;
    if (active) {
        int kk = idx[l * NS_ + lane];
        const float4* krow = (const float4*)(g_K + ((size_t)bh * L_ + kk) * D_);
        float s = 0.f;
#pragma unroll
        for (int d4 = 0; d4 < 16; d4++) {
            float4 q = qrow[d4], k = krow[d4];
            s += q.x*k.x + q.y*k.y + q.z*k.z + q.w*k.w;
        }
        val = s;
    }
    float mx = active ? val : -__int_as_float(0x7f800000);
    float sm = active ? val : 0.f;
#pragma unroll
    for (int off = 16; off > 0; off >>= 1) {
        mx = fmaxf(mx, __shfl_down_sync(0xffffffffu, mx, off));
        sm += __shfl_down_sync(0xffffffffu, sm, off);
    }
    if (lane == 0) g_M[gw] = mx - sm * (1.f / (float)L_);
}

// ---------------- top-27 via packed-key shfl reduce ----------------
__device__ __forceinline__ unsigned ordf(float v) {
    unsigned u = __float_as_uint(v);
    return (u & 0x80000000u) ? ~u : (u | 0x80000000u);
}

__global__ __launch_bounds__(256)
void topk_kernel() {
    int bh = blockIdx.x, t = threadIdx.x;
    int lane = t & 31, wid = t >> 5;
    __shared__ float sm[L_];
    __shared__ unsigned long long wred[8];
    for (int i = t; i < L_; i += 256) sm[i] = g_M[(size_t)bh * L_ + i];
    __syncthreads();
    for (int it = 0; it < NS_; it++) {
        unsigned long long best = 0ull;
#pragma unroll
        for (int jj = 0; jj < L_ / 256; jj++) {
            int i = t + jj * 256;
            unsigned long long key = ((unsigned long long)ordf(sm[i]) << 32)
                                   | (unsigned)(L_ - 1 - i);
            if (key > best) best = key;
        }
#pragma unroll
        for (int off = 16; off > 0; off >>= 1) {
            unsigned long long o = __shfl_down_sync(0xffffffffu, best, off);
            if (o > best) best = o;
        }
        if (lane == 0) wred[wid] = best;
        __syncthreads();
        if (t == 0) {
            unsigned long long b2 = wred[0];
#pragma unroll
            for (int w = 1; w < 8; w++) if (wred[w] > b2) b2 = wred[w];
            int idx = L_ - 1 - (int)(b2 & 0xFFFFFFFFull);
            g_topidx[bh * NS_ + it] = idx;
            sm[idx] = -__int_as_float(0x7f800000);
        }
        __syncthreads();
    }
}

// ---------------- meanV: two-stage deterministic reduce ----------------
__global__ __launch_bounds__(256)
void meanv1_kernel() {
    int bh = blockIdx.x, c = blockIdx.y, t = threadIdx.x;
    int d = t & 63, r = t >> 6;
    float s = 0.f;
    int base = c * 256;
    for (int l = base + r; l < base + 256; l += 4)
        s += g_V[((size_t)bh * L_ + l) * D_ + d];
    __shared__ float red[256];
    red[t] = s; __syncthreads();
    if (t < 64)
        g_vpart[(bh * 16 + c) * D_ + d] = red[d] + red[64+d] + red[128+d] + red[192+d];
}

__global__ __launch_bounds__(64)
void meanv2_kernel() {
    int bh = blockIdx.x, d = threadIdx.x;
    float s = 0.f;
#pragma unroll
    for (int c = 0; c < 16; c++) s += g_vpart[(bh * 16 + c) * D_ + d];
    g_meanV[bh * D_ + d] = s * (1.f / (float)L_);
}

// ---------------- scores S[bh][u][k] = 0.125 * Q[top_u]·K[k] ----------------
__global__ __launch_bounds__(128)
void scores_kernel() {
    int bh = blockIdx.x, kt = blockIdx.y, t = threadIdx.x;
    __shared__ float Qs[NS_][64];
    __shared__ float KsT[64][129];
    for (int f = t; f < NS_ * 16; f += 128) {
        int u = f >> 4, d4 = f & 15;
        int l = g_topidx[bh * NS_ + u];
        *(float4*)&Qs[u][d4 * 4] = *(const float4*)(g_Q + ((size_t)bh * L_ + l) * D_ + d4 * 4);
    }
    for (int f = t; f < 128 * 16; f += 128) {
        int kk = f >> 4, d4 = f & 15;
        float4 v = *(const float4*)(g_K + ((size_t)bh * L_ + kt * 128 + kk) * D_ + d4 * 4);
        KsT[d4*4+0][kk] = v.x; KsT[d4*4+1][kk] = v.y;
        KsT[d4*4+2][kk] = v.z; KsT[d4*4+3][kk] = v.w;
    }
    __syncthreads();
    float acc[NS_];
#pragma unroll
    for (int u = 0; u < NS_; u++) acc[u] = 0.f;
    int kk = t;
#pragma unroll
    for (int d0 = 0; d0 < 64; d0 += 4) {
        float k0 = KsT[d0][kk], k1 = KsT[d0+1][kk], k2 = KsT[d0+2][kk], k3 = KsT[d0+3][kk];
#pragma unroll
        for (int u = 0; u < NS_; u++) {
            float4 q = *(const float4*)&Qs[u][d0];
            acc[u] += q.x*k0 + q.y*k1 + q.z*k2 + q.w*k3;
        }
    }
#pragma unroll
    for (int u = 0; u < NS_; u++)
        g_S[((size_t)bh * NS_ + u) * L_ + kt * 128 + kk] = acc[u] * 0.125f;
}

// ---------------- softmax over each S row (in place) ----------------
__global__ __launch_bounds__(256)
void softmax_kernel() {
    int row = blockIdx.x, t = threadIdx.x;
    float* p = g_S + (size_t)row * L_;
    __shared__ float sm[L_];
    __shared__ float red[256];
    float mx = -__int_as_float(0x7f800000);
    for (int i = t; i < L_; i += 256) { float v = p[i]; sm[i] = v; mx = fmaxf(mx, v); }
    red[t] = mx; __syncthreads();
    for (int s = 128; s > 0; s >>= 1) { if (t < s) red[t] = fmaxf(red[t], red[t+s]); __syncthreads(); }
    float m = red[0];
    __syncthreads();
    float ss = 0.f;
    for (int i = t; i < L_; i += 256) { float e = expf(sm[i] - m); sm[i] = e; ss += e; }
    red[t] = ss; __syncthreads();
    for (int s = 128; s > 0; s >>= 1) { if (t < s) red[t] += red[t+s]; __syncthreads(); }
    float inv = 1.f / red[0];
    for (int i = t; i < L_; i += 256) p[i] = sm[i] * inv;
}

// ---------------- out_top[bh][u][d] += P[u][k] * V[k][d] (split-k) ---------
__global__ __launch_bounds__(256)
void pv_kernel() {
    int bh = blockIdx.x, kc = blockIdx.y, t = threadIdx.x;
    int d = t & 63, ug = t >> 6;
    float acc[7];
#pragma unroll
    for (int j = 0; j < 7; j++) acc[j] = 0.f;
    int k0 = kc * 512;
    for (int k = k0; k < k0 + 512; k += 4) {
        float v0 = g_V[((size_t)bh * L_ + k + 0) * D_ + d];
        float v1 = g_V[((size_t)bh * L_ + k + 1) * D_ + d];
        float v2 = g_V[((size_t)bh * L_ + k + 2) * D_ + d];
        float v3 = g_V[((size_t)bh * L_ + k + 3) * D_ + d];
#pragma unroll
        for (int j = 0; j < 7; j++) {
            int u = ug + j * 4;
            if (u < NS_) {
                float4 pv = *(const float4*)(g_S + ((size_t)bh * NS_ + u) * L_ + k);
                acc[j] += pv.x*v0 + pv.y*v1 + pv.z*v2 + pv.w*v3;
            }
        }
    }
#pragma unroll
    for (int j = 0; j < 7; j++) {
        int u = ug + j * 4;
        if (u < NS_) atomicAdd(&g_outtop[(bh * NS_ + u) * D_ + d], acc[j]);
    }
}

// ---------------- generic GEMV: partials then combine ----------------
__global__ __launch_bounds__(512)
void base1g_kernel(const float* __restrict__ invec, const float* __restrict__ w) {
    int b = blockIdx.x, kc = blockIdx.y, n = threadIdx.x;
    __shared__ float mc[64];
    if (n < 64) mc[n] = invec[b * DM_ + kc * 64 + n];
    __syncthreads();
    float s = 0.f;
#pragma unroll 8
    for (int k = 0; k < 64; k++) s += mc[k] * w[(size_t)(kc * 64 + k) * DM_ + n];
    g_basep[(b * 8 + kc) * DM_ + n] = s;
}

__global__ __launch_bounds__(512)
void base2g_kernel(const float* __restrict__ bias, float* __restrict__ outv) {
    int b = blockIdx.x, n = threadIdx.x;
    float s = bias[n];
#pragma unroll
    for (int p = 0; p < 8; p++) s += g_basep[(b * 8 + p) * DM_ + n];
    outv[b * DM_ + n] = s;
}

// ---------------- fill K/V with per-(b,h) broadcast base row ----------------
__global__ __launch_bounds__(256)
void fill_bcast_kernel(float* __restrict__ dst, const float* __restrict__ basev) {
    int i4 = blockIdx.x * 256 + threadIdx.x;   // over BH_*L_*16 float4
    int d4 = i4 & 15;
    int h = (i4 >> 16) & 7;
    int b = i4 >> 19;
    ((float4*)dst)[i4] = ((const float4*)basev)[b * 128 + h * 16 + d4];
}

// ---------------- K/V corrections: dst[b,:,l,:] += qv @ T[h0*64:,:] ----------
__global__ __launch_bounds__(128)
void corr_kv_kernel(const float* __restrict__ T, float* __restrict__ dst) {
    int blk = blockIdx.x;
    int bh0 = blk / NS_, u = blk % NS_;
    int b = bh0 >> 3, h0 = bh0 & 7;
    int t = threadIdx.x;
    __shared__ float qv[64];
    if (t < 64) qv[t] = g_outtop[(bh0 * NS_ + u) * 64 + t] - g_meanV[bh0 * 64 + t];
    __syncthreads();
    int l = g_topidx[bh0 * NS_ + u];
    float a0 = 0.f, a1 = 0.f, a2 = 0.f, a3 = 0.f;
#pragma unroll 8
    for (int k = 0; k < 64; k++) {
        float q = qv[k];
        float4 w = *(const float4*)(T + (size_t)(h0 * 64 + k) * DM_ + t * 4);
        a0 += q * w.x; a1 += q * w.y; a2 += q * w.z; a3 += q * w.w;
    }
    int n0 = t * 4;
    int h = n0 >> 6, d = n0 & 63;
    float* d_ = dst + (((size_t)(b * H_ + h) * L_) + l) * D_ + d;
    atomicAdd(d_ + 0, a0); atomicAdd(d_ + 1, a1);
    atomicAdd(d_ + 2, a2); atomicAdd(d_ + 3, a3);
}

// ---------------- output broadcasts ----------------
__global__ __launch_bounds__(256)
void bcast_out_kernel(const float* __restrict__ xs, float* __restrict__ out,
                      const float* __restrict__ basev, int row_off) {
    int i4 = blockIdx.x * 256 + threadIdx.x;   // over B_*L_*128
    int n4 = i4 & 127;
    int l = (i4 >> 7) & 4095;
    int b = i4 / (L_ * 128);
    size_t oi = ((size_t)(b * 8192 + row_off + l)) * 128 + n4;
    float4 a = ((const float4*)xs)[oi];
    float4 s = ((const float4*)basev)[b * 128 + n4];
    a.x += s.x; a.y += s.y; a.z += s.z; a.w += s.w;
    ((float4*)out)[oi] = a;
}

// corrections into output rows: out[b, row_off + l] += qv @ Wo[h0*64:,:]
__global__ __launch_bounds__(128)
void corr_kernel(const float* __restrict__ wo, float* __restrict__ dst, int row_off) {
    int blk = blockIdx.x;
    int bh = blk / NS_, u = blk % NS_;
    int b = bh >> 3, h = bh & 7;
    int t = threadIdx.x;
    __shared__ float qv[64];
    if (t < 64) qv[t] = g_outtop[(bh * NS_ + u) * 64 + t] - g_meanV[bh * 64 + t];
    __syncthreads();
    int l = g_topidx[bh * NS_ + u];
    float a0 = 0.f, a1 = 0.f, a2 = 0.f, a3 = 0.f;
#pragma unroll 8
    for (int k = 0; k < 64; k++) {
        float q = qv[k];
        float4 w = *(const float4*)(wo + (size_t)(h * 64 + k) * DM_ + t * 4);
        a0 += q * w.x; a1 += q * w.y; a2 += q * w.z; a3 += q * w.w;
    }
    float* d = dst + ((size_t)(b * 8192 + row_off + l)) * DM_ + t * 4;
    atomicAdd(d + 0, a0); atomicAdd(d + 1, a1);
    atomicAdd(d + 2, a2); atomicAdd(d + 3, a3);
}

// ---------------- host orchestration ----------------
extern "C" void kernel_launch(void* const* d_in, const int* in_sizes, int n_in,
                              void* d_out, int out_size) {
    const float* xs  = (const float*)d_in[0];
    const float* xd  = (const float*)d_in[1];
    const float* xp  = (const float*)d_in[2];
    const float* w0q = (const float*)d_in[3];
    const float* w0k = (const float*)d_in[4];
    const float* w0v = (const float*)d_in[5];
    const float* w0o = (const float*)d_in[6];
    const float* b0q = (const float*)d_in[7];
    const float* b0k = (const float*)d_in[8];
    const float* b0v = (const float*)d_in[9];
    const float* b0o = (const float*)d_in[10];
    const float* w1q = (const float*)d_in[11];
    const float* w1k = (const float*)d_in[12];
    const float* w1v = (const float*)d_in[13];
    const float* w1o = (const float*)d_in[14];
    const float* b1q = (const float*)d_in[15];
    const float* b1k = (const float*)d_in[16];
    const float* b1v = (const float*)d_in[17];
    const float* b1o = (const float*)d_in[18];
    float* out = (float*)d_out;

    float *pQ, *pK, *pV, *pouttop, *pmv, *pb0, *pb1, *pbk, *pbv, *pTk, *pTv;
    int *pidxA, *pidxB;
    __nv_bfloat16 *pAxdH, *pAxdL, *pAxpH, *pAxpL, *pWtH, *pWtL;
    cudaGetSymbolAddress((void**)&pQ, g_Q);
    cudaGetSymbolAddress((void**)&pK, g_K);
    cudaGetSymbolAddress((void**)&pV, g_V);
    cudaGetSymbolAddress((void**)&pouttop, g_outtop);
    cudaGetSymbolAddress((void**)&pmv, g_meanV);
    cudaGetSymbolAddress((void**)&pb0, g_base0);
    cudaGetSymbolAddress((void**)&pb1, g_base1);
    cudaGetSymbolAddress((void**)&pbk, g_basek);
    cudaGetSymbolAddress((void**)&pbv, g_basev);
    cudaGetSymbolAddress((void**)&pTk, g_Tk);
    cudaGetSymbolAddress((void**)&pTv, g_Tv);
    cudaGetSymbolAddress((void**)&pidxA, g_idxA);
    cudaGetSymbolAddress((void**)&pidxB, g_idxB);
    cudaGetSymbolAddress((void**)&pAxdH, g_Axd_hi);
    cudaGetSymbolAddress((void**)&pAxdL, g_Axd_lo);
    cudaGetSymbolAddress((void**)&pAxpH, g_Axp_hi);
    cudaGetSymbolAddress((void**)&pAxpL, g_Axp_lo);
    cudaGetSymbolAddress((void**)&pWtH, g_Wt_hi);
    cudaGetSymbolAddress((void**)&pWtL, g_Wt_lo);

    cudaFuncSetAttribute(gemm_mma, cudaFuncAttributeMaxDynamicSharedMemorySize, GSMEM);

    unsigned a42, b42, a43, b43;
    tf2x32(0u, 42u, 0u, 1u, &a42, &b42);
    tf2x32(0u, 43u, 0u, 1u, &a43, &b43);
    idx_kernel<<<(L_ * NS_ + 255) / 256, 256>>>(a42, b42, pidxA);
    idx_kernel<<<(L_ * NS_ + 255) / 256, 256>>>(a43, b43, pidxB);

    // 4 dense-GEMM weights: w0q, w0k, w0v, w1q
    W4 ws;
    ws.w[0] = w0q; ws.w[1] = w0k; ws.w[2] = w0v; ws.w[3] = w1q;
    wt_cvt_all_kernel<<<dim3(16, 16, 4), dim3(32, 32)>>>(ws, pWtH, pWtL);

    // T = Wo0 @ W1{k,v} for the factored layer-1 K/V path
    sgemm_T<<<dim3(8, 8), 256>>>(w0o, w1k, pTk);
    sgemm_T<<<dim3(8, 8), 256>>>(w0o, w1v, pTv);

    const int N4 = BL_ * DM_ / 4;
    cvt_pair_kernel<<<(N4 + 255) / 256, 256>>>((const float4*)xd,
        (__nv_bfloat162*)pAxdH, (__nv_bfloat162*)pAxdL, N4);
    cvt_pair_kernel<<<(N4 + 255) / 256, 256>>>((const float4*)xp,
        (__nv_bfloat162*)pAxpH, (__nv_bfloat162*)pAxpL, N4);

    dim3 ggrid(DM_ / 128, BL_ / 128);   // (4, 128)

    // ---- layer 0: xp2 = attn(xp; xd, xd) ----
    gemm_mma<<<ggrid, 256, GSMEM>>>(pAxpH, pAxpL, pWtH + 0*(size_t)DM_*DM_, pWtL + 0*(size_t)DM_*DM_, b0q, pQ);
    gemm_mma<<<ggrid, 256, GSMEM>>>(pAxdH, pAxdL, pWtH + 1*(size_t)DM_*DM_, pWtL + 1*(size_t)DM_*DM_, b0k, pK);
    gemm_mma<<<ggrid, 256, GSMEM>>>(pAxdH, pAxdL, pWtH + 2*(size_t)DM_*DM_, pWtL + 2*(size_t)DM_*DM_, b0v, pV);
    sample_m_kernel<<<(BH_ * L_) / 8, 256>>>(pidxA);
    topk_kernel<<<BH_, 256>>>();
    meanv1_kernel<<<dim3(BH_, 16), 256>>>();
    meanv2_kernel<<<BH_, 64>>>();
    cudaMemsetAsync(pouttop, 0, (size_t)BH_ * NS_ * D_ * sizeof(float));
    scores_kernel<<<dim3(BH_, L_ / 128), 128>>>();
    softmax_kernel<<<BH_ * NS_, 256>>>();
    pv_kernel<<<dim3(BH_, 8), 256>>>();

    // base0 = meanctx0 @ Wo0 + bo0
    base1g_kernel<<<dim3(B_, 8), 512>>>(pmv, w0o);
    base2g_kernel<<<B_, 512>>>(b0o, pb0);

    // output upper half (xp2): xs + base0 + layer-0 corrections
    bcast_out_kernel<<<(B_ * L_ * 128) / 256, 256>>>(xs, out, pb0, 4096);
    corr_kernel<<<BH_ * NS_, 128>>>(w0o, out, 4096);

    // ---- build K1, V1 without dense GEMMs ----
    base1g_kernel<<<dim3(B_, 8), 512>>>(pb0, w1k);
    base2g_kernel<<<B_, 512>>>(b1k, pbk);
    base1g_kernel<<<dim3(B_, 8), 512>>>(pb0, w1v);
    base2g_kernel<<<B_, 512>>>(b1v, pbv);
    fill_bcast_kernel<<<(BH_ * L_ * 16) / 256, 256>>>(pK, pbk);
    fill_bcast_kernel<<<(BH_ * L_ * 16) / 256, 256>>>(pV, pbv);
    corr_kv_kernel<<<BH_ * NS_, 128>>>(pTk, pK);
    corr_kv_kernel<<<BH_ * NS_, 128>>>(pTv, pV);

    // layer-1 Q (dense GEMM from xd)
    gemm_mma<<<ggrid, 256, GSMEM>>>(pAxdH, pAxdL, pWtH + 3*(size_t)DM_*DM_, pWtL + 3*(size_t)DM_*DM_, b1q, pQ);

    // ---- layer 1 attention ----
    sample_m_kernel<<<(BH_ * L_) / 8, 256>>>(pidxB);
    topk_kernel<<<BH_, 256>>>();
    meanv1_kernel<<<dim3(BH_, 16), 256>>>();
    meanv2_kernel<<<BH_, 64>>>();
    cudaMemsetAsync(pouttop, 0, (size_t)BH_ * NS_ * D_ * sizeof(float));
    scores_kernel<<<dim3(BH_, L_ / 128), 128>>>();
    softmax_kernel<<<BH_ * NS_, 256>>>();
    pv_kernel<<<dim3(BH_, 8), 256>>>();

    // base1 = meanctx1 @ W1o + b1o; output lower half (xd2)
    base1g_kernel<<<dim3(B_, 8), 512>>>(pmv, w1o);
    base2g_kernel<<<B_, 512>>>(b1o, pb1);
    bcast_out_kernel<<<(B_ * L_ * 128) / 256, 256>>>(xs, out, pb1, 0);
    corr_kernel<<<BH_ * NS_, 128>>>(w1o, out, 0);
}

// round 7
// speedup vs baseline: 2.0888x; 1.0412x over previous
#include <cuda_runtime.h>
#include <cuda_bf16.h>
#include <math.h>
#include <stdint.h>

#define B_   4
#define H_   8
#define L_   4096
#define D_   64
#define DM_  512
#define NS_  27
#define BH_  (B_*H_)
#define BL_  (B_*L_)

// ---------------- scratch (device globals; no runtime alloc) ----------------
__device__ float g_Q[BH_*L_*D_];
__device__ float g_K[BH_*L_*D_];
__device__ float g_V[BH_*L_*D_];
__device__ float g_M[BH_*L_];
__device__ float g_S[(size_t)BH_*NS_*L_];
__device__ float g_outtop[BH_*NS_*D_];
__device__ float g_meanV[BH_*D_];
__device__ float g_vpart[BH_*16*D_];
__device__ float g_base0[B_*DM_];
__device__ float g_base1[B_*DM_];
__device__ float g_basekv[2*B_*DM_];          // [0]=K base, [1]=V base
__device__ float g_basep[B_*8*DM_];
__device__ float g_basep2[2*B_*8*DM_];        // partials for K/V GEMVs
__device__ float g_Tkv[2*DM_*DM_];            // [0]=Tk, [1]=Tv
__device__ float g_Tp[16*DM_*DM_];            // split-K partials (2 mats x 8 slices)
__device__ int   g_idxA[L_*NS_];
__device__ int   g_idxB[L_*NS_];
__device__ int   g_topidx[BH_*NS_];

// bf16-split operand buffers
__device__ __nv_bfloat16 g_Axd_hi[(size_t)BL_*DM_];
__device__ __nv_bfloat16 g_Axd_lo[(size_t)BL_*DM_];
__device__ __nv_bfloat16 g_Axp_hi[(size_t)BL_*DM_];
__device__ __nv_bfloat16 g_Axp_lo[(size_t)BL_*DM_];
__device__ __nv_bfloat16 g_Wt_hi[4*DM_*DM_];   // w0q, w0k, w0v, w1q
__device__ __nv_bfloat16 g_Wt_lo[4*DM_*DM_];

// ---------------- Threefry-2x32 (JAX-exact) ----------------
__host__ __device__ inline void tf2x32(unsigned k0, unsigned k1,
                                       unsigned x0, unsigned x1,
                                       unsigned* o0, unsigned* o1) {
    unsigned ks0 = k0, ks1 = k1, ks2 = 0x1BD11BDAu ^ k0 ^ k1;
    x0 += ks0; x1 += ks1;
#define TF_RND(r) { x0 += x1; x1 = (x1 << (r)) | (x1 >> (32 - (r))); x1 ^= x0; }
    TF_RND(13) TF_RND(15) TF_RND(26) TF_RND(6)   x0 += ks1; x1 += ks2 + 1u;
    TF_RND(17) TF_RND(29) TF_RND(16) TF_RND(24)  x0 += ks2; x1 += ks0 + 2u;
    TF_RND(13) TF_RND(15) TF_RND(26) TF_RND(6)   x0 += ks0; x1 += ks1 + 3u;
    TF_RND(17) TF_RND(29) TF_RND(16) TF_RND(24)  x0 += ks1; x1 += ks2 + 4u;
    TF_RND(13) TF_RND(15) TF_RND(26) TF_RND(6)   x0 += ks2; x1 += ks0 + 5u;
#undef TF_RND
    *o0 = x0; *o1 = x1;
}

__global__ void idx_kernel(unsigned k0, unsigned k1, int* __restrict__ out) {
    int i = blockIdx.x * blockDim.x + threadIdx.x;
    if (i >= L_*NS_) return;
    unsigned o0, o1;
    tf2x32(k0, k1, 0u, (unsigned)i, &o0, &o1);
    out[i] = (int)((o0 ^ o1) & 4095u);
}

// ---------------- bf16-split conversion (both inputs in one launch) --------
struct Cvt2 { const float4* src[2]; __nv_bfloat162* hi[2]; __nv_bfloat162* lo[2]; };
__global__ __launch_bounds__(256)
void cvt_pair2_kernel(Cvt2 c, int n4) {
    int i = blockIdx.x * 256 + threadIdx.x;
    if (i >= n4) return;
    int z = blockIdx.y;
    float4 v = c.src[z][i];
    __nv_bfloat16 h0 = __float2bfloat16(v.x), h1 = __float2bfloat16(v.y);
    __nv_bfloat16 h2 = __float2bfloat16(v.z), h3 = __float2bfloat16(v.w);
    __nv_bfloat16 l0 = __float2bfloat16(v.x - __bfloat162float(h0));
    __nv_bfloat16 l1 = __float2bfloat16(v.y - __bfloat162float(h1));
    __nv_bfloat16 l2 = __float2bfloat16(v.z - __bfloat162float(h2));
    __nv_bfloat16 l3 = __float2bfloat16(v.w - __bfloat162float(h3));
    c.hi[z][i*2]   = __nv_bfloat162(h0, h1);
    c.hi[z][i*2+1] = __nv_bfloat162(h2, h3);
    c.lo[z][i*2]   = __nv_bfloat162(l0, l1);
    c.lo[z][i*2+1] = __nv_bfloat162(l2, l3);
}

__global__ __launch_bounds__(256)
void cvt_pair_kernel(const float4* __restrict__ src,
                     __nv_bfloat162* __restrict__ hi, __nv_bfloat162* __restrict__ lo,
                     int n4) {
    int i = blockIdx.x * 256 + threadIdx.x;
    if (i >= n4) return;
    float4 v = src[i];
    __nv_bfloat16 h0 = __float2bfloat16(v.x), h1 = __float2bfloat16(v.y);
    __nv_bfloat16 h2 = __float2bfloat16(v.z), h3 = __float2bfloat16(v.w);
    __nv_bfloat16 l0 = __float2bfloat16(v.x - __bfloat162float(h0));
    __nv_bfloat16 l1 = __float2bfloat16(v.y - __bfloat162float(h1));
    __nv_bfloat16 l2 = __float2bfloat16(v.z - __bfloat162float(h2));
    __nv_bfloat16 l3 = __float2bfloat16(v.w - __bfloat162float(h3));
    hi[i*2]   = __nv_bfloat162(h0, h1);
    hi[i*2+1] = __nv_bfloat162(h2, h3);
    lo[i*2]   = __nv_bfloat162(l0, l1);
    lo[i*2+1] = __nv_bfloat162(l2, l3);
}

struct W4 { const float* w[4]; };
__global__ __launch_bounds__(1024)
void wt_cvt_all_kernel(W4 ws, __nv_bfloat16* __restrict__ hi, __nv_bfloat16* __restrict__ lo) {
    __shared__ float t[32][33];
    int tx = threadIdx.x, ty = threadIdx.y;
    int n0 = blockIdx.x * 32, k0 = blockIdx.y * 32;
    int z = blockIdx.z;
    const float* W = ws.w[z];
    size_t off = (size_t)z * DM_ * DM_;
    t[ty][tx] = W[(size_t)(k0 + ty) * DM_ + n0 + tx];
    __syncthreads();
    float v = t[tx][ty];
    int n = n0 + ty, k = k0 + tx;
    __nv_bfloat16 h = __float2bfloat16(v);
    hi[off + (size_t)n * DM_ + k] = h;
    lo[off + (size_t)n * DM_ + k] = __float2bfloat16(v - __bfloat162float(h));
}

// ---------------- PTX helpers ----------------
__device__ __forceinline__ void cp16s(uint32_t saddr, const void* g) {
    asm volatile("cp.async.cg.shared.global [%0], [%1], 16;\n" :: "r"(saddr), "l"(g));
}
#define CP_COMMIT() asm volatile("cp.async.commit_group;\n" ::: "memory")
#define CP_WAIT(n)  asm volatile("cp.async.wait_group %0;\n" :: "n"(n) : "memory")

__device__ __forceinline__ void ldsm4(uint32_t& r0, uint32_t& r1, uint32_t& r2, uint32_t& r3,
                                      uint32_t saddr) {
    asm volatile("ldmatrix.sync.aligned.m8n8.x4.shared.b16 {%0,%1,%2,%3}, [%4];"
                 : "=r"(r0), "=r"(r1), "=r"(r2), "=r"(r3) : "r"(saddr));
}

__device__ __forceinline__ void mma_bf16(float* c, const uint32_t* a, const uint32_t* b) {
    asm volatile("mma.sync.aligned.m16n8k16.row.col.f32.bf16.bf16.f32 "
                 "{%0,%1,%2,%3}, {%4,%5,%6,%7}, {%8,%9}, {%0,%1,%2,%3};"
                 : "+f"(c[0]), "+f"(c[1]), "+f"(c[2]), "+f"(c[3])
                 : "r"(a[0]), "r"(a[1]), "r"(a[2]), "r"(a[3]), "r"(b[0]), "r"(b[1]));
}

// ---------------- mma.sync bf16-split GEMM (4-stage pipeline) ----------------
#define GST    40960
#define NSTG   4
#define GSMEM  (2048 + NSTG*GST)

__global__ __launch_bounds__(256, 1)
void gemm_mma(const __nv_bfloat16* __restrict__ Ahi, const __nv_bfloat16* __restrict__ Alo,
              const __nv_bfloat16* __restrict__ Bhi, const __nv_bfloat16* __restrict__ Blo,
              const float* __restrict__ bias, float* __restrict__ C) {
    extern __shared__ char smem[];
    const uint32_t sb = (uint32_t)__cvta_generic_to_shared(smem);
    const int tid = threadIdx.x;
    const int lane = tid & 31, wid = tid >> 5;
    const int warpM = wid >> 2, warpN = wid & 3;
    const int row0 = blockIdx.y * 128, col0 = blockIdx.x * 128;

    float* sbias = (float*)smem;
    if (tid < 128) sbias[tid] = bias[col0 + tid];

    float acc[4][4][4];
#pragma unroll
    for (int i = 0; i < 4; i++)
#pragma unroll
        for (int j = 0; j < 4; j++)
#pragma unroll
            for (int r = 0; r < 4; r++) acc[i][j][r] = 0.f;

    const int a_row = warpM * 64 + (lane & 15);
    const int a_kb  = ((lane >> 4) * 8) * 2;
    const int b_row = warpN * 32 + (lane & 7) + ((lane >> 4) & 1) * 8;
    const int b_kb  = (((lane >> 3) & 1) * 8) * 2;

#define LOAD_CHUNK(c, s) {                                                     \
    uint32_t stb = sb + 2048 + (uint32_t)(s) * GST;                            \
    int k0 = (c) * 32;                                                         \
    _Pragma("unroll")                                                          \
    for (int j = 0; j < 8; j++) {                                              \
        int idx = tid + j * 256;                                               \
        int tile = idx >> 9, w = idx & 511;                                    \
        int r = w >> 2, cc = w & 3;                                            \
        uint32_t so = stb + (uint32_t)tile * 10240u + (uint32_t)(r * 80 + cc * 16); \
        const __nv_bfloat16* gp;                                               \
        if      (tile == 0) gp = Ahi + (size_t)(row0 + r) * DM_ + k0 + cc * 8; \
        else if (tile == 1) gp = Alo + (size_t)(row0 + r) * DM_ + k0 + cc * 8; \
        else if (tile == 2) gp = Bhi + (size_t)(col0 + r) * DM_ + k0 + cc * 8; \
        else                gp = Blo + (size_t)(col0 + r) * DM_ + k0 + cc * 8; \
        cp16s(so, gp);                                                         \
    }                                                                          \
    CP_COMMIT(); }

#define COMPUTE(s) {                                                                 \
    uint32_t stb = sb + 2048 + (uint32_t)(s) * GST;                                  \
    _Pragma("unroll")                                                                \
    for (int k16 = 0; k16 < 2; k16++) {                                             \
        uint32_t ah[4][4], al[4][4], bh[4][2], bl[4][2];                             \
        _Pragma("unroll")                                                            \
        for (int i = 0; i < 4; i++)                                                  \
            ldsm4(ah[i][0], ah[i][1], ah[i][2], ah[i][3],                            \
                  stb + (uint32_t)((a_row + i*16) * 80 + k16*32 + a_kb));            \
        _Pragma("unroll")                                                            \
        for (int n16 = 0; n16 < 2; n16++)                                            \
            ldsm4(bh[n16*2][0], bh[n16*2][1], bh[n16*2+1][0], bh[n16*2+1][1],        \
                  stb + 20480u + (uint32_t)((b_row + n16*16) * 80 + k16*32 + b_kb)); \
        _Pragma("unroll")                                                            \
        for (int i = 0; i < 4; i++)                                                  \
            _Pragma("unroll")                                                        \
            for (int j = 0; j < 4; j++) mma_bf16(acc[i][j], ah[i], bh[j]);           \
        _Pragma("unroll")                                                            \
        for (int n16 = 0; n16 < 2; n16++)                                            \
            ldsm4(bl[n16*2][0], bl[n16*2][1], bl[n16*2+1][0], bl[n16*2+1][1],        \
                  stb + 30720u + (uint32_t)((b_row + n16*16) * 80 + k16*32 + b_kb)); \
        _Pragma("unroll")                                                            \
        for (int i = 0; i < 4; i++)                                                  \
            _Pragma("unroll")                                                        \
            for (int j = 0; j < 4; j++) mma_bf16(acc[i][j], ah[i], bl[j]);           \
        _Pragma("unroll")                                                            \
        for (int i = 0; i < 4; i++)                                                  \
            ldsm4(al[i][0], al[i][1], al[i][2], al[i][3],                            \
                  stb + 10240u + (uint32_t)((a_row + i*16) * 80 + k16*32 + a_kb));   \
        _Pragma("unroll")                                                            \
        for (int i = 0; i < 4; i++)                                                  \
            _Pragma("unroll")                                                        \
            for (int j = 0; j < 4; j++) mma_bf16(acc[i][j], al[i], bh[j]);           \
    } }

    LOAD_CHUNK(0, 0);
    LOAD_CHUNK(1, 1);
    LOAD_CHUNK(2, 2);

    const int nIter = DM_ / 32;   // 16
#pragma unroll 1
    for (int c = 0; c < nIter; c++) {
        if (c < nIter - 2)      { CP_WAIT(2); }
        else if (c == nIter - 2){ CP_WAIT(1); }
        else                    { CP_WAIT(0); }
        __syncthreads();
        if (c + 3 < nIter) LOAD_CHUNK(c + 3, (c + 3) & 3);
        COMPUTE(c & 3);
    }

    __syncthreads();
#pragma unroll
    for (int i = 0; i < 4; i++) {
#pragma unroll
        for (int j = 0; j < 4; j++) {
            int colg = col0 + warpN * 32 + j * 8 + (lane & 3) * 2;
            int hh = colg >> 6, d0 = colg & 63;
            float b0v = sbias[colg - col0], b1v = sbias[colg - col0 + 1];
#pragma unroll
            for (int half = 0; half < 2; half++) {
                int m = row0 + warpM * 64 + i * 16 + (lane >> 2) + half * 8;
                int b = m >> 12, l = m & 4095;
                float2 v;
                v.x = acc[i][j][half*2 + 0] + b0v;
                v.y = acc[i][j][half*2 + 1] + b1v;
                *(float2*)(C + (((size_t)(b * H_ + hh) * L_) + l) * D_ + d0) = v;
            }
        }
    }
#undef LOAD_CHUNK
#undef COMPUTE
}

// ------- T GEMMs: split-K partials, both Tk/Tv in one launch -------
// grid (8, 8, 16): x=n-tile, y=m-tile, z: kc = z&7, which = z>>3
struct TW { const float* b[2]; };
__global__ __launch_bounds__(256)
void sgemm_T_part(const float* __restrict__ A, TW tw) {
    __shared__ float As[16][68];
    __shared__ float Bs[16][64];
    int tid = threadIdx.x, tx = tid & 15, ty = tid >> 4;
    int r0 = blockIdx.y * 64, c0 = blockIdx.x * 64;
    int kc = blockIdx.z & 7, which = blockIdx.z >> 3;
    const float* Bm = tw.b[which];
    float acc[4][4];
#pragma unroll
    for (int i = 0; i < 4; i++)
#pragma unroll
        for (int j = 0; j < 4; j++) acc[i][j] = 0.f;

    for (int kt = kc * 64; kt < kc * 64 + 64; kt += 16) {
        int m = tid >> 2, k4 = tid & 3;
        float4 av = *(const float4*)(A + (size_t)(r0 + m) * DM_ + kt + k4 * 4);
        As[k4*4+0][m] = av.x; As[k4*4+1][m] = av.y;
        As[k4*4+2][m] = av.z; As[k4*4+3][m] = av.w;
        int kk = tid >> 4, n4 = tid & 15;
        *(float4*)&Bs[kk][n4 * 4] = *(const float4*)(Bm + (size_t)(kt + kk) * DM_ + c0 + n4 * 4);
        __syncthreads();
#pragma unroll
        for (int k = 0; k < 16; k++) {
            float a[4], b[4];
            *(float4*)a = *(const float4*)&As[k][ty * 4];
            *(float4*)b = *(const float4*)&Bs[k][tx * 4];
#pragma unroll
            for (int i = 0; i < 4; i++)
#pragma unroll
                for (int j = 0; j < 4; j++) acc[i][j] += a[i] * b[j];
        }
        __syncthreads();
    }
    float* dst = g_Tp + ((size_t)blockIdx.z * DM_ + r0 + ty * 4) * DM_ + c0 + tx * 4;
#pragma unroll
    for (int i = 0; i < 4; i++)
        *(float4*)(dst + (size_t)i * DM_) = make_float4(acc[i][0], acc[i][1], acc[i][2], acc[i][3]);
}

__global__ __launch_bounds__(256)
void t_combine_kernel() {
    int i = blockIdx.x * 256 + threadIdx.x;     // over 2*DM_*DM_/4 float4
    int which = i >= (DM_ * DM_ / 4) ? 1 : 0;
    int j = i - which * (DM_ * DM_ / 4);
    float4 s = make_float4(0.f, 0.f, 0.f, 0.f);
#pragma unroll
    for (int p = 0; p < 8; p++) {
        float4 v = ((const float4*)g_Tp)[(size_t)(which * 8 + p) * (DM_ * DM_ / 4) + j];
        s.x += v.x; s.y += v.y; s.z += v.z; s.w += v.w;
    }
    ((float4*)g_Tkv)[i] = s;
}

// ---------------- M[bh][l] = max_s(q·k_s) - sum_s(q·k_s)/L ----------------
__global__ __launch_bounds__(256)
void sample_m_kernel(const int* __restrict__ idx) {
    int gw = (blockIdx.x * blockDim.x + threadIdx.x) >> 5;
    int lane = threadIdx.x & 31;
    if (gw >= BH_ * L_) return;
    int bh = gw >> 12, l = gw & 4095;
    const float4* qrow = (const float4*)(g_Q + ((size_t)bh * L_ + l) * D_);
    float val = 0.f;
    bool active = lane < NS_;
    if (active) {
        int kk = idx[l * NS_ + lane];
        const float4* krow = (const float4*)(g_K + ((size_t)bh * L_ + kk) * D_);
        float s = 0.f;
#pragma unroll
        for (int d4 = 0; d4 < 16; d4++) {
            float4 q = qrow[d4], k = krow[d4];
            s += q.x*k.x + q.y*k.y + q.z*k.z + q.w*k.w;
        }
        val = s;
    }
    float mx = active ? val : -__int_as_float(0x7f800000);
    float sm = active ? val : 0.f;
#pragma unroll
    for (int off = 16; off > 0; off >>= 1) {
        mx = fmaxf(mx, __shfl_down_sync(0xffffffffu, mx, off));
        sm += __shfl_down_sync(0xffffffffu, sm, off);
    }
    if (lane == 0) g_M[gw] = mx - sm * (1.f / (float)L_);
}

// ---------------- top-27 via packed-key shfl reduce ----------------
__device__ __forceinline__ unsigned ordf(float v) {
    unsigned u = __float_as_uint(v);
    return (u & 0x80000000u) ? ~u : (u | 0x80000000u);
}

__global__ __launch_bounds__(256)
void topk_kernel() {
    int bh = blockIdx.x, t = threadIdx.x;
    int lane = t & 31, wid = t >> 5;
    __shared__ float sm[L_];
    __shared__ unsigned long long wred[8];
    for (int i = t; i < L_; i += 256) sm[i] = g_M[(size_t)bh * L_ + i];
    __syncthreads();
    for (int it = 0; it < NS_; it++) {
        unsigned long long best = 0ull;
#pragma unroll
        for (int jj = 0; jj < L_ / 256; jj++) {
            int i = t + jj * 256;
            unsigned long long key = ((unsigned long long)ordf(sm[i]) << 32)
                                   | (unsigned)(L_ - 1 - i);
            if (key > best) best = key;
        }
#pragma unroll
        for (int off = 16; off > 0; off >>= 1) {
            unsigned long long o = __shfl_down_sync(0xffffffffu, best, off);
            if (o > best) best = o;
        }
        if (lane == 0) wred[wid] = best;
        __syncthreads();
        if (t == 0) {
            unsigned long long b2 = wred[0];
#pragma unroll
            for (int w = 1; w < 8; w++) if (wred[w] > b2) b2 = wred[w];
            int idx = L_ - 1 - (int)(b2 & 0xFFFFFFFFull);
            g_topidx[bh * NS_ + it] = idx;
            sm[idx] = -__int_as_float(0x7f800000);
        }
        __syncthreads();
    }
}

// ---------------- meanV: two-stage deterministic reduce ----------------
__global__ __launch_bounds__(256)
void meanv1_kernel() {
    int bh = blockIdx.x, c = blockIdx.y, t = threadIdx.x;
    int d = t & 63, r = t >> 6;
    float s = 0.f;
    int base = c * 256;
    for (int l = base + r; l < base + 256; l += 4)
        s += g_V[((size_t)bh * L_ + l) * D_ + d];
    __shared__ float red[256];
    red[t] = s; __syncthreads();
    if (t < 64)
        g_vpart[(bh * 16 + c) * D_ + d] = red[d] + red[64+d] + red[128+d] + red[192+d];
}

__global__ __launch_bounds__(64)
void meanv2_kernel() {
    int bh = blockIdx.x, d = threadIdx.x;
    float s = 0.f;
#pragma unroll
    for (int c = 0; c < 16; c++) s += g_vpart[(bh * 16 + c) * D_ + d];
    g_meanV[bh * D_ + d] = s * (1.f / (float)L_);
}

// ---------------- scores S[bh][u][k] = 0.125 * Q[top_u]·K[k] ----------------
__global__ __launch_bounds__(128)
void scores_kernel() {
    int bh = blockIdx.x, kt = blockIdx.y, t = threadIdx.x;
    __shared__ float Qs[NS_][64];
    __shared__ float KsT[64][129];
    for (int f = t; f < NS_ * 16; f += 128) {
        int u = f >> 4, d4 = f & 15;
        int l = g_topidx[bh * NS_ + u];
        *(float4*)&Qs[u][d4 * 4] = *(const float4*)(g_Q + ((size_t)bh * L_ + l) * D_ + d4 * 4);
    }
    for (int f = t; f < 128 * 16; f += 128) {
        int kk = f >> 4, d4 = f & 15;
        float4 v = *(const float4*)(g_K + ((size_t)bh * L_ + kt * 128 + kk) * D_ + d4 * 4);
        KsT[d4*4+0][kk] = v.x; KsT[d4*4+1][kk] = v.y;
        KsT[d4*4+2][kk] = v.z; KsT[d4*4+3][kk] = v.w;
    }
    __syncthreads();
    float acc[NS_];
#pragma unroll
    for (int u = 0; u < NS_; u++) acc[u] = 0.f;
    int kk = t;
#pragma unroll
    for (int d0 = 0; d0 < 64; d0 += 4) {
        float k0 = KsT[d0][kk], k1 = KsT[d0+1][kk], k2 = KsT[d0+2][kk], k3 = KsT[d0+3][kk];
#pragma unroll
        for (int u = 0; u < NS_; u++) {
            float4 q = *(const float4*)&Qs[u][d0];
            acc[u] += q.x*k0 + q.y*k1 + q.z*k2 + q.w*k3;
        }
    }
#pragma unroll
    for (int u = 0; u < NS_; u++)
        g_S[((size_t)bh * NS_ + u) * L_ + kt * 128 + kk] = acc[u] * 0.125f;
}

// ---------------- softmax over each S row (in place) ----------------
__global__ __launch_bounds__(256)
void softmax_kernel() {
    int row = blockIdx.x, t = threadIdx.x;
    float* p = g_S + (size_t)row * L_;
    __shared__ float sm[L_];
    __shared__ float red[256];
    float mx = -__int_as_float(0x7f800000);
    for (int i = t; i < L_; i += 256) { float v = p[i]; sm[i] = v; mx = fmaxf(mx, v); }
    red[t] = mx; __syncthreads();
    for (int s = 128; s > 0; s >>= 1) { if (t < s) red[t] = fmaxf(red[t], red[t+s]); __syncthreads(); }
    float m = red[0];
    __syncthreads();
    float ss = 0.f;
    for (int i = t; i < L_; i += 256) { float e = expf(sm[i] - m); sm[i] = e; ss += e; }
    red[t] = ss; __syncthreads();
    for (int s = 128; s > 0; s >>= 1) { if (t < s) red[t] += red[t+s]; __syncthreads(); }
    float inv = 1.f / red[0];
    for (int i = t; i < L_; i += 256) p[i] = sm[i] * inv;
}

// ---------------- out_top[bh][u][d] += P[u][k] * V[k][d] (split-k) ---------
__global__ __launch_bounds__(256)
void pv_kernel() {
    int bh = blockIdx.x, kc = blockIdx.y, t = threadIdx.x;
    int d = t & 63, ug = t >> 6;
    float acc[7];
#pragma unroll
    for (int j = 0; j < 7; j++) acc[j] = 0.f;
    int k0 = kc * 512;
    for (int k = k0; k < k0 + 512; k += 4) {
        float v0 = g_V[((size_t)bh * L_ + k + 0) * D_ + d];
        float v1 = g_V[((size_t)bh * L_ + k + 1) * D_ + d];
        float v2 = g_V[((size_t)bh * L_ + k + 2) * D_ + d];
        float v3 = g_V[((size_t)bh * L_ + k + 3) * D_ + d];
#pragma unroll
        for (int j = 0; j < 7; j++) {
            int u = ug + j * 4;
            if (u < NS_) {
                float4 pv = *(const float4*)(g_S + ((size_t)bh * NS_ + u) * L_ + k);
                acc[j] += pv.x*v0 + pv.y*v1 + pv.z*v2 + pv.w*v3;
            }
        }
    }
#pragma unroll
    for (int j = 0; j < 7; j++) {
        int u = ug + j * 4;
        if (u < NS_) atomicAdd(&g_outtop[(bh * NS_ + u) * D_ + d], acc[j]);
    }
}

// ---------------- generic GEMV: partials then combine ----------------
__global__ __launch_bounds__(512)
void base1g_kernel(const float* __restrict__ invec, const float* __restrict__ w) {
    int b = blockIdx.x, kc = blockIdx.y, n = threadIdx.x;
    __shared__ float mc[64];
    if (n < 64) mc[n] = invec[b * DM_ + kc * 64 + n];
    __syncthreads();
    float s = 0.f;
#pragma unroll 8
    for (int k = 0; k < 64; k++) s += mc[k] * w[(size_t)(kc * 64 + k) * DM_ + n];
    g_basep[(b * 8 + kc) * DM_ + n] = s;
}

__global__ __launch_bounds__(512)
void base2g_kernel(const float* __restrict__ bias, float* __restrict__ outv) {
    int b = blockIdx.x, n = threadIdx.x;
    float s = bias[n];
#pragma unroll
    for (int p = 0; p < 8; p++) s += g_basep[(b * 8 + p) * DM_ + n];
    outv[b * DM_ + n] = s;
}

// K and V base GEMVs in one launch: z selects weight / output slot
struct KV2 { const float* w[2]; const float* bias[2]; };
__global__ __launch_bounds__(512)
void basekv1_kernel(const float* __restrict__ invec, KV2 kv) {
    int b = blockIdx.x, kc = blockIdx.y, z = blockIdx.z, n = threadIdx.x;
    __shared__ float mc[64];
    if (n < 64) mc[n] = invec[b * DM_ + kc * 64 + n];
    __syncthreads();
    const float* w = kv.w[z];
    float s = 0.f;
#pragma unroll 8
    for (int k = 0; k < 64; k++) s += mc[k] * w[(size_t)(kc * 64 + k) * DM_ + n];
    g_basep2[((z * B_ + b) * 8 + kc) * DM_ + n] = s;
}

__global__ __launch_bounds__(512)
void basekv2_kernel(KV2 kv) {
    int b = blockIdx.x, z = blockIdx.y, n = threadIdx.x;
    float s = kv.bias[z][n];
#pragma unroll
    for (int p = 0; p < 8; p++) s += g_basep2[((z * B_ + b) * 8 + p) * DM_ + n];
    g_basekv[(z * B_ + b) * DM_ + n] = s;
}

// ---------------- fill K and V with broadcast base rows (one launch) -------
__global__ __launch_bounds__(256)
void fill_bcast2_kernel(float* __restrict__ dstK, float* __restrict__ dstV) {
    int i4 = blockIdx.x * 256 + threadIdx.x;   // over BH_*L_*16 float4
    int z = blockIdx.y;
    int d4 = i4 & 15;
    int h = (i4 >> 16) & 7;
    int b = i4 >> 19;
    float* dst = z ? dstV : dstK;
    ((float4*)dst)[i4] = ((const float4*)g_basekv)[(z * B_ + b) * 128 + h * 16 + d4];
}

// ---------------- K/V corrections (one launch, y selects K or V) ----------
__global__ __launch_bounds__(128)
void corr_kv2_kernel(float* __restrict__ dstK, float* __restrict__ dstV) {
    int blk = blockIdx.x, z = blockIdx.y;
    int bh0 = blk / NS_, u = blk % NS_;
    int b = bh0 >> 3, h0 = bh0 & 7;
    int t = threadIdx.x;
    __shared__ float qv[64];
    if (t < 64) qv[t] = g_outtop[(bh0 * NS_ + u) * 64 + t] - g_meanV[bh0 * 64 + t];
    __syncthreads();
    const float* T = g_Tkv + (size_t)z * DM_ * DM_;
    float* dst = z ? dstV : dstK;
    int l = g_topidx[bh0 * NS_ + u];
    float a0 = 0.f, a1 = 0.f, a2 = 0.f, a3 = 0.f;
#pragma unroll 8
    for (int k = 0; k < 64; k++) {
        float q = qv[k];
        float4 w = *(const float4*)(T + (size_t)(h0 * 64 + k) * DM_ + t * 4);
        a0 += q * w.x; a1 += q * w.y; a2 += q * w.z; a3 += q * w.w;
    }
    int n0 = t * 4;
    int h = n0 >> 6, d = n0 & 63;
    float* d_ = dst + (((size_t)(b * H_ + h) * L_) + l) * D_ + d;
    atomicAdd(d_ + 0, a0); atomicAdd(d_ + 1, a1);
    atomicAdd(d_ + 2, a2); atomicAdd(d_ + 3, a3);
}

// ---------------- output broadcasts ----------------
__global__ __launch_bounds__(256)
void bcast_out_kernel(const float* __restrict__ xs, float* __restrict__ out,
                      const float* __restrict__ basev, int row_off) {
    int i4 = blockIdx.x * 256 + threadIdx.x;   // over B_*L_*128
    int n4 = i4 & 127;
    int l = (i4 >> 7) & 4095;
    int b = i4 / (L_ * 128);
    size_t oi = ((size_t)(b * 8192 + row_off + l)) * 128 + n4;
    float4 a = ((const float4*)xs)[oi];
    float4 s = ((const float4*)basev)[b * 128 + n4];
    a.x += s.x; a.y += s.y; a.z += s.z; a.w += s.w;
    ((float4*)out)[oi] = a;
}

__global__ __launch_bounds__(128)
void corr_kernel(const float* __restrict__ wo, float* __restrict__ dst, int row_off) {
    int blk = blockIdx.x;
    int bh = blk / NS_, u = blk % NS_;
    int b = bh >> 3, h = bh & 7;
    int t = threadIdx.x;
    __shared__ float qv[64];
    if (t < 64) qv[t] = g_outtop[(bh * NS_ + u) * 64 + t] - g_meanV[bh * 64 + t];
    __syncthreads();
    int l = g_topidx[bh * NS_ + u];
    float a0 = 0.f, a1 = 0.f, a2 = 0.f, a3 = 0.f;
#pragma unroll 8
    for (int k = 0; k < 64; k++) {
        float q = qv[k];
        float4 w = *(const float4*)(wo + (size_t)(h * 64 + k) * DM_ + t * 4);
        a0 += q * w.x; a1 += q * w.y; a2 += q * w.z; a3 += q * w.w;
    }
    float* d = dst + ((size_t)(b * 8192 + row_off + l)) * DM_ + t * 4;
    atomicAdd(d + 0, a0); atomicAdd(d + 1, a1);
    atomicAdd(d + 2, a2); atomicAdd(d + 3, a3);
}

// ---------------- host orchestration ----------------
extern "C" void kernel_launch(void* const* d_in, const int* in_sizes, int n_in,
                              void* d_out, int out_size) {
    const float* xs  = (const float*)d_in[0];
    const float* xd  = (const float*)d_in[1];
    const float* xp  = (const float*)d_in[2];
    const float* w0q = (const float*)d_in[3];
    const float* w0k = (const float*)d_in[4];
    const float* w0v = (const float*)d_in[5];
    const float* w0o = (const float*)d_in[6];
    const float* b0q = (const float*)d_in[7];
    const float* b0k = (const float*)d_in[8];
    const float* b0v = (const float*)d_in[9];
    const float* b0o = (const float*)d_in[10];
    const float* w1q = (const float*)d_in[11];
    const float* w1k = (const float*)d_in[12];
    const float* w1v = (const float*)d_in[13];
    const float* w1o = (const float*)d_in[14];
    const float* b1q = (const float*)d_in[15];
    const float* b1k = (const float*)d_in[16];
    const float* b1v = (const float*)d_in[17];
    const float* b1o = (const float*)d_in[18];
    float* out = (float*)d_out;

    float *pQ, *pK, *pV, *pouttop, *pmv, *pb0, *pb1;
    int *pidxA, *pidxB;
    __nv_bfloat16 *pAxdH, *pAxdL, *pAxpH, *pAxpL, *pWtH, *pWtL;
    cudaGetSymbolAddress((void**)&pQ, g_Q);
    cudaGetSymbolAddress((void**)&pK, g_K);
    cudaGetSymbolAddress((void**)&pV, g_V);
    cudaGetSymbolAddress((void**)&pouttop, g_outtop);
    cudaGetSymbolAddress((void**)&pmv, g_meanV);
    cudaGetSymbolAddress((void**)&pb0, g_base0);
    cudaGetSymbolAddress((void**)&pb1, g_base1);
    cudaGetSymbolAddress((void**)&pidxA, g_idxA);
    cudaGetSymbolAddress((void**)&pidxB, g_idxB);
    cudaGetSymbolAddress((void**)&pAxdH, g_Axd_hi);
    cudaGetSymbolAddress((void**)&pAxdL, g_Axd_lo);
    cudaGetSymbolAddress((void**)&pAxpH, g_Axp_hi);
    cudaGetSymbolAddress((void**)&pAxpL, g_Axp_lo);
    cudaGetSymbolAddress((void**)&pWtH, g_Wt_hi);
    cudaGetSymbolAddress((void**)&pWtL, g_Wt_lo);

    cudaFuncSetAttribute(gemm_mma, cudaFuncAttributeMaxDynamicSharedMemorySize, GSMEM);

    unsigned a42, b42, a43, b43;
    tf2x32(0u, 42u, 0u, 1u, &a42, &b42);
    tf2x32(0u, 43u, 0u, 1u, &a43, &b43);
    idx_kernel<<<(L_ * NS_ + 255) / 256, 256>>>(a42, b42, pidxA);
    idx_kernel<<<(L_ * NS_ + 255) / 256, 256>>>(a43, b43, pidxB);

    // 4 dense-GEMM weights: w0q, w0k, w0v, w1q
    W4 ws;
    ws.w[0] = w0q; ws.w[1] = w0k; ws.w[2] = w0v; ws.w[3] = w1q;
    wt_cvt_all_kernel<<<dim3(16, 16, 4), dim3(32, 32)>>>(ws, pWtH, pWtL);

    // T = Wo0 @ W1{k,v}: split-K partials + combine (both matrices, one launch)
    TW tw; tw.b[0] = w1k; tw.b[1] = w1v;
    sgemm_T_part<<<dim3(8, 8, 16), 256>>>(w0o, tw);
    t_combine_kernel<<<(2 * DM_ * DM_ / 4) / 256, 256>>>();

    // split xd and xp in one launch
    const int N4 = BL_ * DM_ / 4;
    {
        Cvt2 c;
        c.src[0] = (const float4*)xd; c.src[1] = (const float4*)xp;
        c.hi[0] = (__nv_bfloat162*)pAxdH; c.hi[1] = (__nv_bfloat162*)pAxpH;
        c.lo[0] = (__nv_bfloat162*)pAxdL; c.lo[1] = (__nv_bfloat162*)pAxpL;
        cvt_pair2_kernel<<<dim3((N4 + 255) / 256, 2), 256>>>(c, N4);
    }

    dim3 ggrid(DM_ / 128, BL_ / 128);   // (4, 128)

    // ---- layer 0: xp2 = attn(xp; xd, xd) ----
    gemm_mma<<<ggrid, 256, GSMEM>>>(pAxpH, pAxpL, pWtH + 0*(size_t)DM_*DM_, pWtL + 0*(size_t)DM_*DM_, b0q, pQ);
    gemm_mma<<<ggrid, 256, GSMEM>>>(pAxdH, pAxdL, pWtH + 1*(size_t)DM_*DM_, pWtL + 1*(size_t)DM_*DM_, b0k, pK);
    gemm_mma<<<ggrid, 256, GSMEM>>>(pAxdH, pAxdL, pWtH + 2*(size_t)DM_*DM_, pWtL + 2*(size_t)DM_*DM_, b0v, pV);
    sample_m_kernel<<<(BH_ * L_) / 8, 256>>>(pidxA);
    topk_kernel<<<BH_, 256>>>();
    meanv1_kernel<<<dim3(BH_, 16), 256>>>();
    meanv2_kernel<<<BH_, 64>>>();
    cudaMemsetAsync(pouttop, 0, (size_t)BH_ * NS_ * D_ * sizeof(float));
    scores_kernel<<<dim3(BH_, L_ / 128), 128>>>();
    softmax_kernel<<<BH_ * NS_, 256>>>();
    pv_kernel<<<dim3(BH_, 8), 256>>>();

    // base0 = meanctx0 @ Wo0 + bo0
    base1g_kernel<<<dim3(B_, 8), 512>>>(pmv, w0o);
    base2g_kernel<<<B_, 512>>>(b0o, pb0);

    // output upper half (xp2): xs + base0 + layer-0 corrections
    bcast_out_kernel<<<(B_ * L_ * 128) / 256, 256>>>(xs, out, pb0, 4096);
    corr_kernel<<<BH_ * NS_, 128>>>(w0o, out, 4096);

    // ---- build K1, V1 without dense GEMMs ----
    {
        KV2 kv;
        kv.w[0] = w1k; kv.w[1] = w1v;
        kv.bias[0] = b1k; kv.bias[1] = b1v;
        basekv1_kernel<<<dim3(B_, 8, 2), 512>>>(pb0, kv);
        basekv2_kernel<<<dim3(B_, 2), 512>>>(kv);
    }
    fill_bcast2_kernel<<<dim3((BH_ * L_ * 16) / 256, 2), 256>>>(pK, pV);
    corr_kv2_kernel<<<dim3(BH_ * NS_, 2), 128>>>(pK, pV);

    // layer-1 Q (dense GEMM from xd)
    gemm_mma<<<ggrid, 256, GSMEM>>>(pAxdH, pAxdL, pWtH + 3*(size_t)DM_*DM_, pWtL + 3*(size_t)DM_*DM_, b1q, pQ);

    // ---- layer 1 attention ----
    sample_m_kernel<<<(BH_ * L_) / 8, 256>>>(pidxB);
    topk_kernel<<<BH_, 256>>>();
    meanv1_kernel<<<dim3(BH_, 16), 256>>>();
    meanv2_kernel<<<BH_, 64>>>();
    cudaMemsetAsync(pouttop, 0, (size_t)BH_ * NS_ * D_ * sizeof(float));
    scores_kernel<<<dim3(BH_, L_ / 128), 128>>>();
    softmax_kernel<<<BH_ * NS_, 256>>>();
    pv_kernel<<<dim3(BH_, 8), 256>>>();

    // base1 = meanctx1 @ W1o + b1o; output lower half (xd2)
    base1g_kernel<<<dim3(B_, 8), 512>>>(pmv, w1o);
    base2g_kernel<<<B_, 512>>>(b1o, pb1);
    bcast_out_kernel<<<(B_ * L_ * 128) / 256, 256>>>(xs, out, pb1, 0);
    corr_kernel<<<BH_ * NS_, 128>>>(w1o, out, 0);
}

// round 8
// speedup vs baseline: 2.2171x; 1.0614x over previous
#include <cuda_runtime.h>
#include <cuda_bf16.h>
#include <math.h>
#include <stdint.h>

#define B_   4
#define H_   8
#define L_   4096
#define D_   64
#define DM_  512
#define NS_  27
#define BH_  (B_*H_)
#define BL_  (B_*L_)
#define NCH  8
#define CH   (L_/NCH)   // 512

// ---------------- scratch (device globals; no runtime alloc) ----------------
__device__ float g_Q[BH_*L_*D_];
__device__ float g_K[BH_*L_*D_];
__device__ float g_V[BH_*L_*D_];
__device__ float g_M[BH_*L_];
__device__ float g_outtop[BH_*NS_*D_];
__device__ float g_meanV[BH_*D_];
__device__ float g_vpart[BH_*16*D_];
__device__ float g_attM[BH_*NCH*NS_];
__device__ float g_attS[BH_*NCH*NS_];
__device__ float g_attO[BH_*NCH*NS_*D_];
__device__ float g_base0[B_*DM_];
__device__ float g_base1[B_*DM_];
__device__ float g_basekv[2*B_*DM_];
__device__ float g_basep[B_*8*DM_];
__device__ float g_basep2[2*B_*8*DM_];
__device__ float g_Tkv[2*DM_*DM_];
__device__ float g_Tp[32*DM_*DM_];            // split-K partials (2 mats x 16 slices)
__device__ int   g_idxA[L_*NS_];
__device__ int   g_idxB[L_*NS_];
__device__ int   g_topidx[BH_*NS_];

// bf16-split operand buffers
__device__ __nv_bfloat16 g_Axd_hi[(size_t)BL_*DM_];
__device__ __nv_bfloat16 g_Axd_lo[(size_t)BL_*DM_];
__device__ __nv_bfloat16 g_Axp_hi[(size_t)BL_*DM_];
__device__ __nv_bfloat16 g_Axp_lo[(size_t)BL_*DM_];
__device__ __nv_bfloat16 g_Wt_hi[4*DM_*DM_];   // w0q, w0k, w0v, w1q
__device__ __nv_bfloat16 g_Wt_lo[4*DM_*DM_];

// ---------------- Threefry-2x32 (JAX-exact) ----------------
__host__ __device__ inline void tf2x32(unsigned k0, unsigned k1,
                                       unsigned x0, unsigned x1,
                                       unsigned* o0, unsigned* o1) {
    unsigned ks0 = k0, ks1 = k1, ks2 = 0x1BD11BDAu ^ k0 ^ k1;
    x0 += ks0; x1 += ks1;
#define TF_RND(r) { x0 += x1; x1 = (x1 << (r)) | (x1 >> (32 - (r))); x1 ^= x0; }
    TF_RND(13) TF_RND(15) TF_RND(26) TF_RND(6)   x0 += ks1; x1 += ks2 + 1u;
    TF_RND(17) TF_RND(29) TF_RND(16) TF_RND(24)  x0 += ks2; x1 += ks0 + 2u;
    TF_RND(13) TF_RND(15) TF_RND(26) TF_RND(6)   x0 += ks0; x1 += ks1 + 3u;
    TF_RND(17) TF_RND(29) TF_RND(16) TF_RND(24)  x0 += ks1; x1 += ks2 + 4u;
    TF_RND(13) TF_RND(15) TF_RND(26) TF_RND(6)   x0 += ks2; x1 += ks0 + 5u;
#undef TF_RND
    *o0 = x0; *o1 = x1;
}

struct IdxKeys { unsigned k0[2], k1[2]; int* out[2]; };
__global__ void idx2_kernel(IdxKeys ik) {
    int i = blockIdx.x * blockDim.x + threadIdx.x;
    if (i >= L_*NS_) return;
    int z = blockIdx.y;
    unsigned o0, o1;
    tf2x32(ik.k0[z], ik.k1[z], 0u, (unsigned)i, &o0, &o1);
    ik.out[z][i] = (int)((o0 ^ o1) & 4095u);
}

// ---------------- bf16-split conversion (both inputs in one launch) --------
struct Cvt2 { const float4* src[2]; __nv_bfloat162* hi[2]; __nv_bfloat162* lo[2]; };
__global__ __launch_bounds__(256)
void cvt_pair2_kernel(Cvt2 c, int n4) {
    int i = blockIdx.x * 256 + threadIdx.x;
    if (i >= n4) return;
    int z = blockIdx.y;
    float4 v = c.src[z][i];
    __nv_bfloat16 h0 = __float2bfloat16(v.x), h1 = __float2bfloat16(v.y);
    __nv_bfloat16 h2 = __float2bfloat16(v.z), h3 = __float2bfloat16(v.w);
    __nv_bfloat16 l0 = __float2bfloat16(v.x - __bfloat162float(h0));
    __nv_bfloat16 l1 = __float2bfloat16(v.y - __bfloat162float(h1));
    __nv_bfloat16 l2 = __float2bfloat16(v.z - __bfloat162float(h2));
    __nv_bfloat16 l3 = __float2bfloat16(v.w - __bfloat162float(h3));
    c.hi[z][i*2]   = __nv_bfloat162(h0, h1);
    c.hi[z][i*2+1] = __nv_bfloat162(h2, h3);
    c.lo[z][i*2]   = __nv_bfloat162(l0, l1);
    c.lo[z][i*2+1] = __nv_bfloat162(l2, l3);
}

struct W4 { const float* w[4]; };
__global__ __launch_bounds__(1024)
void wt_cvt_all_kernel(W4 ws, __nv_bfloat16* __restrict__ hi, __nv_bfloat16* __restrict__ lo) {
    __shared__ float t[32][33];
    int tx = threadIdx.x, ty = threadIdx.y;
    int n0 = blockIdx.x * 32, k0 = blockIdx.y * 32;
    int z = blockIdx.z;
    const float* W = ws.w[z];
    size_t off = (size_t)z * DM_ * DM_;
    t[ty][tx] = W[(size_t)(k0 + ty) * DM_ + n0 + tx];
    __syncthreads();
    float v = t[tx][ty];
    int n = n0 + ty, k = k0 + tx;
    __nv_bfloat16 h = __float2bfloat16(v);
    hi[off + (size_t)n * DM_ + k] = h;
    lo[off + (size_t)n * DM_ + k] = __float2bfloat16(v - __bfloat162float(h));
}

// ---------------- PTX helpers ----------------
__device__ __forceinline__ void cp16s(uint32_t saddr, const void* g) {
    asm volatile("cp.async.cg.shared.global [%0], [%1], 16;\n" :: "r"(saddr), "l"(g));
}
#define CP_COMMIT() asm volatile("cp.async.commit_group;\n" ::: "memory")
#define CP_WAIT(n)  asm volatile("cp.async.wait_group %0;\n" :: "n"(n) : "memory")

__device__ __forceinline__ void ldsm4(uint32_t& r0, uint32_t& r1, uint32_t& r2, uint32_t& r3,
                                      uint32_t saddr) {
    asm volatile("ldmatrix.sync.aligned.m8n8.x4.shared.b16 {%0,%1,%2,%3}, [%4];"
                 : "=r"(r0), "=r"(r1), "=r"(r2), "=r"(r3) : "r"(saddr));
}

__device__ __forceinline__ void mma_bf16(float* c, const uint32_t* a, const uint32_t* b) {
    asm volatile("mma.sync.aligned.m16n8k16.row.col.f32.bf16.bf16.f32 "
                 "{%0,%1,%2,%3}, {%4,%5,%6,%7}, {%8,%9}, {%0,%1,%2,%3};"
                 : "+f"(c[0]), "+f"(c[1]), "+f"(c[2]), "+f"(c[3])
                 : "r"(a[0]), "r"(a[1]), "r"(a[2]), "r"(a[3]), "r"(b[0]), "r"(b[1]));
}

// ---------------- mma.sync bf16-split GEMM (4-stage pipeline) ----------------
#define GST    40960
#define NSTG   4
#define GSMEM  (2048 + NSTG*GST)

__global__ __launch_bounds__(256, 1)
void gemm_mma(const __nv_bfloat16* __restrict__ Ahi, const __nv_bfloat16* __restrict__ Alo,
              const __nv_bfloat16* __restrict__ Bhi, const __nv_bfloat16* __restrict__ Blo,
              const float* __restrict__ bias, float* __restrict__ C) {
    extern __shared__ char smem[];
    const uint32_t sb = (uint32_t)__cvta_generic_to_shared(smem);
    const int tid = threadIdx.x;
    const int lane = tid & 31, wid = tid >> 5;
    const int warpM = wid >> 2, warpN = wid & 3;
    const int row0 = blockIdx.y * 128, col0 = blockIdx.x * 128;

    float* sbias = (float*)smem;
    if (tid < 128) sbias[tid] = bias[col0 + tid];

    float acc[4][4][4];
#pragma unroll
    for (int i = 0; i < 4; i++)
#pragma unroll
        for (int j = 0; j < 4; j++)
#pragma unroll
            for (int r = 0; r < 4; r++) acc[i][j][r] = 0.f;

    const int a_row = warpM * 64 + (lane & 15);
    const int a_kb  = ((lane >> 4) * 8) * 2;
    const int b_row = warpN * 32 + (lane & 7) + ((lane >> 4) & 1) * 8;
    const int b_kb  = (((lane >> 3) & 1) * 8) * 2;

#define LOAD_CHUNK(c, s) {                                                     \
    uint32_t stb = sb + 2048 + (uint32_t)(s) * GST;                            \
    int k0 = (c) * 32;                                                         \
    _Pragma("unroll")                                                          \
    for (int j = 0; j < 8; j++) {                                              \
        int idx = tid + j * 256;                                               \
        int tile = idx >> 9, w = idx & 511;                                    \
        int r = w >> 2, cc = w & 3;                                            \
        uint32_t so = stb + (uint32_t)tile * 10240u + (uint32_t)(r * 80 + cc * 16); \
        const __nv_bfloat16* gp;                                               \
        if      (tile == 0) gp = Ahi + (size_t)(row0 + r) * DM_ + k0 + cc * 8; \
        else if (tile == 1) gp = Alo + (size_t)(row0 + r) * DM_ + k0 + cc * 8; \
        else if (tile == 2) gp = Bhi + (size_t)(col0 + r) * DM_ + k0 + cc * 8; \
        else                gp = Blo + (size_t)(col0 + r) * DM_ + k0 + cc * 8; \
        cp16s(so, gp);                                                         \
    }                                                                          \
    CP_COMMIT(); }

#define COMPUTE(s) {                                                                 \
    uint32_t stb = sb + 2048 + (uint32_t)(s) * GST;                                  \
    _Pragma("unroll")                                                                \
    for (int k16 = 0; k16 < 2; k16++) {                                             \
        uint32_t ah[4][4], al[4][4], bh[4][2], bl[4][2];                             \
        _Pragma("unroll")                                                            \
        for (int i = 0; i < 4; i++)                                                  \
            ldsm4(ah[i][0], ah[i][1], ah[i][2], ah[i][3],                            \
                  stb + (uint32_t)((a_row + i*16) * 80 + k16*32 + a_kb));            \
        _Pragma("unroll")                                                            \
        for (int n16 = 0; n16 < 2; n16++)                                            \
            ldsm4(bh[n16*2][0], bh[n16*2][1], bh[n16*2+1][0], bh[n16*2+1][1],        \
                  stb + 20480u + (uint32_t)((b_row + n16*16) * 80 + k16*32 + b_kb)); \
        _Pragma("unroll")                                                            \
        for (int i = 0; i < 4; i++)                                                  \
            _Pragma("unroll")                                                        \
            for (int j = 0; j < 4; j++) mma_bf16(acc[i][j], ah[i], bh[j]);           \
        _Pragma("unroll")                                                            \
        for (int n16 = 0; n16 < 2; n16++)                                            \
            ldsm4(bl[n16*2][0], bl[n16*2][1], bl[n16*2+1][0], bl[n16*2+1][1],        \
                  stb + 30720u + (uint32_t)((b_row + n16*16) * 80 + k16*32 + b_kb)); \
        _Pragma("unroll")                                                            \
        for (int i = 0; i < 4; i++)                                                  \
            _Pragma("unroll")                                                        \
            for (int j = 0; j < 4; j++) mma_bf16(acc[i][j], ah[i], bl[j]);           \
        _Pragma("unroll")                                                            \
        for (int i = 0; i < 4; i++)                                                  \
            ldsm4(al[i][0], al[i][1], al[i][2], al[i][3],                            \
                  stb + 10240u + (uint32_t)((a_row + i*16) * 80 + k16*32 + a_kb));   \
        _Pragma("unroll")                                                            \
        for (int i = 0; i < 4; i++)                                                  \
            _Pragma("unroll")                                                        \
            for (int j = 0; j < 4; j++) mma_bf16(acc[i][j], al[i], bh[j]);           \
    } }

    LOAD_CHUNK(0, 0);
    LOAD_CHUNK(1, 1);
    LOAD_CHUNK(2, 2);

    const int nIter = DM_ / 32;   // 16
#pragma unroll 1
    for (int c = 0; c < nIter; c++) {
        if (c < nIter - 2)      { CP_WAIT(2); }
        else if (c == nIter - 2){ CP_WAIT(1); }
        else                    { CP_WAIT(0); }
        __syncthreads();
        if (c + 3 < nIter) LOAD_CHUNK(c + 3, (c + 3) & 3);
        COMPUTE(c & 3);
    }

    __syncthreads();
#pragma unroll
    for (int i = 0; i < 4; i++) {
#pragma unroll
        for (int j = 0; j < 4; j++) {
            int colg = col0 + warpN * 32 + j * 8 + (lane & 3) * 2;
            int hh = colg >> 6, d0 = colg & 63;
            float b0v = sbias[colg - col0], b1v = sbias[colg - col0 + 1];
#pragma unroll
            for (int half = 0; half < 2; half++) {
                int m = row0 + warpM * 64 + i * 16 + (lane >> 2) + half * 8;
                int b = m >> 12, l = m & 4095;
                float2 v;
                v.x = acc[i][j][half*2 + 0] + b0v;
                v.y = acc[i][j][half*2 + 1] + b1v;
                *(float2*)(C + (((size_t)(b * H_ + hh) * L_) + l) * D_ + d0) = v;
            }
        }
    }
#undef LOAD_CHUNK
#undef COMPUTE
}

// ------- T GEMMs: split-K (16 slices of 32), both Tk/Tv in one launch -------
struct TW { const float* b[2]; };
__global__ __launch_bounds__(256)
void sgemm_T_part(const float* __restrict__ A, TW tw) {
    __shared__ float As[16][68];
    __shared__ float Bs[16][64];
    int tid = threadIdx.x, tx = tid & 15, ty = tid >> 4;
    int r0 = blockIdx.y * 64, c0 = blockIdx.x * 64;
    int kc = blockIdx.z & 15, which = blockIdx.z >> 4;
    const float* Bm = tw.b[which];
    float acc[4][4];
#pragma unroll
    for (int i = 0; i < 4; i++)
#pragma unroll
        for (int j = 0; j < 4; j++) acc[i][j] = 0.f;

    for (int kt = kc * 32; kt < kc * 32 + 32; kt += 16) {
        int m = tid >> 2, k4 = tid & 3;
        float4 av = *(const float4*)(A + (size_t)(r0 + m) * DM_ + kt + k4 * 4);
        As[k4*4+0][m] = av.x; As[k4*4+1][m] = av.y;
        As[k4*4+2][m] = av.z; As[k4*4+3][m] = av.w;
        int kk = tid >> 4, n4 = tid & 15;
        *(float4*)&Bs[kk][n4 * 4] = *(const float4*)(Bm + (size_t)(kt + kk) * DM_ + c0 + n4 * 4);
        __syncthreads();
#pragma unroll
        for (int k = 0; k < 16; k++) {
            float a[4], b[4];
            *(float4*)a = *(const float4*)&As[k][ty * 4];
            *(float4*)b = *(const float4*)&Bs[k][tx * 4];
#pragma unroll
            for (int i = 0; i < 4; i++)
#pragma unroll
                for (int j = 0; j < 4; j++) acc[i][j] += a[i] * b[j];
        }
        __syncthreads();
    }
    float* dst = g_Tp + ((size_t)blockIdx.z * DM_ + r0 + ty * 4) * DM_ + c0 + tx * 4;
#pragma unroll
    for (int i = 0; i < 4; i++)
        *(float4*)(dst + (size_t)i * DM_) = make_float4(acc[i][0], acc[i][1], acc[i][2], acc[i][3]);
}

__global__ __launch_bounds__(256)
void t_combine_kernel() {
    int i = blockIdx.x * 256 + threadIdx.x;     // over 2*DM_*DM_/4 float4
    int which = i >= (DM_ * DM_ / 4) ? 1 : 0;
    int j = i - which * (DM_ * DM_ / 4);
    float4 s = make_float4(0.f, 0.f, 0.f, 0.f);
#pragma unroll
    for (int p = 0; p < 16; p++) {
        float4 v = ((const float4*)g_Tp)[(size_t)(which * 16 + p) * (DM_ * DM_ / 4) + j];
        s.x += v.x; s.y += v.y; s.z += v.z; s.w += v.w;
    }
    ((float4*)g_Tkv)[i] = s;
}

// ---------------- M[bh][l] = max_s(q·k_s) - sum_s(q·k_s)/L ----------------
__global__ __launch_bounds__(256)
void sample_m_kernel(const int* __restrict__ idx) {
    int gw = (blockIdx.x * blockDim.x + threadIdx.x) >> 5;
    int lane = threadIdx.x & 31;
    if (gw >= BH_ * L_) return;
    int bh = gw >> 12, l = gw & 4095;
    const float4* qrow = (const float4*)(g_Q + ((size_t)bh * L_ + l) * D_);
    float val = 0.f;
    bool active = lane < NS_;
    if (active) {
        int kk = idx[l * NS_ + lane];
        const float4* krow = (const float4*)(g_K + ((size_t)bh * L_ + kk) * D_);
        float s = 0.f;
#pragma unroll
        for (int d4 = 0; d4 < 16; d4++) {
            float4 q = qrow[d4], k = krow[d4];
            s += q.x*k.x + q.y*k.y + q.z*k.z + q.w*k.w;
        }
        val = s;
    }
    float mx = active ? val : -__int_as_float(0x7f800000);
    float sm = active ? val : 0.f;
#pragma unroll
    for (int off = 16; off > 0; off >>= 1) {
        mx = fmaxf(mx, __shfl_down_sync(0xffffffffu, mx, off));
        sm += __shfl_down_sync(0xffffffffu, sm, off);
    }
    if (lane == 0) g_M[gw] = mx - sm * (1.f / (float)L_);
}

// ---------------- top-27 via packed-key shfl reduce ----------------
__device__ __forceinline__ unsigned ordf(float v) {
    unsigned u = __float_as_uint(v);
    return (u & 0x80000000u) ? ~u : (u | 0x80000000u);
}

__global__ __launch_bounds__(256)
void topk_kernel() {
    int bh = blockIdx.x, t = threadIdx.x;
    int lane = t & 31, wid = t >> 5;
    __shared__ float sm[L_];
    __shared__ unsigned long long wred[8];
    for (int i = t; i < L_; i += 256) sm[i] = g_M[(size_t)bh * L_ + i];
    __syncthreads();
    for (int it = 0; it < NS_; it++) {
        unsigned long long best = 0ull;
#pragma unroll
        for (int jj = 0; jj < L_ / 256; jj++) {
            int i = t + jj * 256;
            unsigned long long key = ((unsigned long long)ordf(sm[i]) << 32)
                                   | (unsigned)(L_ - 1 - i);
            if (key > best) best = key;
        }
#pragma unroll
        for (int off = 16; off > 0; off >>= 1) {
            unsigned long long o = __shfl_down_sync(0xffffffffu, best, off);
            if (o > best) best = o;
        }
        if (lane == 0) wred[wid] = best;
        __syncthreads();
        if (t == 0) {
            unsigned long long b2 = wred[0];
#pragma unroll
            for (int w = 1; w < 8; w++) if (wred[w] > b2) b2 = wred[w];
            int idx = L_ - 1 - (int)(b2 & 0xFFFFFFFFull);
            g_topidx[bh * NS_ + it] = idx;
            sm[idx] = -__int_as_float(0x7f800000);
        }
        __syncthreads();
    }
}

// ---------------- meanV: two-stage deterministic reduce ----------------
__global__ __launch_bounds__(256)
void meanv1_kernel() {
    int bh = blockIdx.x, c = blockIdx.y, t = threadIdx.x;
    int d = t & 63, r = t >> 6;
    float s = 0.f;
    int base = c * 256;
    for (int l = base + r; l < base + 256; l += 4)
        s += g_V[((size_t)bh * L_ + l) * D_ + d];
    __shared__ float red[256];
    red[t] = s; __syncthreads();
    if (t < 64)
        g_vpart[(bh * 16 + c) * D_ + d] = red[d] + red[64+d] + red[128+d] + red[192+d];
}

__global__ __launch_bounds__(64)
void meanv2_kernel() {
    int bh = blockIdx.x, d = threadIdx.x;
    float s = 0.f;
#pragma unroll
    for (int c = 0; c < 16; c++) s += g_vpart[(bh * 16 + c) * D_ + d];
    g_meanV[bh * D_ + d] = s * (1.f / (float)L_);
}

// ---------------- fused scores+softmax+pv over one L-chunk ----------------
// grid (BH_, NCH), 256 threads. Partial (m, sum, o) per (bh, chunk, u).
#define ATT_SMEM ((NS_*CH + 64*129 + NS_*64 + 64) * 4)
__global__ __launch_bounds__(256, 2)
void att_fused_kernel() {
    extern __shared__ float smf[];
    float* sS   = smf;                       // [NS_][CH]
    float* KsT  = smf + NS_ * CH;            // [64][129]
    float* sQ   = KsT + 64 * 129;            // [NS_][64]
    float* sM   = sQ + NS_ * 64;             // [27] (+pad)
    float* sSum = sM + 32;

    int bh = blockIdx.x, ch = blockIdx.y, t = threadIdx.x;
    int lane = t & 31, w = t >> 5;
    int l0 = ch * CH;

    // load 27 Q rows
    for (int f = t; f < NS_ * 16; f += 256) {
        int u = f >> 4, d4 = f & 15;
        int l = g_topidx[bh * NS_ + u];
        *(float4*)&sQ[u * 64 + d4 * 4] =
            *(const float4*)(g_Q + ((size_t)bh * L_ + l) * D_ + d4 * 4);
    }

    // phase 1: scores into sS, subtiles of 128 k
    const int ubeg = (t >> 7) ? 14 : 0;
    const int ucnt = (t >> 7) ? 13 : 14;
    const int kk = t & 127;
#pragma unroll 1
    for (int st = 0; st < CH / 128; st++) {
        __syncthreads();
        for (int f = t; f < 128 * 16; f += 256) {
            int kr = f >> 4, d4 = f & 15;
            float4 v = *(const float4*)(g_K + ((size_t)bh * L_ + l0 + st * 128 + kr) * D_ + d4 * 4);
            KsT[(d4*4+0) * 129 + kr] = v.x; KsT[(d4*4+1) * 129 + kr] = v.y;
            KsT[(d4*4+2) * 129 + kr] = v.z; KsT[(d4*4+3) * 129 + kr] = v.w;
        }
        __syncthreads();
        float acc[14];
#pragma unroll
        for (int i = 0; i < 14; i++) acc[i] = 0.f;
#pragma unroll
        for (int d0 = 0; d0 < 64; d0 += 4) {
            float k0 = KsT[d0*129 + kk], k1 = KsT[(d0+1)*129 + kk];
            float k2 = KsT[(d0+2)*129 + kk], k3 = KsT[(d0+3)*129 + kk];
#pragma unroll
            for (int i = 0; i < 14; i++) {
                if (i < ucnt) {
                    float4 q = *(const float4*)&sQ[(ubeg + i) * 64 + d0];
                    acc[i] += q.x*k0 + q.y*k1 + q.z*k2 + q.w*k3;
                }
            }
        }
#pragma unroll
        for (int i = 0; i < 14; i++)
            if (i < ucnt) sS[(ubeg + i) * CH + st * 128 + kk] = acc[i] * 0.125f;
    }
    __syncthreads();

    // phase 2: per-u max, exp, sum (warp w handles u = w, w+8, ...)
    for (int u = w; u < NS_; u += 8) {
        float mx = -__int_as_float(0x7f800000);
#pragma unroll
        for (int j = 0; j < CH / 32; j++)
            mx = fmaxf(mx, sS[u * CH + lane + j * 32]);
#pragma unroll
        for (int off = 16; off > 0; off >>= 1)
            mx = fmaxf(mx, __shfl_xor_sync(0xffffffffu, mx, off));
        float ss = 0.f;
#pragma unroll
        for (int j = 0; j < CH / 32; j++) {
            float e = __expf(sS[u * CH + lane + j * 32] - mx);
            sS[u * CH + lane + j * 32] = e;
            ss += e;
        }
#pragma unroll
        for (int off = 16; off > 0; off >>= 1)
            ss += __shfl_xor_sync(0xffffffffu, ss, off);
        if (lane == 0) {
            int pi = (bh * NCH + ch) * NS_ + u;
            g_attM[pi] = mx;
            g_attS[pi] = ss;
        }
    }
    __syncthreads();

    // phase 3: o_partial[u][d] = sum_k p[u][k] * V[l0+k][d]
    int d = t & 63, ug = t >> 6;
    float acc[7];
#pragma unroll
    for (int j = 0; j < 7; j++) acc[j] = 0.f;
    for (int k = 0; k < CH; k += 4) {
        float v0 = g_V[((size_t)bh * L_ + l0 + k + 0) * D_ + d];
        float v1 = g_V[((size_t)bh * L_ + l0 + k + 1) * D_ + d];
        float v2 = g_V[((size_t)bh * L_ + l0 + k + 2) * D_ + d];
        float v3 = g_V[((size_t)bh * L_ + l0 + k + 3) * D_ + d];
#pragma unroll
        for (int j = 0; j < 7; j++) {
            int u = ug + j * 4;
            if (u < NS_) {
                float4 p = *(const float4*)&sS[u * CH + k];
                acc[j] += p.x*v0 + p.y*v1 + p.z*v2 + p.w*v3;
            }
        }
    }
#pragma unroll
    for (int j = 0; j < 7; j++) {
        int u = ug + j * 4;
        if (u < NS_)
            g_attO[((size_t)(bh * NCH + ch) * NS_ + u) * D_ + d] = acc[j];
    }
}

// combine partials -> g_outtop
__global__ __launch_bounds__(64)
void att_combine_kernel() {
    int bu = blockIdx.x;           // BH_*NS_
    int bh = bu / NS_, u = bu % NS_;
    int d = threadIdx.x;
    float m = -__int_as_float(0x7f800000);
#pragma unroll
    for (int c = 0; c < NCH; c++)
        m = fmaxf(m, g_attM[(bh * NCH + c) * NS_ + u]);
    float s = 0.f, o = 0.f;
#pragma unroll
    for (int c = 0; c < NCH; c++) {
        int pi = (bh * NCH + c) * NS_ + u;
        float wgt = __expf(g_attM[pi] - m);
        s += wgt * g_attS[pi];
        o += wgt * g_attO[(size_t)pi * D_ + d];
    }
    g_outtop[(bh * NS_ + u) * D_ + d] = o / s;
}

// ---------------- generic GEMV: partials then combine ----------------
__global__ __launch_bounds__(512)
void base1g_kernel(const float* __restrict__ invec, const float* __restrict__ w) {
    int b = blockIdx.x, kc = blockIdx.y, n = threadIdx.x;
    __shared__ float mc[64];
    if (n < 64) mc[n] = invec[b * DM_ + kc * 64 + n];
    __syncthreads();
    float s = 0.f;
#pragma unroll 8
    for (int k = 0; k < 64; k++) s += mc[k] * w[(size_t)(kc * 64 + k) * DM_ + n];
    g_basep[(b * 8 + kc) * DM_ + n] = s;
}

__global__ __launch_bounds__(512)
void base2g_kernel(const float* __restrict__ bias, float* __restrict__ outv) {
    int b = blockIdx.x, n = threadIdx.x;
    float s = bias[n];
#pragma unroll
    for (int p = 0; p < 8; p++) s += g_basep[(b * 8 + p) * DM_ + n];
    outv[b * DM_ + n] = s;
}

struct KV2 { const float* w[2]; const float* bias[2]; };
__global__ __launch_bounds__(512)
void basekv1_kernel(const float* __restrict__ invec, KV2 kv) {
    int b = blockIdx.x, kc = blockIdx.y, z = blockIdx.z, n = threadIdx.x;
    __shared__ float mc[64];
    if (n < 64) mc[n] = invec[b * DM_ + kc * 64 + n];
    __syncthreads();
    const float* w = kv.w[z];
    float s = 0.f;
#pragma unroll 8
    for (int k = 0; k < 64; k++) s += mc[k] * w[(size_t)(kc * 64 + k) * DM_ + n];
    g_basep2[((z * B_ + b) * 8 + kc) * DM_ + n] = s;
}

__global__ __launch_bounds__(512)
void basekv2_kernel(KV2 kv) {
    int b = blockIdx.x, z = blockIdx.y, n = threadIdx.x;
    float s = kv.bias[z][n];
#pragma unroll
    for (int p = 0; p < 8; p++) s += g_basep2[((z * B_ + b) * 8 + p) * DM_ + n];
    g_basekv[(z * B_ + b) * DM_ + n] = s;
}

// ---------------- fill K and V with broadcast base rows (one launch) -------
__global__ __launch_bounds__(256)
void fill_bcast2_kernel(float* __restrict__ dstK, float* __restrict__ dstV) {
    int i4 = blockIdx.x * 256 + threadIdx.x;
    int z = blockIdx.y;
    int d4 = i4 & 15;
    int h = (i4 >> 16) & 7;
    int b = i4 >> 19;
    float* dst = z ? dstV : dstK;
    ((float4*)dst)[i4] = ((const float4*)g_basekv)[(z * B_ + b) * 128 + h * 16 + d4];
}

// ---------------- K/V corrections ----------------
__global__ __launch_bounds__(128)
void corr_kv2_kernel(float* __restrict__ dstK, float* __restrict__ dstV) {
    int blk = blockIdx.x, z = blockIdx.y;
    int bh0 = blk / NS_, u = blk % NS_;
    int b = bh0 >> 3, h0 = bh0 & 7;
    int t = threadIdx.x;
    __shared__ float qv[64];
    if (t < 64) qv[t] = g_outtop[(bh0 * NS_ + u) * 64 + t] - g_meanV[bh0 * 64 + t];
    __syncthreads();
    const float* T = g_Tkv + (size_t)z * DM_ * DM_;
    float* dst = z ? dstV : dstK;
    int l = g_topidx[bh0 * NS_ + u];
    float a0 = 0.f, a1 = 0.f, a2 = 0.f, a3 = 0.f;
#pragma unroll 8
    for (int k = 0; k < 64; k++) {
        float q = qv[k];
        float4 wv = *(const float4*)(T + (size_t)(h0 * 64 + k) * DM_ + t * 4);
        a0 += q * wv.x; a1 += q * wv.y; a2 += q * wv.z; a3 += q * wv.w;
    }
    int n0 = t * 4;
    int h = n0 >> 6, d = n0 & 63;
    float* d_ = dst + (((size_t)(b * H_ + h) * L_) + l) * D_ + d;
    atomicAdd(d_ + 0, a0); atomicAdd(d_ + 1, a1);
    atomicAdd(d_ + 2, a2); atomicAdd(d_ + 3, a3);
}

// ---------------- output broadcasts ----------------
__global__ __launch_bounds__(256)
void bcast_out_kernel(const float* __restrict__ xs, float* __restrict__ out,
                      const float* __restrict__ basev, int row_off) {
    int i4 = blockIdx.x * 256 + threadIdx.x;
    int n4 = i4 & 127;
    int l = (i4 >> 7) & 4095;
    int b = i4 / (L_ * 128);
    size_t oi = ((size_t)(b * 8192 + row_off + l)) * 128 + n4;
    float4 a = ((const float4*)xs)[oi];
    float4 s = ((const float4*)basev)[b * 128 + n4];
    a.x += s.x; a.y += s.y; a.z += s.z; a.w += s.w;
    ((float4*)out)[oi] = a;
}

__global__ __launch_bounds__(128)
void corr_kernel(const float* __restrict__ wo, float* __restrict__ dst, int row_off) {
    int blk = blockIdx.x;
    int bh = blk / NS_, u = blk % NS_;
    int b = bh >> 3, h = bh & 7;
    int t = threadIdx.x;
    __shared__ float qv[64];
    if (t < 64) qv[t] = g_outtop[(bh * NS_ + u) * 64 + t] - g_meanV[bh * 64 + t];
    __syncthreads();
    int l = g_topidx[bh * NS_ + u];
    float a0 = 0.f, a1 = 0.f, a2 = 0.f, a3 = 0.f;
#pragma unroll 8
    for (int k = 0; k < 64; k++) {
        float q = qv[k];
        float4 wv = *(const float4*)(wo + (size_t)(h * 64 + k) * DM_ + t * 4);
        a0 += q * wv.x; a1 += q * wv.y; a2 += q * wv.z; a3 += q * wv.w;
    }
    float* d = dst + ((size_t)(b * 8192 + row_off + l)) * DM_ + t * 4;
    atomicAdd(d + 0, a0); atomicAdd(d + 1, a1);
    atomicAdd(d + 2, a2); atomicAdd(d + 3, a3);
}

// ---------------- host orchestration ----------------
extern "C" void kernel_launch(void* const* d_in, const int* in_sizes, int n_in,
                              void* d_out, int out_size) {
    const float* xs  = (const float*)d_in[0];
    const float* xd  = (const float*)d_in[1];
    const float* xp  = (const float*)d_in[2];
    const float* w0q = (const float*)d_in[3];
    const float* w0k = (const float*)d_in[4];
    const float* w0v = (const float*)d_in[5];
    const float* w0o = (const float*)d_in[6];
    const float* b0q = (const float*)d_in[7];
    const float* b0k = (const float*)d_in[8];
    const float* b0v = (const float*)d_in[9];
    const float* b0o = (const float*)d_in[10];
    const float* w1q = (const float*)d_in[11];
    const float* w1k = (const float*)d_in[12];
    const float* w1v = (const float*)d_in[13];
    const float* w1o = (const float*)d_in[14];
    const float* b1q = (const float*)d_in[15];
    const float* b1k = (const float*)d_in[16];
    const float* b1v = (const float*)d_in[17];
    const float* b1o = (const float*)d_in[18];
    float* out = (float*)d_out;

    float *pQ, *pK, *pV, *pmv, *pb0, *pb1;
    int *pidxA, *pidxB;
    __nv_bfloat16 *pAxdH, *pAxdL, *pAxpH, *pAxpL, *pWtH, *pWtL;
    cudaGetSymbolAddress((void**)&pQ, g_Q);
    cudaGetSymbolAddress((void**)&pK, g_K);
    cudaGetSymbolAddress((void**)&pV, g_V);
    cudaGetSymbolAddress((void**)&pmv, g_meanV);
    cudaGetSymbolAddress((void**)&pb0, g_base0);
    cudaGetSymbolAddress((void**)&pb1, g_base1);
    cudaGetSymbolAddress((void**)&pidxA, g_idxA);
    cudaGetSymbolAddress((void**)&pidxB, g_idxB);
    cudaGetSymbolAddress((void**)&pAxdH, g_Axd_hi);
    cudaGetSymbolAddress((void**)&pAxdL, g_Axd_lo);
    cudaGetSymbolAddress((void**)&pAxpH, g_Axp_hi);
    cudaGetSymbolAddress((void**)&pAxpL, g_Axp_lo);
    cudaGetSymbolAddress((void**)&pWtH, g_Wt_hi);
    cudaGetSymbolAddress((void**)&pWtL, g_Wt_lo);

    cudaFuncSetAttribute(gemm_mma, cudaFuncAttributeMaxDynamicSharedMemorySize, GSMEM);
    cudaFuncSetAttribute(att_fused_kernel, cudaFuncAttributeMaxDynamicSharedMemorySize, ATT_SMEM);

    // both idx streams in one launch
    {
        unsigned a42, b42, a43, b43;
        tf2x32(0u, 42u, 0u, 1u, &a42, &b42);
        tf2x32(0u, 43u, 0u, 1u, &a43, &b43);
        IdxKeys ik;
        ik.k0[0] = a42; ik.k1[0] = b42; ik.out[0] = pidxA;
        ik.k0[1] = a43; ik.k1[1] = b43; ik.out[1] = pidxB;
        idx2_kernel<<<dim3((L_ * NS_ + 255) / 256, 2), 256>>>(ik);
    }

    // 4 dense-GEMM weights: w0q, w0k, w0v, w1q
    W4 ws;
    ws.w[0] = w0q; ws.w[1] = w0k; ws.w[2] = w0v; ws.w[3] = w1q;
    wt_cvt_all_kernel<<<dim3(16, 16, 4), dim3(32, 32)>>>(ws, pWtH, pWtL);

    // T = Wo0 @ W1{k,v}: 16-way split-K partials + combine
    TW tw; tw.b[0] = w1k; tw.b[1] = w1v;
    sgemm_T_part<<<dim3(8, 8, 32), 256>>>(w0o, tw);
    t_combine_kernel<<<(2 * DM_ * DM_ / 4) / 256, 256>>>();

    // split xd and xp in one launch
    const int N4 = BL_ * DM_ / 4;
    {
        Cvt2 c;
        c.src[0] = (const float4*)xd; c.src[1] = (const float4*)xp;
        c.hi[0] = (__nv_bfloat162*)pAxdH; c.hi[1] = (__nv_bfloat162*)pAxpH;
        c.lo[0] = (__nv_bfloat162*)pAxdL; c.lo[1] = (__nv_bfloat162*)pAxpL;
        cvt_pair2_kernel<<<dim3((N4 + 255) / 256, 2), 256>>>(c, N4);
    }

    dim3 ggrid(DM_ / 128, BL_ / 128);   // (4, 128)

    // ---- layer 0: xp2 = attn(xp; xd, xd) ----
    gemm_mma<<<ggrid, 256, GSMEM>>>(pAxpH, pAxpL, pWtH + 0*(size_t)DM_*DM_, pWtL + 0*(size_t)DM_*DM_, b0q, pQ);
    gemm_mma<<<ggrid, 256, GSMEM>>>(pAxdH, pAxdL, pWtH + 1*(size_t)DM_*DM_, pWtL + 1*(size_t)DM_*DM_, b0k, pK);
    gemm_mma<<<ggrid, 256, GSMEM>>>(pAxdH, pAxdL, pWtH + 2*(size_t)DM_*DM_, pWtL + 2*(size_t)DM_*DM_, b0v, pV);
    sample_m_kernel<<<(BH_ * L_) / 8, 256>>>(pidxA);
    topk_kernel<<<BH_, 256>>>();
    meanv1_kernel<<<dim3(BH_, 16), 256>>>();
    meanv2_kernel<<<BH_, 64>>>();
    att_fused_kernel<<<dim3(BH_, NCH), 256, ATT_SMEM>>>();
    att_combine_kernel<<<BH_ * NS_, 64>>>();

    // base0 = meanctx0 @ Wo0 + bo0
    base1g_kernel<<<dim3(B_, 8), 512>>>(pmv, w0o);
    base2g_kernel<<<B_, 512>>>(b0o, pb0);

    // output upper half (xp2): xs + base0 + layer-0 corrections
    bcast_out_kernel<<<(B_ * L_ * 128) / 256, 256>>>(xs, out, pb0, 4096);
    corr_kernel<<<BH_ * NS_, 128>>>(w0o, out, 4096);

    // ---- build K1, V1 without dense GEMMs ----
    {
        KV2 kv;
        kv.w[0] = w1k; kv.w[1] = w1v;
        kv.bias[0] = b1k; kv.bias[1] = b1v;
        basekv1_kernel<<<dim3(B_, 8, 2), 512>>>(pb0, kv);
        basekv2_kernel<<<dim3(B_, 2), 512>>>(kv);
    }
    fill_bcast2_kernel<<<dim3((BH_ * L_ * 16) / 256, 2), 256>>>(pK, pV);
    corr_kv2_kernel<<<dim3(BH_ * NS_, 2), 128>>>(pK, pV);

    // layer-1 Q (dense GEMM from xd)
    gemm_mma<<<ggrid, 256, GSMEM>>>(pAxdH, pAxdL, pWtH + 3*(size_t)DM_*DM_, pWtL + 3*(size_t)DM_*DM_, b1q, pQ);

    // ---- layer 1 attention ----
    sample_m_kernel<<<(BH_ * L_) / 8, 256>>>(pidxB);
    topk_kernel<<<BH_, 256>>>();
    meanv1_kernel<<<dim3(BH_, 16), 256>>>();
    meanv2_kernel<<<BH_, 64>>>();
    att_fused_kernel<<<dim3(BH_, NCH), 256, ATT_SMEM>>>();
    att_combine_kernel<<<BH_ * NS_, 64>>>();

    // base1 = meanctx1 @ W1o + b1o; output lower half (xd2)
    base1g_kernel<<<dim3(B_, 8), 512>>>(pmv, w1o);
    base2g_kernel<<<B_, 512>>>(b1o, pb1);
    bcast_out_kernel<<<(B_ * L_ * 128) / 256, 256>>>(xs, out, pb1, 0);
    corr_kernel<<<BH_ * NS_, 128>>>(w1o, out, 0);
}

// round 9
// speedup vs baseline: 2.4776x; 1.1175x over previous
#include <cuda_runtime.h>
#include <cuda_bf16.h>
#include <math.h>
#include <stdint.h>

#define B_   4
#define H_   8
#define L_   4096
#define D_   64
#define DM_  512
#define NS_  27
#define BH_  (B_*H_)
#define BL_  (B_*L_)
#define NCH  8
#define CH   (L_/NCH)   // 512
#define SLOTS 216

// ---------------- scratch (device globals; no runtime alloc) ----------------
__device__ float g_Q[BH_*L_*D_];
__device__ float g_K[BH_*L_*D_];
__device__ float g_V[BH_*L_*D_];
__device__ float g_M[BH_*L_];
__device__ float g_outtop[BH_*NS_*D_];
__device__ float g_meanV[BH_*D_];
__device__ float g_vpart[BH_*16*D_];
__device__ float g_attM[BH_*NCH*NS_];
__device__ float g_attS[BH_*NCH*NS_];
__device__ float g_attO[BH_*NCH*NS_*D_];
__device__ float g_base0[B_*DM_];
__device__ float g_base1[B_*DM_];
__device__ float g_basekv[2*B_*DM_];
__device__ float g_basep[B_*8*DM_];
__device__ float g_basep2[2*B_*8*DM_];
__device__ float g_Tkv[2*DM_*DM_];
__device__ float g_Tp[32*DM_*DM_];
__device__ float g_ckK[B_*SLOTS*DM_];
__device__ float g_ckV[B_*SLOTS*DM_];
__device__ int   g_map[B_*L_];
__device__ int   g_cnt[B_];
__device__ int   g_idxA[L_*NS_];
__device__ int   g_idxB[L_*NS_];
__device__ int   g_topidx[BH_*NS_];

// bf16-split operand buffers
__device__ __nv_bfloat16 g_Axd_hi[(size_t)BL_*DM_];
__device__ __nv_bfloat16 g_Axd_lo[(size_t)BL_*DM_];
__device__ __nv_bfloat16 g_Axp_hi[(size_t)BL_*DM_];
__device__ __nv_bfloat16 g_Axp_lo[(size_t)BL_*DM_];
__device__ __nv_bfloat16 g_Wt_hi[4*DM_*DM_];   // w0q, w0k, w0v, w1q
__device__ __nv_bfloat16 g_Wt_lo[4*DM_*DM_];

// ---------------- Threefry-2x32 (JAX-exact) ----------------
__host__ __device__ inline void tf2x32(unsigned k0, unsigned k1,
                                       unsigned x0, unsigned x1,
                                       unsigned* o0, unsigned* o1) {
    unsigned ks0 = k0, ks1 = k1, ks2 = 0x1BD11BDAu ^ k0 ^ k1;
    x0 += ks0; x1 += ks1;
#define TF_RND(r) { x0 += x1; x1 = (x1 << (r)) | (x1 >> (32 - (r))); x1 ^= x0; }
    TF_RND(13) TF_RND(15) TF_RND(26) TF_RND(6)   x0 += ks1; x1 += ks2 + 1u;
    TF_RND(17) TF_RND(29) TF_RND(16) TF_RND(24)  x0 += ks2; x1 += ks0 + 2u;
    TF_RND(13) TF_RND(15) TF_RND(26) TF_RND(6)   x0 += ks0; x1 += ks1 + 3u;
    TF_RND(17) TF_RND(29) TF_RND(16) TF_RND(24)  x0 += ks1; x1 += ks2 + 4u;
    TF_RND(13) TF_RND(15) TF_RND(26) TF_RND(6)   x0 += ks2; x1 += ks0 + 5u;
#undef TF_RND
    *o0 = x0; *o1 = x1;
}

struct IdxKeys { unsigned k0[2], k1[2]; int* out[2]; };
__global__ void idx2_kernel(IdxKeys ik) {
    int i = blockIdx.x * blockDim.x + threadIdx.x;
    if (i >= L_*NS_) return;
    int z = blockIdx.y;
    unsigned o0, o1;
    tf2x32(ik.k0[z], ik.k1[z], 0u, (unsigned)i, &o0, &o1);
    ik.out[z][i] = (int)((o0 ^ o1) & 4095u);
}

// ---------------- bf16-split conversion (both inputs in one launch) --------
struct Cvt2 { const float4* src[2]; __nv_bfloat162* hi[2]; __nv_bfloat162* lo[2]; };
__global__ __launch_bounds__(256)
void cvt_pair2_kernel(Cvt2 c, int n4) {
    int i = blockIdx.x * 256 + threadIdx.x;
    if (i >= n4) return;
    int z = blockIdx.y;
    float4 v = c.src[z][i];
    __nv_bfloat16 h0 = __float2bfloat16(v.x), h1 = __float2bfloat16(v.y);
    __nv_bfloat16 h2 = __float2bfloat16(v.z), h3 = __float2bfloat16(v.w);
    __nv_bfloat16 l0 = __float2bfloat16(v.x - __bfloat162float(h0));
    __nv_bfloat16 l1 = __float2bfloat16(v.y - __bfloat162float(h1));
    __nv_bfloat16 l2 = __float2bfloat16(v.z - __bfloat162float(h2));
    __nv_bfloat16 l3 = __float2bfloat16(v.w - __bfloat162float(h3));
    c.hi[z][i*2]   = __nv_bfloat162(h0, h1);
    c.hi[z][i*2+1] = __nv_bfloat162(h2, h3);
    c.lo[z][i*2]   = __nv_bfloat162(l0, l1);
    c.lo[z][i*2+1] = __nv_bfloat162(l2, l3);
}

struct W4 { const float* w[4]; };
__global__ __launch_bounds__(1024)
void wt_cvt_all_kernel(W4 ws, __nv_bfloat16* __restrict__ hi, __nv_bfloat16* __restrict__ lo) {
    __shared__ float t[32][33];
    int tx = threadIdx.x, ty = threadIdx.y;
    int n0 = blockIdx.x * 32, k0 = blockIdx.y * 32;
    int z = blockIdx.z;
    const float* W = ws.w[z];
    size_t off = (size_t)z * DM_ * DM_;
    t[ty][tx] = W[(size_t)(k0 + ty) * DM_ + n0 + tx];
    __syncthreads();
    float v = t[tx][ty];
    int n = n0 + ty, k = k0 + tx;
    __nv_bfloat16 h = __float2bfloat16(v);
    hi[off + (size_t)n * DM_ + k] = h;
    lo[off + (size_t)n * DM_ + k] = __float2bfloat16(v - __bfloat162float(h));
}

// ---------------- PTX helpers ----------------
__device__ __forceinline__ void cp16s(uint32_t saddr, const void* g) {
    asm volatile("cp.async.cg.shared.global [%0], [%1], 16;\n" :: "r"(saddr), "l"(g));
}
#define CP_COMMIT() asm volatile("cp.async.commit_group;\n" ::: "memory")
#define CP_WAIT(n)  asm volatile("cp.async.wait_group %0;\n" :: "n"(n) : "memory")

__device__ __forceinline__ void ldsm4(uint32_t& r0, uint32_t& r1, uint32_t& r2, uint32_t& r3,
                                      uint32_t saddr) {
    asm volatile("ldmatrix.sync.aligned.m8n8.x4.shared.b16 {%0,%1,%2,%3}, [%4];"
                 : "=r"(r0), "=r"(r1), "=r"(r2), "=r"(r3) : "r"(saddr));
}

__device__ __forceinline__ void mma_bf16(float* c, const uint32_t* a, const uint32_t* b) {
    asm volatile("mma.sync.aligned.m16n8k16.row.col.f32.bf16.bf16.f32 "
                 "{%0,%1,%2,%3}, {%4,%5,%6,%7}, {%8,%9}, {%0,%1,%2,%3};"
                 : "+f"(c[0]), "+f"(c[1]), "+f"(c[2]), "+f"(c[3])
                 : "r"(a[0]), "r"(a[1]), "r"(a[2]), "r"(a[3]), "r"(b[0]), "r"(b[1]));
}

// ---------------- mma.sync bf16-split GEMM (4-stage pipeline) ----------------
#define GST    40960
#define NSTG   4
#define GSMEM  (2048 + NSTG*GST)

__global__ __launch_bounds__(256, 1)
void gemm_mma(const __nv_bfloat16* __restrict__ Ahi, const __nv_bfloat16* __restrict__ Alo,
              const __nv_bfloat16* __restrict__ Bhi, const __nv_bfloat16* __restrict__ Blo,
              const float* __restrict__ bias, float* __restrict__ C) {
    extern __shared__ char smem[];
    const uint32_t sb = (uint32_t)__cvta_generic_to_shared(smem);
    const int tid = threadIdx.x;
    const int lane = tid & 31, wid = tid >> 5;
    const int warpM = wid >> 2, warpN = wid & 3;
    const int row0 = blockIdx.y * 128, col0 = blockIdx.x * 128;

    float* sbias = (float*)smem;
    if (tid < 128) sbias[tid] = bias[col0 + tid];

    float acc[4][4][4];
#pragma unroll
    for (int i = 0; i < 4; i++)
#pragma unroll
        for (int j = 0; j < 4; j++)
#pragma unroll
            for (int r = 0; r < 4; r++) acc[i][j][r] = 0.f;

    const int a_row = warpM * 64 + (lane & 15);
    const int a_kb  = ((lane >> 4) * 8) * 2;
    const int b_row = warpN * 32 + (lane & 7) + ((lane >> 4) & 1) * 8;
    const int b_kb  = (((lane >> 3) & 1) * 8) * 2;

#define LOAD_CHUNK(c, s) {                                                     \
    uint32_t stb = sb + 2048 + (uint32_t)(s) * GST;                            \
    int k0 = (c) * 32;                                                         \
    _Pragma("unroll")                                                          \
    for (int j = 0; j < 8; j++) {                                              \
        int idx = tid + j * 256;                                               \
        int tile = idx >> 9, w = idx & 511;                                    \
        int r = w >> 2, cc = w & 3;                                            \
        uint32_t so = stb + (uint32_t)tile * 10240u + (uint32_t)(r * 80 + cc * 16); \
        const __nv_bfloat16* gp;                                               \
        if      (tile == 0) gp = Ahi + (size_t)(row0 + r) * DM_ + k0 + cc * 8; \
        else if (tile == 1) gp = Alo + (size_t)(row0 + r) * DM_ + k0 + cc * 8; \
        else if (tile == 2) gp = Bhi + (size_t)(col0 + r) * DM_ + k0 + cc * 8; \
        else                gp = Blo + (size_t)(col0 + r) * DM_ + k0 + cc * 8; \
        cp16s(so, gp);                                                         \
    }                                                                          \
    CP_COMMIT(); }

#define COMPUTE(s) {                                                                 \
    uint32_t stb = sb + 2048 + (uint32_t)(s) * GST;                                  \
    _Pragma("unroll")                                                                \
    for (int k16 = 0; k16 < 2; k16++) {                                             \
        uint32_t ah[4][4], al[4][4], bh[4][2], bl[4][2];                             \
        _Pragma("unroll")                                                            \
        for (int i = 0; i < 4; i++)                                                  \
            ldsm4(ah[i][0], ah[i][1], ah[i][2], ah[i][3],                            \
                  stb + (uint32_t)((a_row + i*16) * 80 + k16*32 + a_kb));            \
        _Pragma("unroll")                                                            \
        for (int n16 = 0; n16 < 2; n16++)                                            \
            ldsm4(bh[n16*2][0], bh[n16*2][1], bh[n16*2+1][0], bh[n16*2+1][1],        \
                  stb + 20480u + (uint32_t)((b_row + n16*16) * 80 + k16*32 + b_kb)); \
        _Pragma("unroll")                                                            \
        for (int i = 0; i < 4; i++)                                                  \
            _Pragma("unroll")                                                        \
            for (int j = 0; j < 4; j++) mma_bf16(acc[i][j], ah[i], bh[j]);           \
        _Pragma("unroll")                                                            \
        for (int n16 = 0; n16 < 2; n16++)                                            \
            ldsm4(bl[n16*2][0], bl[n16*2][1], bl[n16*2+1][0], bl[n16*2+1][1],        \
                  stb + 30720u + (uint32_t)((b_row + n16*16) * 80 + k16*32 + b_kb)); \
        _Pragma("unroll")                                                            \
        for (int i = 0; i < 4; i++)                                                  \
            _Pragma("unroll")                                                        \
            for (int j = 0; j < 4; j++) mma_bf16(acc[i][j], ah[i], bl[j]);           \
        _Pragma("unroll")                                                            \
        for (int i = 0; i < 4; i++)                                                  \
            ldsm4(al[i][0], al[i][1], al[i][2], al[i][3],                            \
                  stb + 10240u + (uint32_t)((a_row + i*16) * 80 + k16*32 + a_kb));   \
        _Pragma("unroll")                                                            \
        for (int i = 0; i < 4; i++)                                                  \
            _Pragma("unroll")                                                        \
            for (int j = 0; j < 4; j++) mma_bf16(acc[i][j], al[i], bh[j]);           \
    } }

    LOAD_CHUNK(0, 0);
    LOAD_CHUNK(1, 1);
    LOAD_CHUNK(2, 2);

    const int nIter = DM_ / 32;   // 16
#pragma unroll 1
    for (int c = 0; c < nIter; c++) {
        if (c < nIter - 2)      { CP_WAIT(2); }
        else if (c == nIter - 2){ CP_WAIT(1); }
        else                    { CP_WAIT(0); }
        __syncthreads();
        if (c + 3 < nIter) LOAD_CHUNK(c + 3, (c + 3) & 3);
        COMPUTE(c & 3);
    }

    __syncthreads();
#pragma unroll
    for (int i = 0; i < 4; i++) {
#pragma unroll
        for (int j = 0; j < 4; j++) {
            int colg = col0 + warpN * 32 + j * 8 + (lane & 3) * 2;
            int hh = colg >> 6, d0 = colg & 63;
            float b0v = sbias[colg - col0], b1v = sbias[colg - col0 + 1];
#pragma unroll
            for (int half = 0; half < 2; half++) {
                int m = row0 + warpM * 64 + i * 16 + (lane >> 2) + half * 8;
                int b = m >> 12, l = m & 4095;
                float2 v;
                v.x = acc[i][j][half*2 + 0] + b0v;
                v.y = acc[i][j][half*2 + 1] + b1v;
                *(float2*)(C + (((size_t)(b * H_ + hh) * L_) + l) * D_ + d0) = v;
            }
        }
    }
#undef LOAD_CHUNK
#undef COMPUTE
}

// ------- T GEMMs: split-K (16 slices of 32), both Tk/Tv in one launch -------
struct TW { const float* b[2]; };
__global__ __launch_bounds__(256)
void sgemm_T_part(const float* __restrict__ A, TW tw) {
    __shared__ float As[16][68];
    __shared__ float Bs[16][64];
    int tid = threadIdx.x, tx = tid & 15, ty = tid >> 4;
    int r0 = blockIdx.y * 64, c0 = blockIdx.x * 64;
    int kc = blockIdx.z & 15, which = blockIdx.z >> 4;
    const float* Bm = tw.b[which];
    float acc[4][4];
#pragma unroll
    for (int i = 0; i < 4; i++)
#pragma unroll
        for (int j = 0; j < 4; j++) acc[i][j] = 0.f;

    for (int kt = kc * 32; kt < kc * 32 + 32; kt += 16) {
        int m = tid >> 2, k4 = tid & 3;
        float4 av = *(const float4*)(A + (size_t)(r0 + m) * DM_ + kt + k4 * 4);
        As[k4*4+0][m] = av.x; As[k4*4+1][m] = av.y;
        As[k4*4+2][m] = av.z; As[k4*4+3][m] = av.w;
        int kk = tid >> 4, n4 = tid & 15;
        *(float4*)&Bs[kk][n4 * 4] = *(const float4*)(Bm + (size_t)(kt + kk) * DM_ + c0 + n4 * 4);
        __syncthreads();
#pragma unroll
        for (int k = 0; k < 16; k++) {
            float a[4], b[4];
            *(float4*)a = *(const float4*)&As[k][ty * 4];
            *(float4*)b = *(const float4*)&Bs[k][tx * 4];
#pragma unroll
            for (int i = 0; i < 4; i++)
#pragma unroll
                for (int j = 0; j < 4; j++) acc[i][j] += a[i] * b[j];
        }
        __syncthreads();
    }
    float* dst = g_Tp + ((size_t)blockIdx.z * DM_ + r0 + ty * 4) * DM_ + c0 + tx * 4;
#pragma unroll
    for (int i = 0; i < 4; i++)
        *(float4*)(dst + (size_t)i * DM_) = make_float4(acc[i][0], acc[i][1], acc[i][2], acc[i][3]);
}

__global__ __launch_bounds__(256)
void t_combine_kernel() {
    int i = blockIdx.x * 256 + threadIdx.x;
    int which = i >= (DM_ * DM_ / 4) ? 1 : 0;
    int j = i - which * (DM_ * DM_ / 4);
    float4 s = make_float4(0.f, 0.f, 0.f, 0.f);
#pragma unroll
    for (int p = 0; p < 16; p++) {
        float4 v = ((const float4*)g_Tp)[(size_t)(which * 16 + p) * (DM_ * DM_ / 4) + j];
        s.x += v.x; s.y += v.y; s.z += v.z; s.w += v.w;
    }
    ((float4*)g_Tkv)[i] = s;
}

// ---------------- layer-0 sample_m (dense K) ----------------
__global__ __launch_bounds__(256)
void sample_m_kernel(const int* __restrict__ idx) {
    int gw = (blockIdx.x * blockDim.x + threadIdx.x) >> 5;
    int lane = threadIdx.x & 31;
    if (gw >= BH_ * L_) return;
    int bh = gw >> 12, l = gw & 4095;
    const float4* qrow = (const float4*)(g_Q + ((size_t)bh * L_ + l) * D_);
    float val = 0.f;
    bool active = lane < NS_;
    if (active) {
        int kk = idx[l * NS_ + lane];
        const float4* krow = (const float4*)(g_K + ((size_t)bh * L_ + kk) * D_);
        float s = 0.f;
#pragma unroll
        for (int d4 = 0; d4 < 16; d4++) {
            float4 q = qrow[d4], k = krow[d4];
            s += q.x*k.x + q.y*k.y + q.z*k.z + q.w*k.w;
        }
        val = s;
    }
    float mx = active ? val : -__int_as_float(0x7f800000);
    float sm = active ? val : 0.f;
#pragma unroll
    for (int off = 16; off > 0; off >>= 1) {
        mx = fmaxf(mx, __shfl_down_sync(0xffffffffu, mx, off));
        sm += __shfl_down_sync(0xffffffffu, sm, off);
    }
    if (lane == 0) g_M[gw] = mx - sm * (1.f / (float)L_);
}

// ---------------- layer-1 sample_m (low-rank K1) ----------------
__global__ __launch_bounds__(256)
void sample_m1_kernel(const int* __restrict__ idx) {
    int gw = (blockIdx.x * blockDim.x + threadIdx.x) >> 5;
    int lane = threadIdx.x & 31;
    if (gw >= BH_ * L_) return;
    int bh = gw >> 12, l = gw & 4095;
    int b = bh >> 3, h = bh & 7;
    const float4* qrow = (const float4*)(g_Q + ((size_t)bh * L_ + l) * D_);
    const float4* brow = (const float4*)(g_basekv + (size_t)b * DM_ + h * D_);
    bool active = lane < NS_;
    int j = -1;
    if (active) {
        int kk = idx[l * NS_ + lane];
        j = g_map[b * L_ + kk];
    }
    float s = 0.f;
#pragma unroll
    for (int d4 = 0; d4 < 16; d4++) {
        float4 q = qrow[d4], bb = brow[d4];
        s += q.x*bb.x + q.y*bb.y + q.z*bb.z + q.w*bb.w;
    }
    if (j >= 0) {
        const float4* crow = (const float4*)(g_ckK + ((size_t)(b * SLOTS + j)) * DM_ + h * D_);
#pragma unroll
        for (int d4 = 0; d4 < 16; d4++) {
            float4 q = qrow[d4], c = crow[d4];
            s += q.x*c.x + q.y*c.y + q.z*c.z + q.w*c.w;
        }
    }
    float val = s;
    float mx = active ? val : -__int_as_float(0x7f800000);
    float sm = active ? val : 0.f;
#pragma unroll
    for (int off = 16; off > 0; off >>= 1) {
        mx = fmaxf(mx, __shfl_down_sync(0xffffffffu, mx, off));
        sm += __shfl_down_sync(0xffffffffu, sm, off);
    }
    if (lane == 0) g_M[gw] = mx - sm * (1.f / (float)L_);
}

// ---------------- top-27 via packed-key shfl reduce ----------------
__device__ __forceinline__ unsigned ordf(float v) {
    unsigned u = __float_as_uint(v);
    return (u & 0x80000000u) ? ~u : (u | 0x80000000u);
}

__global__ __launch_bounds__(256)
void topk_kernel() {
    int bh = blockIdx.x, t = threadIdx.x;
    int lane = t & 31, wid = t >> 5;
    __shared__ float sm[L_];
    __shared__ unsigned long long wred[8];
    for (int i = t; i < L_; i += 256) sm[i] = g_M[(size_t)bh * L_ + i];
    __syncthreads();
    for (int it = 0; it < NS_; it++) {
        unsigned long long best = 0ull;
#pragma unroll
        for (int jj = 0; jj < L_ / 256; jj++) {
            int i = t + jj * 256;
            unsigned long long key = ((unsigned long long)ordf(sm[i]) << 32)
                                   | (unsigned)(L_ - 1 - i);
            if (key > best) best = key;
        }
#pragma unroll
        for (int off = 16; off > 0; off >>= 1) {
            unsigned long long o = __shfl_down_sync(0xffffffffu, best, off);
            if (o > best) best = o;
        }
        if (lane == 0) wred[wid] = best;
        __syncthreads();
        if (t == 0) {
            unsigned long long b2 = wred[0];
#pragma unroll
            for (int w = 1; w < 8; w++) if (wred[w] > b2) b2 = wred[w];
            int idx = L_ - 1 - (int)(b2 & 0xFFFFFFFFull);
            g_topidx[bh * NS_ + it] = idx;
            sm[idx] = -__int_as_float(0x7f800000);
        }
        __syncthreads();
    }
}

// ---------------- layer-0 meanV: two-stage ----------------
__global__ __launch_bounds__(256)
void meanv1_kernel() {
    int bh = blockIdx.x, c = blockIdx.y, t = threadIdx.x;
    int d = t & 63, r = t >> 6;
    float s = 0.f;
    int base = c * 256;
    for (int l = base + r; l < base + 256; l += 4)
        s += g_V[((size_t)bh * L_ + l) * D_ + d];
    __shared__ float red[256];
    red[t] = s; __syncthreads();
    if (t < 64)
        g_vpart[(bh * 16 + c) * D_ + d] = red[d] + red[64+d] + red[128+d] + red[192+d];
}

__global__ __launch_bounds__(64)
void meanv2_kernel() {
    int bh = blockIdx.x, d = threadIdx.x;
    float s = 0.f;
#pragma unroll
    for (int c = 0; c < 16; c++) s += g_vpart[(bh * 16 + c) * D_ + d];
    g_meanV[bh * D_ + d] = s * (1.f / (float)L_);
}

// ---------------- layer-1 meanV (low-rank) ----------------
__global__ __launch_bounds__(64)
void meanv1b_kernel() {
    int bh = blockIdx.x, t = threadIdx.x;
    int b = bh >> 3, h = bh & 7;
    int cnt = g_cnt[b];
    float s = 0.f;
    for (int j = 0; j < cnt; j++)
        s += g_ckV[((size_t)(b * SLOTS + j)) * DM_ + h * D_ + t];
    g_meanV[bh * D_ + t] = g_basekv[(size_t)(B_ + b) * DM_ + h * D_ + t] + s * (1.f / (float)L_);
}

// ---------------- layer-0 fused scores+softmax+pv ----------------
#define ATT_SMEM ((NS_*CH + 64*129 + NS_*64 + 64) * 4)
__global__ __launch_bounds__(256, 2)
void att_fused_kernel() {
    extern __shared__ float smf[];
    float* sS   = smf;
    float* KsT  = smf + NS_ * CH;
    float* sQ   = KsT + 64 * 129;

    int bh = blockIdx.x, ch = blockIdx.y, t = threadIdx.x;
    int lane = t & 31, w = t >> 5;
    int l0 = ch * CH;

    for (int f = t; f < NS_ * 16; f += 256) {
        int u = f >> 4, d4 = f & 15;
        int l = g_topidx[bh * NS_ + u];
        *(float4*)&sQ[u * 64 + d4 * 4] =
            *(const float4*)(g_Q + ((size_t)bh * L_ + l) * D_ + d4 * 4);
    }

    const int ubeg = (t >> 7) ? 14 : 0;
    const int ucnt = (t >> 7) ? 13 : 14;
    const int kk = t & 127;
#pragma unroll 1
    for (int st = 0; st < CH / 128; st++) {
        __syncthreads();
        for (int f = t; f < 128 * 16; f += 256) {
            int kr = f >> 4, d4 = f & 15;
            float4 v = *(const float4*)(g_K + ((size_t)bh * L_ + l0 + st * 128 + kr) * D_ + d4 * 4);
            KsT[(d4*4+0) * 129 + kr] = v.x; KsT[(d4*4+1) * 129 + kr] = v.y;
            KsT[(d4*4+2) * 129 + kr] = v.z; KsT[(d4*4+3) * 129 + kr] = v.w;
        }
        __syncthreads();
        float acc[14];
#pragma unroll
        for (int i = 0; i < 14; i++) acc[i] = 0.f;
#pragma unroll
        for (int d0 = 0; d0 < 64; d0 += 4) {
            float k0 = KsT[d0*129 + kk], k1 = KsT[(d0+1)*129 + kk];
            float k2 = KsT[(d0+2)*129 + kk], k3 = KsT[(d0+3)*129 + kk];
#pragma unroll
            for (int i = 0; i < 14; i++) {
                if (i < ucnt) {
                    float4 q = *(const float4*)&sQ[(ubeg + i) * 64 + d0];
                    acc[i] += q.x*k0 + q.y*k1 + q.z*k2 + q.w*k3;
                }
            }
        }
#pragma unroll
        for (int i = 0; i < 14; i++)
            if (i < ucnt) sS[(ubeg + i) * CH + st * 128 + kk] = acc[i] * 0.125f;
    }
    __syncthreads();

    for (int u = w; u < NS_; u += 8) {
        float mx = -__int_as_float(0x7f800000);
#pragma unroll
        for (int j = 0; j < CH / 32; j++)
            mx = fmaxf(mx, sS[u * CH + lane + j * 32]);
#pragma unroll
        for (int off = 16; off > 0; off >>= 1)
            mx = fmaxf(mx, __shfl_xor_sync(0xffffffffu, mx, off));
        float ss = 0.f;
#pragma unroll
        for (int j = 0; j < CH / 32; j++) {
            float e = __expf(sS[u * CH + lane + j * 32] - mx);
            sS[u * CH + lane + j * 32] = e;
            ss += e;
        }
#pragma unroll
        for (int off = 16; off > 0; off >>= 1)
            ss += __shfl_xor_sync(0xffffffffu, ss, off);
        if (lane == 0) {
            int pi = (bh * NCH + ch) * NS_ + u;
            g_attM[pi] = mx;
            g_attS[pi] = ss;
        }
    }
    __syncthreads();

    int d = t & 63, ug = t >> 6;
    float acc[7];
#pragma unroll
    for (int j = 0; j < 7; j++) acc[j] = 0.f;
    for (int k = 0; k < CH; k += 4) {
        float v0 = g_V[((size_t)bh * L_ + l0 + k + 0) * D_ + d];
        float v1 = g_V[((size_t)bh * L_ + l0 + k + 1) * D_ + d];
        float v2 = g_V[((size_t)bh * L_ + l0 + k + 2) * D_ + d];
        float v3 = g_V[((size_t)bh * L_ + l0 + k + 3) * D_ + d];
#pragma unroll
        for (int j = 0; j < 7; j++) {
            int u = ug + j * 4;
            if (u < NS_) {
                float4 p = *(const float4*)&sS[u * CH + k];
                acc[j] += p.x*v0 + p.y*v1 + p.z*v2 + p.w*v3;
            }
        }
    }
#pragma unroll
    for (int j = 0; j < 7; j++) {
        int u = ug + j * 4;
        if (u < NS_)
            g_attO[((size_t)(bh * NCH + ch) * NS_ + u) * D_ + d] = acc[j];
    }
}

__global__ __launch_bounds__(64)
void att_combine_kernel() {
    int bu = blockIdx.x;
    int bh = bu / NS_, u = bu % NS_;
    int d = threadIdx.x;
    float m = -__int_as_float(0x7f800000);
#pragma unroll
    for (int c = 0; c < NCH; c++)
        m = fmaxf(m, g_attM[(bh * NCH + c) * NS_ + u]);
    float s = 0.f, o = 0.f;
#pragma unroll
    for (int c = 0; c < NCH; c++) {
        int pi = (bh * NCH + c) * NS_ + u;
        float wgt = __expf(g_attM[pi] - m);
        s += wgt * g_attS[pi];
        o += wgt * g_attO[(size_t)pi * D_ + d];
    }
    g_outtop[(bh * NS_ + u) * D_ + d] = o / s;
}

// ---------------- layer-1 attention over low-rank K1/V1 ----------------
__global__ __launch_bounds__(256)
void att1_fused_kernel() {
    __shared__ float sQ[64];
    __shared__ float sS[SLOTS];
    __shared__ float red[256];
    __shared__ float sstat[2];
    int bu = blockIdx.x;
    int bh = bu / NS_, u = bu % NS_;
    int b = bh >> 3, h = bh & 7;
    int t = threadIdx.x;
    int cnt = g_cnt[b];
    int lsel = g_topidx[bh * NS_ + u];
    if (t < 64) sQ[t] = g_Q[((size_t)bh * L_ + lsel) * D_ + t];
    __syncthreads();

    // qb = 0.125 * q . base_k
    if (t < 32) {
        float p = sQ[t] * g_basekv[(size_t)b * DM_ + h * D_ + t]
                + sQ[t + 32] * g_basekv[(size_t)b * DM_ + h * D_ + t + 32];
#pragma unroll
        for (int off = 16; off > 0; off >>= 1)
            p += __shfl_xor_sync(0xffffffffu, p, off);
        if (t == 0) sstat[0] = 0.125f * p;
    }
    __syncthreads();
    float qb = sstat[0];

    float sj = -__int_as_float(0x7f800000);
    if (t < cnt) {
        const float4* c = (const float4*)(g_ckK + ((size_t)(b * SLOTS + t)) * DM_ + h * D_);
        float dot = 0.f;
#pragma unroll
        for (int d4 = 0; d4 < 16; d4++) {
            float4 cv = c[d4];
            dot += sQ[d4*4]*cv.x + sQ[d4*4+1]*cv.y + sQ[d4*4+2]*cv.z + sQ[d4*4+3]*cv.w;
        }
        sj = qb + 0.125f * dot;
        sS[t] = sj;
    }
    red[t] = sj;
    __syncthreads();
    for (int s = 128; s > 0; s >>= 1) {
        if (t < s) red[t] = fmaxf(red[t], red[t + s]);
        __syncthreads();
    }
    float m = fmaxf(red[0], qb);
    __syncthreads();

    float e = 0.f;
    if (t < cnt) { e = __expf(sS[t] - m); sS[t] = e; }
    red[t] = e;
    __syncthreads();
    for (int s = 128; s > 0; s >>= 1) {
        if (t < s) red[t] += red[t + s];
        __syncthreads();
    }
    if (t == 0)
        sstat[1] = 1.f / (red[0] + (float)(L_ - cnt) * __expf(qb - m));
    __syncthreads();
    float inv = sstat[1];

    if (t < 64) {
        float o = 0.f;
        for (int j = 0; j < cnt; j++)
            o += sS[j] * g_ckV[((size_t)(b * SLOTS + j)) * DM_ + h * D_ + t];
        o = o * inv + g_basekv[(size_t)(B_ + b) * DM_ + h * D_ + t];
        g_outtop[(bh * NS_ + u) * D_ + t] = o;
    }
}

// ---------------- map build: mark -> slot-assign -> accumulate -------------
__global__ void mark_kernel() {
    int i = threadIdx.x;
    if (i < BH_ * NS_) {
        int bh = i / NS_;
        int b = bh >> 3;
        g_map[b * L_ + g_topidx[i]] = 1;
    }
}

__global__ __launch_bounds__(256)
void slot_assign_kernel() {
    int b = blockIdx.x, t = threadIdx.x;
    __shared__ int cs[256];
    int base = t * 16;
    int c = 0;
#pragma unroll
    for (int i = 0; i < 16; i++)
        if (g_map[b * L_ + base + i] == 1) c++;
    cs[t] = c;
    __syncthreads();
    for (int off = 1; off < 256; off <<= 1) {
        int v = (t >= off) ? cs[t - off] : 0;
        __syncthreads();
        cs[t] += v;
        __syncthreads();
    }
    int slot = cs[t] - c;
#pragma unroll
    for (int i = 0; i < 16; i++) {
        if (g_map[b * L_ + base + i] == 1)
            g_map[b * L_ + base + i] = slot++;
    }
    if (t == 255) g_cnt[b] = cs[255];
}

// accumulate compact corrections: ck{K,V}[b][slot] += qv @ T[h0*64:,:]
__global__ __launch_bounds__(128)
void corr_compact_kernel() {
    int blk = blockIdx.x, z = blockIdx.y;
    int bh0 = blk / NS_, u = blk % NS_;
    int b = bh0 >> 3, h0 = bh0 & 7;
    int t = threadIdx.x;
    __shared__ float qv[64];
    if (t < 64) qv[t] = g_outtop[(bh0 * NS_ + u) * 64 + t] - g_meanV[bh0 * 64 + t];
    __syncthreads();
    const float* T = g_Tkv + (size_t)z * DM_ * DM_;
    int l = g_topidx[bh0 * NS_ + u];
    int slot = g_map[b * L_ + l];
    float a0 = 0.f, a1 = 0.f, a2 = 0.f, a3 = 0.f;
#pragma unroll 8
    for (int k = 0; k < 64; k++) {
        float q = qv[k];
        float4 wv = *(const float4*)(T + (size_t)(h0 * 64 + k) * DM_ + t * 4);
        a0 += q * wv.x; a1 += q * wv.y; a2 += q * wv.z; a3 += q * wv.w;
    }
    float* dst = (z ? g_ckV : g_ckK) + ((size_t)(b * SLOTS + slot)) * DM_ + t * 4;
    atomicAdd(dst + 0, a0); atomicAdd(dst + 1, a1);
    atomicAdd(dst + 2, a2); atomicAdd(dst + 3, a3);
}

// ---------------- generic GEMV: partials then combine ----------------
__global__ __launch_bounds__(512)
void base1g_kernel(const float* __restrict__ invec, const float* __restrict__ w) {
    int b = blockIdx.x, kc = blockIdx.y, n = threadIdx.x;
    __shared__ float mc[64];
    if (n < 64) mc[n] = invec[b * DM_ + kc * 64 + n];
    __syncthreads();
    float s = 0.f;
#pragma unroll 8
    for (int k = 0; k < 64; k++) s += mc[k] * w[(size_t)(kc * 64 + k) * DM_ + n];
    g_basep[(b * 8 + kc) * DM_ + n] = s;
}

__global__ __launch_bounds__(512)
void base2g_kernel(const float* __restrict__ bias, float* __restrict__ outv) {
    int b = blockIdx.x, n = threadIdx.x;
    float s = bias[n];
#pragma unroll
    for (int p = 0; p < 8; p++) s += g_basep[(b * 8 + p) * DM_ + n];
    outv[b * DM_ + n] = s;
}

struct KV2 { const float* w[2]; const float* bias[2]; };
__global__ __launch_bounds__(512)
void basekv1_kernel(const float* __restrict__ invec, KV2 kv) {
    int b = blockIdx.x, kc = blockIdx.y, z = blockIdx.z, n = threadIdx.x;
    __shared__ float mc[64];
    if (n < 64) mc[n] = invec[b * DM_ + kc * 64 + n];
    __syncthreads();
    const float* w = kv.w[z];
    float s = 0.f;
#pragma unroll 8
    for (int k = 0; k < 64; k++) s += mc[k] * w[(size_t)(kc * 64 + k) * DM_ + n];
    g_basep2[((z * B_ + b) * 8 + kc) * DM_ + n] = s;
}

__global__ __launch_bounds__(512)
void basekv2_kernel(KV2 kv) {
    int b = blockIdx.x, z = blockIdx.y, n = threadIdx.x;
    float s = kv.bias[z][n];
#pragma unroll
    for (int p = 0; p < 8; p++) s += g_basep2[((z * B_ + b) * 8 + p) * DM_ + n];
    g_basekv[(z * B_ + b) * DM_ + n] = s;
}

// ---------------- output broadcasts ----------------
__global__ __launch_bounds__(256)
void bcast_out_kernel(const float* __restrict__ xs, float* __restrict__ out,
                      const float* __restrict__ basev, int row_off) {
    int i4 = blockIdx.x * 256 + threadIdx.x;
    int n4 = i4 & 127;
    int l = (i4 >> 7) & 4095;
    int b = i4 / (L_ * 128);
    size_t oi = ((size_t)(b * 8192 + row_off + l)) * 128 + n4;
    float4 a = ((const float4*)xs)[oi];
    float4 s = ((const float4*)basev)[b * 128 + n4];
    a.x += s.x; a.y += s.y; a.z += s.z; a.w += s.w;
    ((float4*)out)[oi] = a;
}

__global__ __launch_bounds__(128)
void corr_kernel(const float* __restrict__ wo, float* __restrict__ dst, int row_off) {
    int blk = blockIdx.x;
    int bh = blk / NS_, u = blk % NS_;
    int b = bh >> 3, h = bh & 7;
    int t = threadIdx.x;
    __shared__ float qv[64];
    if (t < 64) qv[t] = g_outtop[(bh * NS_ + u) * 64 + t] - g_meanV[bh * 64 + t];
    __syncthreads();
    int l = g_topidx[bh * NS_ + u];
    float a0 = 0.f, a1 = 0.f, a2 = 0.f, a3 = 0.f;
#pragma unroll 8
    for (int k = 0; k < 64; k++) {
        float q = qv[k];
        float4 wv = *(const float4*)(wo + (size_t)(h * 64 + k) * DM_ + t * 4);
        a0 += q * wv.x; a1 += q * wv.y; a2 += q * wv.z; a3 += q * wv.w;
    }
    float* d = dst + ((size_t)(b * 8192 + row_off + l)) * DM_ + t * 4;
    atomicAdd(d + 0, a0); atomicAdd(d + 1, a1);
    atomicAdd(d + 2, a2); atomicAdd(d + 3, a3);
}

// ---------------- host orchestration ----------------
extern "C" void kernel_launch(void* const* d_in, const int* in_sizes, int n_in,
                              void* d_out, int out_size) {
    const float* xs  = (const float*)d_in[0];
    const float* xd  = (const float*)d_in[1];
    const float* xp  = (const float*)d_in[2];
    const float* w0q = (const float*)d_in[3];
    const float* w0k = (const float*)d_in[4];
    const float* w0v = (const float*)d_in[5];
    const float* w0o = (const float*)d_in[6];
    const float* b0q = (const float*)d_in[7];
    const float* b0k = (const float*)d_in[8];
    const float* b0v = (const float*)d_in[9];
    const float* b0o = (const float*)d_in[10];
    const float* w1q = (const float*)d_in[11];
    const float* w1k = (const float*)d_in[12];
    const float* w1v = (const float*)d_in[13];
    const float* w1o = (const float*)d_in[14];
    const float* b1q = (const float*)d_in[15];
    const float* b1k = (const float*)d_in[16];
    const float* b1v = (const float*)d_in[17];
    const float* b1o = (const float*)d_in[18];
    float* out = (float*)d_out;

    float *pQ, *pK, *pV, *pmv, *pb0, *pb1, *pckK, *pckV;
    int *pidxA, *pidxB, *pmap, *pcnt;
    __nv_bfloat16 *pAxdH, *pAxdL, *pAxpH, *pAxpL, *pWtH, *pWtL;
    cudaGetSymbolAddress((void**)&pQ, g_Q);
    cudaGetSymbolAddress((void**)&pK, g_K);
    cudaGetSymbolAddress((void**)&pV, g_V);
    cudaGetSymbolAddress((void**)&pmv, g_meanV);
    cudaGetSymbolAddress((void**)&pb0, g_base0);
    cudaGetSymbolAddress((void**)&pb1, g_base1);
    cudaGetSymbolAddress((void**)&pckK, g_ckK);
    cudaGetSymbolAddress((void**)&pckV, g_ckV);
    cudaGetSymbolAddress((void**)&pmap, g_map);
    cudaGetSymbolAddress((void**)&pcnt, g_cnt);
    cudaGetSymbolAddress((void**)&pidxA, g_idxA);
    cudaGetSymbolAddress((void**)&pidxB, g_idxB);
    cudaGetSymbolAddress((void**)&pAxdH, g_Axd_hi);
    cudaGetSymbolAddress((void**)&pAxdL, g_Axd_lo);
    cudaGetSymbolAddress((void**)&pAxpH, g_Axp_hi);
    cudaGetSymbolAddress((void**)&pAxpL, g_Axp_lo);
    cudaGetSymbolAddress((void**)&pWtH, g_Wt_hi);
    cudaGetSymbolAddress((void**)&pWtL, g_Wt_lo);

    cudaFuncSetAttribute(gemm_mma, cudaFuncAttributeMaxDynamicSharedMemorySize, GSMEM);
    cudaFuncSetAttribute(att_fused_kernel, cudaFuncAttributeMaxDynamicSharedMemorySize, ATT_SMEM);

    // scratch init for the compact-correction machinery
    cudaMemsetAsync(pmap, 0xFF, (size_t)B_ * L_ * sizeof(int));
    cudaMemsetAsync(pcnt, 0, B_ * sizeof(int));
    cudaMemsetAsync(pckK, 0, (size_t)B_ * SLOTS * DM_ * sizeof(float));
    cudaMemsetAsync(pckV, 0, (size_t)B_ * SLOTS * DM_ * sizeof(float));

    // both idx streams in one launch
    {
        unsigned a42, b42, a43, b43;
        tf2x32(0u, 42u, 0u, 1u, &a42, &b42);
        tf2x32(0u, 43u, 0u, 1u, &a43, &b43);
        IdxKeys ik;
        ik.k0[0] = a42; ik.k1[0] = b42; ik.out[0] = pidxA;
        ik.k0[1] = a43; ik.k1[1] = b43; ik.out[1] = pidxB;
        idx2_kernel<<<dim3((L_ * NS_ + 255) / 256, 2), 256>>>(ik);
    }

    // 4 dense-GEMM weights: w0q, w0k, w0v, w1q
    W4 ws;
    ws.w[0] = w0q; ws.w[1] = w0k; ws.w[2] = w0v; ws.w[3] = w1q;
    wt_cvt_all_kernel<<<dim3(16, 16, 4), dim3(32, 32)>>>(ws, pWtH, pWtL);

    // T = Wo0 @ W1{k,v}: split-K partials + combine
    TW tw; tw.b[0] = w1k; tw.b[1] = w1v;
    sgemm_T_part<<<dim3(8, 8, 32), 256>>>(w0o, tw);
    t_combine_kernel<<<(2 * DM_ * DM_ / 4) / 256, 256>>>();

    // split xd and xp in one launch
    const int N4 = BL_ * DM_ / 4;
    {
        Cvt2 c;
        c.src[0] = (const float4*)xd; c.src[1] = (const float4*)xp;
        c.hi[0] = (__nv_bfloat162*)pAxdH; c.hi[1] = (__nv_bfloat162*)pAxpH;
        c.lo[0] = (__nv_bfloat162*)pAxdL; c.lo[1] = (__nv_bfloat162*)pAxpL;
        cvt_pair2_kernel<<<dim3((N4 + 255) / 256, 2), 256>>>(c, N4);
    }

    dim3 ggrid(DM_ / 128, BL_ / 128);   // (4, 128)

    // ---- layer 0: xp2 = attn(xp; xd, xd) ----
    gemm_mma<<<ggrid, 256, GSMEM>>>(pAxpH, pAxpL, pWtH + 0*(size_t)DM_*DM_, pWtL + 0*(size_t)DM_*DM_, b0q, pQ);
    gemm_mma<<<ggrid, 256, GSMEM>>>(pAxdH, pAxdL, pWtH + 1*(size_t)DM_*DM_, pWtL + 1*(size_t)DM_*DM_, b0k, pK);
    gemm_mma<<<ggrid, 256, GSMEM>>>(pAxdH, pAxdL, pWtH + 2*(size_t)DM_*DM_, pWtL + 2*(size_t)DM_*DM_, b0v, pV);
    sample_m_kernel<<<(BH_ * L_) / 8, 256>>>(pidxA);
    topk_kernel<<<BH_, 256>>>();
    meanv1_kernel<<<dim3(BH_, 16), 256>>>();
    meanv2_kernel<<<BH_, 64>>>();
    att_fused_kernel<<<dim3(BH_, NCH), 256, ATT_SMEM>>>();
    att_combine_kernel<<<BH_ * NS_, 64>>>();

    // base0 = meanctx0 @ Wo0 + bo0
    base1g_kernel<<<dim3(B_, 8), 512>>>(pmv, w0o);
    base2g_kernel<<<B_, 512>>>(b0o, pb0);

    // output upper half (xp2): xs + base0 + layer-0 corrections
    bcast_out_kernel<<<(B_ * L_ * 128) / 256, 256>>>(xs, out, pb0, 4096);
    corr_kernel<<<BH_ * NS_, 128>>>(w0o, out, 4096);

    // ---- compact low-rank representation of K1/V1 ----
    mark_kernel<<<1, BH_ * NS_>>>();
    slot_assign_kernel<<<B_, 256>>>();
    corr_compact_kernel<<<dim3(BH_ * NS_, 2), 128>>>();
    {
        KV2 kv;
        kv.w[0] = w1k; kv.w[1] = w1v;
        kv.bias[0] = b1k; kv.bias[1] = b1v;
        basekv1_kernel<<<dim3(B_, 8, 2), 512>>>(pb0, kv);
        basekv2_kernel<<<dim3(B_, 2), 512>>>(kv);
    }

    // layer-1 Q (dense GEMM from xd)
    gemm_mma<<<ggrid, 256, GSMEM>>>(pAxdH, pAxdL, pWtH + 3*(size_t)DM_*DM_, pWtL + 3*(size_t)DM_*DM_, b1q, pQ);

    // ---- layer 1 attention (low-rank K1/V1) ----
    sample_m1_kernel<<<(BH_ * L_) / 8, 256>>>(pidxB);
    topk_kernel<<<BH_, 256>>>();
    meanv1b_kernel<<<BH_, 64>>>();
    att1_fused_kernel<<<BH_ * NS_, 256>>>();

    // base1 = meanctx1 @ W1o + b1o; output lower half (xd2)
    base1g_kernel<<<dim3(B_, 8), 512>>>(pmv, w1o);
    base2g_kernel<<<B_, 512>>>(b1o, pb1);
    bcast_out_kernel<<<(B_ * L_ * 128) / 256, 256>>>(xs, out, pb1, 0);
    corr_kernel<<<BH_ * NS_, 128>>>(w1o, out, 0);
}

// round 10
// speedup vs baseline: 2.5798x; 1.0413x over previous
#include <cuda_runtime.h>
#include <cuda_bf16.h>
#include <math.h>
#include <stdint.h>

#define B_   4
#define H_   8
#define L_   4096
#define D_   64
#define DM_  512
#define NS_  27
#define BH_  (B_*H_)
#define BL_  (B_*L_)
#define NCH  8
#define CH   (L_/NCH)   // 512
#define SLOTS 216

// ---------------- scratch (device globals; no runtime alloc) ----------------
__device__ float g_Q[BH_*L_*D_];
__device__ float g_Q1[BH_*L_*D_];
__device__ float g_K[BH_*L_*D_];
__device__ float g_V[BH_*L_*D_];
__device__ float g_M[BH_*L_];
__device__ float g_outtop[BH_*NS_*D_];
__device__ float g_meanV[BH_*D_];
__device__ float g_vpart[BH_*16*D_];
__device__ float g_attM[BH_*NCH*NS_];
__device__ float g_attS[BH_*NCH*NS_];
__device__ float g_attO[BH_*NCH*NS_*D_];
__device__ float g_base0[B_*DM_];
__device__ float g_base1[B_*DM_];
__device__ float g_basekv[2*B_*DM_];
__device__ float g_basep[B_*8*DM_];
__device__ float g_basep2[2*B_*8*DM_];
__device__ float g_Tkv[2*DM_*DM_];
__device__ float g_ckK[B_*SLOTS*DM_];
__device__ float g_ckV[B_*SLOTS*DM_];
__device__ int   g_map[B_*L_];
__device__ int   g_cnt[B_];
__device__ int   g_idxA[L_*NS_];
__device__ int   g_idxB[L_*NS_];
__device__ int   g_topidx[BH_*NS_];

// bf16-split operand buffers
__device__ __nv_bfloat16 g_Axd_hi[(size_t)BL_*DM_];
__device__ __nv_bfloat16 g_Axd_lo[(size_t)BL_*DM_];
__device__ __nv_bfloat16 g_Axp_hi[(size_t)BL_*DM_];
__device__ __nv_bfloat16 g_Axp_lo[(size_t)BL_*DM_];
__device__ __nv_bfloat16 g_Wt_hi[4*DM_*DM_];   // w0q, w0k, w0v, w1q
__device__ __nv_bfloat16 g_Wt_lo[4*DM_*DM_];

// ---------------- Threefry-2x32 (JAX-exact) ----------------
__host__ __device__ inline void tf2x32(unsigned k0, unsigned k1,
                                       unsigned x0, unsigned x1,
                                       unsigned* o0, unsigned* o1) {
    unsigned ks0 = k0, ks1 = k1, ks2 = 0x1BD11BDAu ^ k0 ^ k1;
    x0 += ks0; x1 += ks1;
#define TF_RND(r) { x0 += x1; x1 = (x1 << (r)) | (x1 >> (32 - (r))); x1 ^= x0; }
    TF_RND(13) TF_RND(15) TF_RND(26) TF_RND(6)   x0 += ks1; x1 += ks2 + 1u;
    TF_RND(17) TF_RND(29) TF_RND(16) TF_RND(24)  x0 += ks2; x1 += ks0 + 2u;
    TF_RND(13) TF_RND(15) TF_RND(26) TF_RND(6)   x0 += ks0; x1 += ks1 + 3u;
    TF_RND(17) TF_RND(29) TF_RND(16) TF_RND(24)  x0 += ks1; x1 += ks2 + 4u;
    TF_RND(13) TF_RND(15) TF_RND(26) TF_RND(6)   x0 += ks2; x1 += ks0 + 5u;
#undef TF_RND
    *o0 = x0; *o1 = x1;
}

struct IdxKeys { unsigned k0[2], k1[2]; int* out[2]; };
__global__ void idx2_kernel(IdxKeys ik) {
    int i = blockIdx.x * blockDim.x + threadIdx.x;
    if (i >= L_*NS_) return;
    int z = blockIdx.y;
    unsigned o0, o1;
    tf2x32(ik.k0[z], ik.k1[z], 0u, (unsigned)i, &o0, &o1);
    ik.out[z][i] = (int)((o0 ^ o1) & 4095u);
}

// ---------------- bf16-split conversion (both inputs in one launch) --------
struct Cvt2 { const float4* src[2]; __nv_bfloat162* hi[2]; __nv_bfloat162* lo[2]; };
__global__ __launch_bounds__(256)
void cvt_pair2_kernel(Cvt2 c, int n4) {
    int i = blockIdx.x * 256 + threadIdx.x;
    if (i >= n4) return;
    int z = blockIdx.y;
    float4 v = c.src[z][i];
    __nv_bfloat16 h0 = __float2bfloat16(v.x), h1 = __float2bfloat16(v.y);
    __nv_bfloat16 h2 = __float2bfloat16(v.z), h3 = __float2bfloat16(v.w);
    __nv_bfloat16 l0 = __float2bfloat16(v.x - __bfloat162float(h0));
    __nv_bfloat16 l1 = __float2bfloat16(v.y - __bfloat162float(h1));
    __nv_bfloat16 l2 = __float2bfloat16(v.z - __bfloat162float(h2));
    __nv_bfloat16 l3 = __float2bfloat16(v.w - __bfloat162float(h3));
    c.hi[z][i*2]   = __nv_bfloat162(h0, h1);
    c.hi[z][i*2+1] = __nv_bfloat162(h2, h3);
    c.lo[z][i*2]   = __nv_bfloat162(l0, l1);
    c.lo[z][i*2+1] = __nv_bfloat162(l2, l3);
}

struct W4 { const float* w[4]; };
__global__ __launch_bounds__(1024)
void wt_cvt_all_kernel(W4 ws, __nv_bfloat16* __restrict__ hi, __nv_bfloat16* __restrict__ lo) {
    __shared__ float t[32][33];
    int tx = threadIdx.x, ty = threadIdx.y;
    int n0 = blockIdx.x * 32, k0 = blockIdx.y * 32;
    int z = blockIdx.z;
    const float* W = ws.w[z];
    size_t off = (size_t)z * DM_ * DM_;
    t[ty][tx] = W[(size_t)(k0 + ty) * DM_ + n0 + tx];
    __syncthreads();
    float v = t[tx][ty];
    int n = n0 + ty, k = k0 + tx;
    __nv_bfloat16 h = __float2bfloat16(v);
    hi[off + (size_t)n * DM_ + k] = h;
    lo[off + (size_t)n * DM_ + k] = __float2bfloat16(v - __bfloat162float(h));
}

// ---------------- PTX helpers ----------------
__device__ __forceinline__ void cp16s(uint32_t saddr, const void* g) {
    asm volatile("cp.async.cg.shared.global [%0], [%1], 16;\n" :: "r"(saddr), "l"(g));
}
#define CP_COMMIT() asm volatile("cp.async.commit_group;\n" ::: "memory")
#define CP_WAIT(n)  asm volatile("cp.async.wait_group %0;\n" :: "n"(n) : "memory")

__device__ __forceinline__ void ldsm4(uint32_t& r0, uint32_t& r1, uint32_t& r2, uint32_t& r3,
                                      uint32_t saddr) {
    asm volatile("ldmatrix.sync.aligned.m8n8.x4.shared.b16 {%0,%1,%2,%3}, [%4];"
                 : "=r"(r0), "=r"(r1), "=r"(r2), "=r"(r3) : "r"(saddr));
}

__device__ __forceinline__ void mma_bf16(float* c, const uint32_t* a, const uint32_t* b) {
    asm volatile("mma.sync.aligned.m16n8k16.row.col.f32.bf16.bf16.f32 "
                 "{%0,%1,%2,%3}, {%4,%5,%6,%7}, {%8,%9}, {%0,%1,%2,%3};"
                 : "+f"(c[0]), "+f"(c[1]), "+f"(c[2]), "+f"(c[3])
                 : "r"(a[0]), "r"(a[1]), "r"(a[2]), "r"(a[3]), "r"(b[0]), "r"(b[1]));
}

// ---------------- mma.sync bf16-split GEMM (4 jobs in one launch) ----------
#define GST    40960
#define NSTG   4
#define GSMEM  (2048 + NSTG*GST)

struct GJob { const __nv_bfloat16 *ahi, *alo, *bhi, *blo; const float* bias; float* c; };
struct G4 { GJob j[4]; };

__global__ __launch_bounds__(256, 1)
void gemm_mma4(G4 g4) {
    extern __shared__ char smem[];
    const uint32_t sb = (uint32_t)__cvta_generic_to_shared(smem);
    const int tid = threadIdx.x;
    const int lane = tid & 31, wid = tid >> 5;
    const int warpM = wid >> 2, warpN = wid & 3;
    const int row0 = blockIdx.y * 128, col0 = blockIdx.x * 128;
    GJob jb = g4.j[blockIdx.z];
    const __nv_bfloat16* __restrict__ Ahi = jb.ahi;
    const __nv_bfloat16* __restrict__ Alo = jb.alo;
    const __nv_bfloat16* __restrict__ Bhi = jb.bhi;
    const __nv_bfloat16* __restrict__ Blo = jb.blo;

    float* sbias = (float*)smem;
    if (tid < 128) sbias[tid] = jb.bias[col0 + tid];

    float acc[4][4][4];
#pragma unroll
    for (int i = 0; i < 4; i++)
#pragma unroll
        for (int j = 0; j < 4; j++)
#pragma unroll
            for (int r = 0; r < 4; r++) acc[i][j][r] = 0.f;

    const int a_row = warpM * 64 + (lane & 15);
    const int a_kb  = ((lane >> 4) * 8) * 2;
    const int b_row = warpN * 32 + (lane & 7) + ((lane >> 4) & 1) * 8;
    const int b_kb  = (((lane >> 3) & 1) * 8) * 2;

#define LOAD_CHUNK(c, s) {                                                     \
    uint32_t stb = sb + 2048 + (uint32_t)(s) * GST;                            \
    int k0 = (c) * 32;                                                         \
    _Pragma("unroll")                                                          \
    for (int j = 0; j < 8; j++) {                                              \
        int idx = tid + j * 256;                                               \
        int tile = idx >> 9, w = idx & 511;                                    \
        int r = w >> 2, cc = w & 3;                                            \
        uint32_t so = stb + (uint32_t)tile * 10240u + (uint32_t)(r * 80 + cc * 16); \
        const __nv_bfloat16* gp;                                               \
        if      (tile == 0) gp = Ahi + (size_t)(row0 + r) * DM_ + k0 + cc * 8; \
        else if (tile == 1) gp = Alo + (size_t)(row0 + r) * DM_ + k0 + cc * 8; \
        else if (tile == 2) gp = Bhi + (size_t)(col0 + r) * DM_ + k0 + cc * 8; \
        else                gp = Blo + (size_t)(col0 + r) * DM_ + k0 + cc * 8; \
        cp16s(so, gp);                                                         \
    }                                                                          \
    CP_COMMIT(); }

#define COMPUTE(s) {                                                                 \
    uint32_t stb = sb + 2048 + (uint32_t)(s) * GST;                                  \
    _Pragma("unroll")                                                                \
    for (int k16 = 0; k16 < 2; k16++) {                                             \
        uint32_t ah[4][4], al[4][4], bh[4][2], bl[4][2];                             \
        _Pragma("unroll")                                                            \
        for (int i = 0; i < 4; i++)                                                  \
            ldsm4(ah[i][0], ah[i][1], ah[i][2], ah[i][3],                            \
                  stb + (uint32_t)((a_row + i*16) * 80 + k16*32 + a_kb));            \
        _Pragma("unroll")                                                            \
        for (int n16 = 0; n16 < 2; n16++)                                            \
            ldsm4(bh[n16*2][0], bh[n16*2][1], bh[n16*2+1][0], bh[n16*2+1][1],        \
                  stb + 20480u + (uint32_t)((b_row + n16*16) * 80 + k16*32 + b_kb)); \
        _Pragma("unroll")                                                            \
        for (int i = 0; i < 4; i++)                                                  \
            _Pragma("unroll")                                                        \
            for (int j = 0; j < 4; j++) mma_bf16(acc[i][j], ah[i], bh[j]);           \
        _Pragma("unroll")                                                            \
        for (int n16 = 0; n16 < 2; n16++)                                            \
            ldsm4(bl[n16*2][0], bl[n16*2][1], bl[n16*2+1][0], bl[n16*2+1][1],        \
                  stb + 30720u + (uint32_t)((b_row + n16*16) * 80 + k16*32 + b_kb)); \
        _Pragma("unroll")                                                            \
        for (int i = 0; i < 4; i++)                                                  \
            _Pragma("unroll")                                                        \
            for (int j = 0; j < 4; j++) mma_bf16(acc[i][j], ah[i], bl[j]);           \
        _Pragma("unroll")                                                            \
        for (int i = 0; i < 4; i++)                                                  \
            ldsm4(al[i][0], al[i][1], al[i][2], al[i][3],                            \
                  stb + 10240u + (uint32_t)((a_row + i*16) * 80 + k16*32 + a_kb));   \
        _Pragma("unroll")                                                            \
        for (int i = 0; i < 4; i++)                                                  \
            _Pragma("unroll")                                                        \
            for (int j = 0; j < 4; j++) mma_bf16(acc[i][j], al[i], bh[j]);           \
    } }

    LOAD_CHUNK(0, 0);
    LOAD_CHUNK(1, 1);
    LOAD_CHUNK(2, 2);

    const int nIter = DM_ / 32;   // 16
#pragma unroll 1
    for (int c = 0; c < nIter; c++) {
        if (c < nIter - 2)      { CP_WAIT(2); }
        else if (c == nIter - 2){ CP_WAIT(1); }
        else                    { CP_WAIT(0); }
        __syncthreads();
        if (c + 3 < nIter) LOAD_CHUNK(c + 3, (c + 3) & 3);
        COMPUTE(c & 3);
    }

    __syncthreads();
#pragma unroll
    for (int i = 0; i < 4; i++) {
#pragma unroll
        for (int j = 0; j < 4; j++) {
            int colg = col0 + warpN * 32 + j * 8 + (lane & 3) * 2;
            int hh = colg >> 6, d0 = colg & 63;
            float b0v = sbias[colg - col0], b1v = sbias[colg - col0 + 1];
#pragma unroll
            for (int half = 0; half < 2; half++) {
                int m = row0 + warpM * 64 + i * 16 + (lane >> 2) + half * 8;
                int b = m >> 12, l = m & 4095;
                float2 v;
                v.x = acc[i][j][half*2 + 0] + b0v;
                v.y = acc[i][j][half*2 + 1] + b1v;
                *(float2*)(jb.c + (((size_t)(b * H_ + hh) * L_) + l) * D_ + d0) = v;
            }
        }
    }
#undef LOAD_CHUNK
#undef COMPUTE
}

// ------- T GEMMs: split-K, atomic accumulate directly into g_Tkv -------
struct TW { const float* b[2]; };
__global__ __launch_bounds__(256)
void sgemm_T_part(const float* __restrict__ A, TW tw) {
    __shared__ float As[16][68];
    __shared__ float Bs[16][64];
    int tid = threadIdx.x, tx = tid & 15, ty = tid >> 4;
    int r0 = blockIdx.y * 64, c0 = blockIdx.x * 64;
    int kc = blockIdx.z & 15, which = blockIdx.z >> 4;
    const float* Bm = tw.b[which];
    float acc[4][4];
#pragma unroll
    for (int i = 0; i < 4; i++)
#pragma unroll
        for (int j = 0; j < 4; j++) acc[i][j] = 0.f;

    for (int kt = kc * 32; kt < kc * 32 + 32; kt += 16) {
        int m = tid >> 2, k4 = tid & 3;
        float4 av = *(const float4*)(A + (size_t)(r0 + m) * DM_ + kt + k4 * 4);
        As[k4*4+0][m] = av.x; As[k4*4+1][m] = av.y;
        As[k4*4+2][m] = av.z; As[k4*4+3][m] = av.w;
        int kk = tid >> 4, n4 = tid & 15;
        *(float4*)&Bs[kk][n4 * 4] = *(const float4*)(Bm + (size_t)(kt + kk) * DM_ + c0 + n4 * 4);
        __syncthreads();
#pragma unroll
        for (int k = 0; k < 16; k++) {
            float a[4], b[4];
            *(float4*)a = *(const float4*)&As[k][ty * 4];
            *(float4*)b = *(const float4*)&Bs[k][tx * 4];
#pragma unroll
            for (int i = 0; i < 4; i++)
#pragma unroll
                for (int j = 0; j < 4; j++) acc[i][j] += a[i] * b[j];
        }
        __syncthreads();
    }
    float* dst = g_Tkv + (size_t)which * DM_ * DM_ + (size_t)(r0 + ty * 4) * DM_ + c0 + tx * 4;
#pragma unroll
    for (int i = 0; i < 4; i++) {
        atomicAdd(dst + (size_t)i * DM_ + 0, acc[i][0]);
        atomicAdd(dst + (size_t)i * DM_ + 1, acc[i][1]);
        atomicAdd(dst + (size_t)i * DM_ + 2, acc[i][2]);
        atomicAdd(dst + (size_t)i * DM_ + 3, acc[i][3]);
    }
}

// ---------------- layer-0 sample_m (dense K) ----------------
__global__ __launch_bounds__(256)
void sample_m_kernel(const int* __restrict__ idx) {
    int gw = (blockIdx.x * blockDim.x + threadIdx.x) >> 5;
    int lane = threadIdx.x & 31;
    if (gw >= BH_ * L_) return;
    int bh = gw >> 12, l = gw & 4095;
    const float4* qrow = (const float4*)(g_Q + ((size_t)bh * L_ + l) * D_);
    float val = 0.f;
    bool active = lane < NS_;
    if (active) {
        int kk = idx[l * NS_ + lane];
        const float4* krow = (const float4*)(g_K + ((size_t)bh * L_ + kk) * D_);
        float s = 0.f;
#pragma unroll
        for (int d4 = 0; d4 < 16; d4++) {
            float4 q = qrow[d4], k = krow[d4];
            s += q.x*k.x + q.y*k.y + q.z*k.z + q.w*k.w;
        }
        val = s;
    }
    float mx = active ? val : -__int_as_float(0x7f800000);
    float sm = active ? val : 0.f;
#pragma unroll
    for (int off = 16; off > 0; off >>= 1) {
        mx = fmaxf(mx, __shfl_down_sync(0xffffffffu, mx, off));
        sm += __shfl_down_sync(0xffffffffu, sm, off);
    }
    if (lane == 0) g_M[gw] = mx - sm * (1.f / (float)L_);
}

// ---------------- layer-1 sample_m (low-rank K1, Q from g_Q1) --------------
__global__ __launch_bounds__(256)
void sample_m1_kernel(const int* __restrict__ idx) {
    int gw = (blockIdx.x * blockDim.x + threadIdx.x) >> 5;
    int lane = threadIdx.x & 31;
    if (gw >= BH_ * L_) return;
    int bh = gw >> 12, l = gw & 4095;
    int b = bh >> 3, h = bh & 7;
    const float4* qrow = (const float4*)(g_Q1 + ((size_t)bh * L_ + l) * D_);
    const float4* brow = (const float4*)(g_basekv + (size_t)b * DM_ + h * D_);
    bool active = lane < NS_;
    int j = -1;
    if (active) {
        int kk = idx[l * NS_ + lane];
        j = g_map[b * L_ + kk];
    }
    float s = 0.f;
#pragma unroll
    for (int d4 = 0; d4 < 16; d4++) {
        float4 q = qrow[d4], bb = brow[d4];
        s += q.x*bb.x + q.y*bb.y + q.z*bb.z + q.w*bb.w;
    }
    if (j >= 0) {
        const float4* crow = (const float4*)(g_ckK + ((size_t)(b * SLOTS + j)) * DM_ + h * D_);
#pragma unroll
        for (int d4 = 0; d4 < 16; d4++) {
            float4 q = qrow[d4], c = crow[d4];
            s += q.x*c.x + q.y*c.y + q.z*c.z + q.w*c.w;
        }
    }
    float val = s;
    float mx = active ? val : -__int_as_float(0x7f800000);
    float sm = active ? val : 0.f;
#pragma unroll
    for (int off = 16; off > 0; off >>= 1) {
        mx = fmaxf(mx, __shfl_down_sync(0xffffffffu, mx, off));
        sm += __shfl_down_sync(0xffffffffu, sm, off);
    }
    if (lane == 0) g_M[gw] = mx - sm * (1.f / (float)L_);
}

// ---------------- top-27 via packed-key shfl reduce ----------------
__device__ __forceinline__ unsigned ordf(float v) {
    unsigned u = __float_as_uint(v);
    return (u & 0x80000000u) ? ~u : (u | 0x80000000u);
}

__global__ __launch_bounds__(256)
void topk_kernel() {
    int bh = blockIdx.x, t = threadIdx.x;
    int lane = t & 31, wid = t >> 5;
    __shared__ float sm[L_];
    __shared__ unsigned long long wred[8];
    for (int i = t; i < L_; i += 256) sm[i] = g_M[(size_t)bh * L_ + i];
    __syncthreads();
    for (int it = 0; it < NS_; it++) {
        unsigned long long best = 0ull;
#pragma unroll
        for (int jj = 0; jj < L_ / 256; jj++) {
            int i = t + jj * 256;
            unsigned long long key = ((unsigned long long)ordf(sm[i]) << 32)
                                   | (unsigned)(L_ - 1 - i);
            if (key > best) best = key;
        }
#pragma unroll
        for (int off = 16; off > 0; off >>= 1) {
            unsigned long long o = __shfl_down_sync(0xffffffffu, best, off);
            if (o > best) best = o;
        }
        if (lane == 0) wred[wid] = best;
        __syncthreads();
        if (t == 0) {
            unsigned long long b2 = wred[0];
#pragma unroll
            for (int w = 1; w < 8; w++) if (wred[w] > b2) b2 = wred[w];
            int idx = L_ - 1 - (int)(b2 & 0xFFFFFFFFull);
            g_topidx[bh * NS_ + it] = idx;
            sm[idx] = -__int_as_float(0x7f800000);
        }
        __syncthreads();
    }
}

// ---------------- layer-0 meanV: two-stage ----------------
__global__ __launch_bounds__(256)
void meanv1_kernel() {
    int bh = blockIdx.x, c = blockIdx.y, t = threadIdx.x;
    int d = t & 63, r = t >> 6;
    float s = 0.f;
    int base = c * 256;
    for (int l = base + r; l < base + 256; l += 4)
        s += g_V[((size_t)bh * L_ + l) * D_ + d];
    __shared__ float red[256];
    red[t] = s; __syncthreads();
    if (t < 64)
        g_vpart[(bh * 16 + c) * D_ + d] = red[d] + red[64+d] + red[128+d] + red[192+d];
}

__global__ __launch_bounds__(64)
void meanv2_kernel() {
    int bh = blockIdx.x, d = threadIdx.x;
    float s = 0.f;
#pragma unroll
    for (int c = 0; c < 16; c++) s += g_vpart[(bh * 16 + c) * D_ + d];
    g_meanV[bh * D_ + d] = s * (1.f / (float)L_);
}

// ---------------- layer-1 meanV (low-rank) ----------------
__global__ __launch_bounds__(64)
void meanv1b_kernel() {
    int bh = blockIdx.x, t = threadIdx.x;
    int b = bh >> 3, h = bh & 7;
    int cnt = g_cnt[b];
    float s = 0.f;
    for (int j = 0; j < cnt; j++)
        s += g_ckV[((size_t)(b * SLOTS + j)) * DM_ + h * D_ + t];
    g_meanV[bh * D_ + t] = g_basekv[(size_t)(B_ + b) * DM_ + h * D_ + t] + s * (1.f / (float)L_);
}

// ---------------- layer-0 fused scores+softmax+pv ----------------
#define ATT_SMEM ((NS_*CH + 64*129 + NS_*64 + 64) * 4)
__global__ __launch_bounds__(256, 2)
void att_fused_kernel() {
    extern __shared__ float smf[];
    float* sS   = smf;
    float* KsT  = smf + NS_ * CH;
    float* sQ   = KsT + 64 * 129;

    int bh = blockIdx.x, ch = blockIdx.y, t = threadIdx.x;
    int lane = t & 31, w = t >> 5;
    int l0 = ch * CH;

    for (int f = t; f < NS_ * 16; f += 256) {
        int u = f >> 4, d4 = f & 15;
        int l = g_topidx[bh * NS_ + u];
        *(float4*)&sQ[u * 64 + d4 * 4] =
            *(const float4*)(g_Q + ((size_t)bh * L_ + l) * D_ + d4 * 4);
    }

    const int ubeg = (t >> 7) ? 14 : 0;
    const int ucnt = (t >> 7) ? 13 : 14;
    const int kk = t & 127;
#pragma unroll 1
    for (int st = 0; st < CH / 128; st++) {
        __syncthreads();
        for (int f = t; f < 128 * 16; f += 256) {
            int kr = f >> 4, d4 = f & 15;
            float4 v = *(const float4*)(g_K + ((size_t)bh * L_ + l0 + st * 128 + kr) * D_ + d4 * 4);
            KsT[(d4*4+0) * 129 + kr] = v.x; KsT[(d4*4+1) * 129 + kr] = v.y;
            KsT[(d4*4+2) * 129 + kr] = v.z; KsT[(d4*4+3) * 129 + kr] = v.w;
        }
        __syncthreads();
        float acc[14];
#pragma unroll
        for (int i = 0; i < 14; i++) acc[i] = 0.f;
#pragma unroll
        for (int d0 = 0; d0 < 64; d0 += 4) {
            float k0 = KsT[d0*129 + kk], k1 = KsT[(d0+1)*129 + kk];
            float k2 = KsT[(d0+2)*129 + kk], k3 = KsT[(d0+3)*129 + kk];
#pragma unroll
            for (int i = 0; i < 14; i++) {
                if (i < ucnt) {
                    float4 q = *(const float4*)&sQ[(ubeg + i) * 64 + d0];
                    acc[i] += q.x*k0 + q.y*k1 + q.z*k2 + q.w*k3;
                }
            }
        }
#pragma unroll
        for (int i = 0; i < 14; i++)
            if (i < ucnt) sS[(ubeg + i) * CH + st * 128 + kk] = acc[i] * 0.125f;
    }
    __syncthreads();

    for (int u = w; u < NS_; u += 8) {
        float mx = -__int_as_float(0x7f800000);
#pragma unroll
        for (int j = 0; j < CH / 32; j++)
            mx = fmaxf(mx, sS[u * CH + lane + j * 32]);
#pragma unroll
        for (int off = 16; off > 0; off >>= 1)
            mx = fmaxf(mx, __shfl_xor_sync(0xffffffffu, mx, off));
        float ss = 0.f;
#pragma unroll
        for (int j = 0; j < CH / 32; j++) {
            float e = __expf(sS[u * CH + lane + j * 32] - mx);
            sS[u * CH + lane + j * 32] = e;
            ss += e;
        }
#pragma unroll
        for (int off = 16; off > 0; off >>= 1)
            ss += __shfl_xor_sync(0xffffffffu, ss, off);
        if (lane == 0) {
            int pi = (bh * NCH + ch) * NS_ + u;
            g_attM[pi] = mx;
            g_attS[pi] = ss;
        }
    }
    __syncthreads();

    int d = t & 63, ug = t >> 6;
    float acc[7];
#pragma unroll
    for (int j = 0; j < 7; j++) acc[j] = 0.f;
    for (int k = 0; k < CH; k += 4) {
        float v0 = g_V[((size_t)bh * L_ + l0 + k + 0) * D_ + d];
        float v1 = g_V[((size_t)bh * L_ + l0 + k + 1) * D_ + d];
        float v2 = g_V[((size_t)bh * L_ + l0 + k + 2) * D_ + d];
        float v3 = g_V[((size_t)bh * L_ + l0 + k + 3) * D_ + d];
#pragma unroll
        for (int j = 0; j < 7; j++) {
            int u = ug + j * 4;
            if (u < NS_) {
                float4 p = *(const float4*)&sS[u * CH + k];
                acc[j] += p.x*v0 + p.y*v1 + p.z*v2 + p.w*v3;
            }
        }
    }
#pragma unroll
    for (int j = 0; j < 7; j++) {
        int u = ug + j * 4;
        if (u < NS_)
            g_attO[((size_t)(bh * NCH + ch) * NS_ + u) * D_ + d] = acc[j];
    }
}

__global__ __launch_bounds__(64)
void att_combine_kernel() {
    int bu = blockIdx.x;
    int bh = bu / NS_, u = bu % NS_;
    int d = threadIdx.x;
    float m = -__int_as_float(0x7f800000);
#pragma unroll
    for (int c = 0; c < NCH; c++)
        m = fmaxf(m, g_attM[(bh * NCH + c) * NS_ + u]);
    float s = 0.f, o = 0.f;
#pragma unroll
    for (int c = 0; c < NCH; c++) {
        int pi = (bh * NCH + c) * NS_ + u;
        float wgt = __expf(g_attM[pi] - m);
        s += wgt * g_attS[pi];
        o += wgt * g_attO[(size_t)pi * D_ + d];
    }
    g_outtop[(bh * NS_ + u) * D_ + d] = o / s;
}

// ---------------- layer-1 attention over low-rank K1/V1 (Q from g_Q1) ------
__global__ __launch_bounds__(256)
void att1_fused_kernel() {
    __shared__ float sQ[64];
    __shared__ float sS[SLOTS];
    __shared__ float red[256];
    __shared__ float sstat[2];
    int bu = blockIdx.x;
    int bh = bu / NS_, u = bu % NS_;
    int b = bh >> 3, h = bh & 7;
    int t = threadIdx.x;
    int cnt = g_cnt[b];
    int lsel = g_topidx[bh * NS_ + u];
    if (t < 64) sQ[t] = g_Q1[((size_t)bh * L_ + lsel) * D_ + t];
    __syncthreads();

    if (t < 32) {
        float p = sQ[t] * g_basekv[(size_t)b * DM_ + h * D_ + t]
                + sQ[t + 32] * g_basekv[(size_t)b * DM_ + h * D_ + t + 32];
#pragma unroll
        for (int off = 16; off > 0; off >>= 1)
            p += __shfl_xor_sync(0xffffffffu, p, off);
        if (t == 0) sstat[0] = 0.125f * p;
    }
    __syncthreads();
    float qb = sstat[0];

    float sj = -__int_as_float(0x7f800000);
    if (t < cnt) {
        const float4* c = (const float4*)(g_ckK + ((size_t)(b * SLOTS + t)) * DM_ + h * D_);
        float dot = 0.f;
#pragma unroll
        for (int d4 = 0; d4 < 16; d4++) {
            float4 cv = c[d4];
            dot += sQ[d4*4]*cv.x + sQ[d4*4+1]*cv.y + sQ[d4*4+2]*cv.z + sQ[d4*4+3]*cv.w;
        }
        sj = qb + 0.125f * dot;
        sS[t] = sj;
    }
    red[t] = sj;
    __syncthreads();
    for (int s = 128; s > 0; s >>= 1) {
        if (t < s) red[t] = fmaxf(red[t], red[t + s]);
        __syncthreads();
    }
    float m = fmaxf(red[0], qb);
    __syncthreads();

    float e = 0.f;
    if (t < cnt) { e = __expf(sS[t] - m); sS[t] = e; }
    red[t] = e;
    __syncthreads();
    for (int s = 128; s > 0; s >>= 1) {
        if (t < s) red[t] += red[t + s];
        __syncthreads();
    }
    if (t == 0)
        sstat[1] = 1.f / (red[0] + (float)(L_ - cnt) * __expf(qb - m));
    __syncthreads();
    float inv = sstat[1];

    if (t < 64) {
        float o = 0.f;
        for (int j = 0; j < cnt; j++)
            o += sS[j] * g_ckV[((size_t)(b * SLOTS + j)) * DM_ + h * D_ + t];
        o = o * inv + g_basekv[(size_t)(B_ + b) * DM_ + h * D_ + t];
        g_outtop[(bh * NS_ + u) * D_ + t] = o;
    }
}

// ---------------- map build ----------------
__global__ void mark_kernel() {
    int i = threadIdx.x;
    if (i < BH_ * NS_) {
        int bh = i / NS_;
        int b = bh >> 3;
        g_map[b * L_ + g_topidx[i]] = 1;
    }
}

__global__ __launch_bounds__(256)
void slot_assign_kernel() {
    int b = blockIdx.x, t = threadIdx.x;
    __shared__ int cs[256];
    int base = t * 16;
    int c = 0;
#pragma unroll
    for (int i = 0; i < 16; i++)
        if (g_map[b * L_ + base + i] == 1) c++;
    cs[t] = c;
    __syncthreads();
    for (int off = 1; off < 256; off <<= 1) {
        int v = (t >= off) ? cs[t - off] : 0;
        __syncthreads();
        cs[t] += v;
        __syncthreads();
    }
    int slot = cs[t] - c;
#pragma unroll
    for (int i = 0; i < 16; i++) {
        if (g_map[b * L_ + base + i] == 1)
            g_map[b * L_ + base + i] = slot++;
    }
    if (t == 255) g_cnt[b] = cs[255];
}

__global__ __launch_bounds__(128)
void corr_compact_kernel() {
    int blk = blockIdx.x, z = blockIdx.y;
    int bh0 = blk / NS_, u = blk % NS_;
    int b = bh0 >> 3, h0 = bh0 & 7;
    int t = threadIdx.x;
    __shared__ float qv[64];
    if (t < 64) qv[t] = g_outtop[(bh0 * NS_ + u) * 64 + t] - g_meanV[bh0 * 64 + t];
    __syncthreads();
    const float* T = g_Tkv + (size_t)z * DM_ * DM_;
    int l = g_topidx[bh0 * NS_ + u];
    int slot = g_map[b * L_ + l];
    float a0 = 0.f, a1 = 0.f, a2 = 0.f, a3 = 0.f;
#pragma unroll 8
    for (int k = 0; k < 64; k++) {
        float q = qv[k];
        float4 wv = *(const float4*)(T + (size_t)(h0 * 64 + k) * DM_ + t * 4);
        a0 += q * wv.x; a1 += q * wv.y; a2 += q * wv.z; a3 += q * wv.w;
    }
    float* dst = (z ? g_ckV : g_ckK) + ((size_t)(b * SLOTS + slot)) * DM_ + t * 4;
    atomicAdd(dst + 0, a0); atomicAdd(dst + 1, a1);
    atomicAdd(dst + 2, a2); atomicAdd(dst + 3, a3);
}

// ---------------- generic GEMV: partials then combine ----------------
__global__ __launch_bounds__(512)
void base1g_kernel(const float* __restrict__ invec, const float* __restrict__ w) {
    int b = blockIdx.x, kc = blockIdx.y, n = threadIdx.x;
    __shared__ float mc[64];
    if (n < 64) mc[n] = invec[b * DM_ + kc * 64 + n];
    __syncthreads();
    float s = 0.f;
#pragma unroll 8
    for (int k = 0; k < 64; k++) s += mc[k] * w[(size_t)(kc * 64 + k) * DM_ + n];
    g_basep[(b * 8 + kc) * DM_ + n] = s;
}

__global__ __launch_bounds__(512)
void base2g_kernel(const float* __restrict__ bias, float* __restrict__ outv) {
    int b = blockIdx.x, n = threadIdx.x;
    float s = bias[n];
#pragma unroll
    for (int p = 0; p < 8; p++) s += g_basep[(b * 8 + p) * DM_ + n];
    outv[b * DM_ + n] = s;
}

struct KV2 { const float* w[2]; const float* bias[2]; };
__global__ __launch_bounds__(512)
void basekv1_kernel(const float* __restrict__ invec, KV2 kv) {
    int b = blockIdx.x, kc = blockIdx.y, z = blockIdx.z, n = threadIdx.x;
    __shared__ float mc[64];
    if (n < 64) mc[n] = invec[b * DM_ + kc * 64 + n];
    __syncthreads();
    const float* w = kv.w[z];
    float s = 0.f;
#pragma unroll 8
    for (int k = 0; k < 64; k++) s += mc[k] * w[(size_t)(kc * 64 + k) * DM_ + n];
    g_basep2[((z * B_ + b) * 8 + kc) * DM_ + n] = s;
}

__global__ __launch_bounds__(512)
void basekv2_kernel(KV2 kv) {
    int b = blockIdx.x, z = blockIdx.y, n = threadIdx.x;
    float s = kv.bias[z][n];
#pragma unroll
    for (int p = 0; p < 8; p++) s += g_basep2[((z * B_ + b) * 8 + p) * DM_ + n];
    g_basekv[(z * B_ + b) * DM_ + n] = s;
}

// ---------------- output broadcasts ----------------
__global__ __launch_bounds__(256)
void bcast_out_kernel(const float* __restrict__ xs, float* __restrict__ out,
                      const float* __restrict__ basev, int row_off) {
    int i4 = blockIdx.x * 256 + threadIdx.x;
    int n4 = i4 & 127;
    int l = (i4 >> 7) & 4095;
    int b = i4 / (L_ * 128);
    size_t oi = ((size_t)(b * 8192 + row_off + l)) * 128 + n4;
    float4 a = ((const float4*)xs)[oi];
    float4 s = ((const float4*)basev)[b * 128 + n4];
    a.x += s.x; a.y += s.y; a.z += s.z; a.w += s.w;
    ((float4*)out)[oi] = a;
}

__global__ __launch_bounds__(128)
void corr_kernel(const float* __restrict__ wo, float* __restrict__ dst, int row_off) {
    int blk = blockIdx.x;
    int bh = blk / NS_, u = blk % NS_;
    int b = bh >> 3, h = bh & 7;
    int t = threadIdx.x;
    __shared__ float qv[64];
    if (t < 64) qv[t] = g_outtop[(bh * NS_ + u) * 64 + t] - g_meanV[bh * 64 + t];
    __syncthreads();
    int l = g_topidx[bh * NS_ + u];
    float a0 = 0.f, a1 = 0.f, a2 = 0.f, a3 = 0.f;
#pragma unroll 8
    for (int k = 0; k < 64; k++) {
        float q = qv[k];
        float4 wv = *(const float4*)(wo + (size_t)(h * 64 + k) * DM_ + t * 4);
        a0 += q * wv.x; a1 += q * wv.y; a2 += q * wv.z; a3 += q * wv.w;
    }
    float* d = dst + ((size_t)(b * 8192 + row_off + l)) * DM_ + t * 4;
    atomicAdd(d + 0, a0); atomicAdd(d + 1, a1);
    atomicAdd(d + 2, a2); atomicAdd(d + 3, a3);
}

// ---------------- host orchestration ----------------
extern "C" void kernel_launch(void* const* d_in, const int* in_sizes, int n_in,
                              void* d_out, int out_size) {
    const float* xs  = (const float*)d_in[0];
    const float* xd  = (const float*)d_in[1];
    const float* xp  = (const float*)d_in[2];
    const float* w0q = (const float*)d_in[3];
    const float* w0k = (const float*)d_in[4];
    const float* w0v = (const float*)d_in[5];
    const float* w0o = (const float*)d_in[6];
    const float* b0q = (const float*)d_in[7];
    const float* b0k = (const float*)d_in[8];
    const float* b0v = (const float*)d_in[9];
    const float* b0o = (const float*)d_in[10];
    const float* w1q = (const float*)d_in[11];
    const float* w1k = (const float*)d_in[12];
    const float* w1v = (const float*)d_in[13];
    const float* w1o = (const float*)d_in[14];
    const float* b1q = (const float*)d_in[15];
    const float* b1k = (const float*)d_in[16];
    const float* b1v = (const float*)d_in[17];
    const float* b1o = (const float*)d_in[18];
    float* out = (float*)d_out;

    float *pQ, *pQ1, *pK, *pV, *pmv, *pb0, *pb1, *pckK, *pckV, *pTkv;
    int *pidxA, *pidxB, *pmap, *pcnt;
    __nv_bfloat16 *pAxdH, *pAxdL, *pAxpH, *pAxpL, *pWtH, *pWtL;
    cudaGetSymbolAddress((void**)&pQ, g_Q);
    cudaGetSymbolAddress((void**)&pQ1, g_Q1);
    cudaGetSymbolAddress((void**)&pK, g_K);
    cudaGetSymbolAddress((void**)&pV, g_V);
    cudaGetSymbolAddress((void**)&pmv, g_meanV);
    cudaGetSymbolAddress((void**)&pb0, g_base0);
    cudaGetSymbolAddress((void**)&pb1, g_base1);
    cudaGetSymbolAddress((void**)&pckK, g_ckK);
    cudaGetSymbolAddress((void**)&pckV, g_ckV);
    cudaGetSymbolAddress((void**)&pTkv, g_Tkv);
    cudaGetSymbolAddress((void**)&pmap, g_map);
    cudaGetSymbolAddress((void**)&pcnt, g_cnt);
    cudaGetSymbolAddress((void**)&pidxA, g_idxA);
    cudaGetSymbolAddress((void**)&pidxB, g_idxB);
    cudaGetSymbolAddress((void**)&pAxdH, g_Axd_hi);
    cudaGetSymbolAddress((void**)&pAxdL, g_Axd_lo);
    cudaGetSymbolAddress((void**)&pAxpH, g_Axp_hi);
    cudaGetSymbolAddress((void**)&pAxpL, g_Axp_lo);
    cudaGetSymbolAddress((void**)&pWtH, g_Wt_hi);
    cudaGetSymbolAddress((void**)&pWtL, g_Wt_lo);

    cudaFuncSetAttribute(gemm_mma4, cudaFuncAttributeMaxDynamicSharedMemorySize, GSMEM);
    cudaFuncSetAttribute(att_fused_kernel, cudaFuncAttributeMaxDynamicSharedMemorySize, ATT_SMEM);

    // scratch init
    cudaMemsetAsync(pmap, 0xFF, (size_t)B_ * L_ * sizeof(int));
    cudaMemsetAsync(pcnt, 0, B_ * sizeof(int));
    cudaMemsetAsync(pckK, 0, (size_t)B_ * SLOTS * DM_ * sizeof(float));
    cudaMemsetAsync(pckV, 0, (size_t)B_ * SLOTS * DM_ * sizeof(float));
    cudaMemsetAsync(pTkv, 0, (size_t)2 * DM_ * DM_ * sizeof(float));

    {
        unsigned a42, b42, a43, b43;
        tf2x32(0u, 42u, 0u, 1u, &a42, &b42);
        tf2x32(0u, 43u, 0u, 1u, &a43, &b43);
        IdxKeys ik;
        ik.k0[0] = a42; ik.k1[0] = b42; ik.out[0] = pidxA;
        ik.k0[1] = a43; ik.k1[1] = b43; ik.out[1] = pidxB;
        idx2_kernel<<<dim3((L_ * NS_ + 255) / 256, 2), 256>>>(ik);
    }

    W4 ws;
    ws.w[0] = w0q; ws.w[1] = w0k; ws.w[2] = w0v; ws.w[3] = w1q;
    wt_cvt_all_kernel<<<dim3(16, 16, 4), dim3(32, 32)>>>(ws, pWtH, pWtL);

    // T = Wo0 @ W1{k,v}: split-K with direct atomic accumulation
    TW tw; tw.b[0] = w1k; tw.b[1] = w1v;
    sgemm_T_part<<<dim3(8, 8, 32), 256>>>(w0o, tw);

    const int N4 = BL_ * DM_ / 4;
    {
        Cvt2 c;
        c.src[0] = (const float4*)xd; c.src[1] = (const float4*)xp;
        c.hi[0] = (__nv_bfloat162*)pAxdH; c.hi[1] = (__nv_bfloat162*)pAxpH;
        c.lo[0] = (__nv_bfloat162*)pAxdL; c.lo[1] = (__nv_bfloat162*)pAxpL;
        cvt_pair2_kernel<<<dim3((N4 + 255) / 256, 2), 256>>>(c, N4);
    }

    // ---- ALL 4 dense GEMMs in one launch (Q0, K0, V0, Q1) ----
    {
        G4 g4;
        size_t WS = (size_t)DM_ * DM_;
        g4.j[0].ahi = pAxpH; g4.j[0].alo = pAxpL; g4.j[0].bhi = pWtH + 0*WS; g4.j[0].blo = pWtL + 0*WS; g4.j[0].bias = b0q; g4.j[0].c = pQ;
        g4.j[1].ahi = pAxdH; g4.j[1].alo = pAxdL; g4.j[1].bhi = pWtH + 1*WS; g4.j[1].blo = pWtL + 1*WS; g4.j[1].bias = b0k; g4.j[1].c = pK;
        g4.j[2].ahi = pAxdH; g4.j[2].alo = pAxdL; g4.j[2].bhi = pWtH + 2*WS; g4.j[2].blo = pWtL + 2*WS; g4.j[2].bias = b0v; g4.j[2].c = pV;
        g4.j[3].ahi = pAxdH; g4.j[3].alo = pAxdL; g4.j[3].bhi = pWtH + 3*WS; g4.j[3].blo = pWtL + 3*WS; g4.j[3].bias = b1q; g4.j[3].c = pQ1;
        gemm_mma4<<<dim3(DM_ / 128, BL_ / 128, 4), 256, GSMEM>>>(g4);
    }

    // ---- layer 0 attention ----
    sample_m_kernel<<<(BH_ * L_) / 8, 256>>>(pidxA);
    topk_kernel<<<BH_, 256>>>();
    meanv1_kernel<<<dim3(BH_, 16), 256>>>();
    meanv2_kernel<<<BH_, 64>>>();
    att_fused_kernel<<<dim3(BH_, NCH), 256, ATT_SMEM>>>();
    att_combine_kernel<<<BH_ * NS_, 64>>>();

    // base0 = meanctx0 @ Wo0 + bo0
    base1g_kernel<<<dim3(B_, 8), 512>>>(pmv, w0o);
    base2g_kernel<<<B_, 512>>>(b0o, pb0);

    // output upper half (xp2)
    bcast_out_kernel<<<(B_ * L_ * 128) / 256, 256>>>(xs, out, pb0, 4096);
    corr_kernel<<<BH_ * NS_, 128>>>(w0o, out, 4096);

    // ---- compact low-rank K1/V1 ----
    mark_kernel<<<1, BH_ * NS_>>>();
    slot_assign_kernel<<<B_, 256>>>();
    corr_compact_kernel<<<dim3(BH_ * NS_, 2), 128>>>();
    {
        KV2 kv;
        kv.w[0] = w1k; kv.w[1] = w1v;
        kv.bias[0] = b1k; kv.bias[1] = b1v;
        basekv1_kernel<<<dim3(B_, 8, 2), 512>>>(pb0, kv);
        basekv2_kernel<<<dim3(B_, 2), 512>>>(kv);
    }

    // ---- layer 1 attention (low-rank K1/V1, Q from g_Q1) ----
    sample_m1_kernel<<<(BH_ * L_) / 8, 256>>>(pidxB);
    topk_kernel<<<BH_, 256>>>();
    meanv1b_kernel<<<BH_, 64>>>();
    att1_fused_kernel<<<BH_ * NS_, 256>>>();

    // base1 + output lower half (xd2)
    base1g_kernel<<<dim3(B_, 8), 512>>>(pmv, w1o);
    base2g_kernel<<<B_, 512>>>(b1o, pb1);
    bcast_out_kernel<<<(B_ * L_ * 128) / 256, 256>>>(xs, out, pb1, 0);
    corr_kernel<<<BH_ * NS_, 128>>>(w1o, out, 0);
}

// round 11
// speedup vs baseline: 2.7402x; 1.0622x over previous
#include <cuda_runtime.h>
#include <cuda_bf16.h>
#include <math.h>
#include <stdint.h>

#define B_   4
#define H_   8
#define L_   4096
#define D_   64
#define DM_  512
#define NS_  27
#define BH_  (B_*H_)
#define BL_  (B_*L_)
#define NCH  8
#define CH   (L_/NCH)   // 512
#define SLOTS 216

// ---------------- scratch (device globals; no runtime alloc) ----------------
__device__ float g_Q[BH_*L_*D_];
__device__ float g_Q1[BH_*L_*D_];
__device__ float g_K[BH_*L_*D_];
__device__ float g_V[BH_*L_*D_];
__device__ float g_M[BH_*L_];
__device__ float g_outtop[BH_*NS_*D_];
__device__ float g_meanV[BH_*D_];
__device__ float g_vpart[BH_*16*D_];
__device__ float g_attM[BH_*NCH*NS_];
__device__ float g_attS[BH_*NCH*NS_];
__device__ float g_attO[BH_*NCH*NS_*D_];
__device__ float g_base0[B_*DM_];
__device__ float g_base1[B_*DM_];
__device__ float g_basekv[2*B_*DM_];
__device__ float g_basep[B_*8*DM_];
__device__ float g_basep2[2*B_*8*DM_];
__device__ float g_Tkv[2*DM_*DM_];
__device__ float g_ckK[B_*SLOTS*DM_];
__device__ float g_ckV[B_*SLOTS*DM_];
__device__ int   g_map[B_*L_];
__device__ int   g_cnt[B_];
__device__ int   g_idxA[L_*NS_];
__device__ int   g_idxB[L_*NS_];
__device__ int   g_topidx[BH_*NS_];

// bf16-split operand buffers
__device__ __nv_bfloat16 g_Axd_hi[(size_t)BL_*DM_];
__device__ __nv_bfloat16 g_Axd_lo[(size_t)BL_*DM_];
__device__ __nv_bfloat16 g_Axp_hi[(size_t)BL_*DM_];
__device__ __nv_bfloat16 g_Axp_lo[(size_t)BL_*DM_];
__device__ __nv_bfloat16 g_Wt_hi[4*DM_*DM_];   // w0q, w0k, w0v, w1q
__device__ __nv_bfloat16 g_Wt_lo[4*DM_*DM_];

// ---------------- Threefry-2x32 (JAX-exact) ----------------
__host__ __device__ inline void tf2x32(unsigned k0, unsigned k1,
                                       unsigned x0, unsigned x1,
                                       unsigned* o0, unsigned* o1) {
    unsigned ks0 = k0, ks1 = k1, ks2 = 0x1BD11BDAu ^ k0 ^ k1;
    x0 += ks0; x1 += ks1;
#define TF_RND(r) { x0 += x1; x1 = (x1 << (r)) | (x1 >> (32 - (r))); x1 ^= x0; }
    TF_RND(13) TF_RND(15) TF_RND(26) TF_RND(6)   x0 += ks1; x1 += ks2 + 1u;
    TF_RND(17) TF_RND(29) TF_RND(16) TF_RND(24)  x0 += ks2; x1 += ks0 + 2u;
    TF_RND(13) TF_RND(15) TF_RND(26) TF_RND(6)   x0 += ks0; x1 += ks1 + 3u;
    TF_RND(17) TF_RND(29) TF_RND(16) TF_RND(24)  x0 += ks1; x1 += ks2 + 4u;
    TF_RND(13) TF_RND(15) TF_RND(26) TF_RND(6)   x0 += ks2; x1 += ks0 + 5u;
#undef TF_RND
    *o0 = x0; *o1 = x1;
}

struct IdxKeys { unsigned k0[2], k1[2]; int* out[2]; };
__global__ void idx2_kernel(IdxKeys ik) {
    int i = blockIdx.x * blockDim.x + threadIdx.x;
    if (i >= L_*NS_) return;
    int z = blockIdx.y;
    unsigned o0, o1;
    tf2x32(ik.k0[z], ik.k1[z], 0u, (unsigned)i, &o0, &o1);
    ik.out[z][i] = (int)((o0 ^ o1) & 4095u);
}

// ---------------- bf16-split conversion (MLP=4, both inputs one launch) ----
struct Cvt2 { const float4* src[2]; __nv_bfloat162* hi[2]; __nv_bfloat162* lo[2]; };
__global__ __launch_bounds__(256)
void cvt_pair2_kernel(Cvt2 c, int n4q) {   // n4q = N4/4
    int z = blockIdx.y;
    int i = blockIdx.x * 256 + threadIdx.x;
    if (i >= n4q) return;
    const float4* __restrict__ src = c.src[z];
    __nv_bfloat162* __restrict__ hi = c.hi[z];
    __nv_bfloat162* __restrict__ lo = c.lo[z];
    float4 v[4];
#pragma unroll
    for (int j = 0; j < 4; j++) v[j] = src[i + j * n4q];
#pragma unroll
    for (int j = 0; j < 4; j++) {
        int ii = i + j * n4q;
        float4 w = v[j];
        __nv_bfloat16 h0 = __float2bfloat16(w.x), h1 = __float2bfloat16(w.y);
        __nv_bfloat16 h2 = __float2bfloat16(w.z), h3 = __float2bfloat16(w.w);
        __nv_bfloat16 l0 = __float2bfloat16(w.x - __bfloat162float(h0));
        __nv_bfloat16 l1 = __float2bfloat16(w.y - __bfloat162float(h1));
        __nv_bfloat16 l2 = __float2bfloat16(w.z - __bfloat162float(h2));
        __nv_bfloat16 l3 = __float2bfloat16(w.w - __bfloat162float(h3));
        hi[ii*2]   = __nv_bfloat162(h0, h1);
        hi[ii*2+1] = __nv_bfloat162(h2, h3);
        lo[ii*2]   = __nv_bfloat162(l0, l1);
        lo[ii*2+1] = __nv_bfloat162(l2, l3);
    }
}

struct W4 { const float* w[4]; };
__global__ __launch_bounds__(1024)
void wt_cvt_all_kernel(W4 ws, __nv_bfloat16* __restrict__ hi, __nv_bfloat16* __restrict__ lo) {
    __shared__ float t[32][33];
    int tx = threadIdx.x, ty = threadIdx.y;
    int n0 = blockIdx.x * 32, k0 = blockIdx.y * 32;
    int z = blockIdx.z;
    const float* W = ws.w[z];
    size_t off = (size_t)z * DM_ * DM_;
    t[ty][tx] = W[(size_t)(k0 + ty) * DM_ + n0 + tx];
    __syncthreads();
    float v = t[tx][ty];
    int n = n0 + ty, k = k0 + tx;
    __nv_bfloat16 h = __float2bfloat16(v);
    hi[off + (size_t)n * DM_ + k] = h;
    lo[off + (size_t)n * DM_ + k] = __float2bfloat16(v - __bfloat162float(h));
}

// ---------------- PTX helpers ----------------
__device__ __forceinline__ void cp16s(uint32_t saddr, const void* g) {
    asm volatile("cp.async.cg.shared.global [%0], [%1], 16;\n" :: "r"(saddr), "l"(g));
}
#define CP_COMMIT() asm volatile("cp.async.commit_group;\n" ::: "memory")
#define CP_WAIT(n)  asm volatile("cp.async.wait_group %0;\n" :: "n"(n) : "memory")

__device__ __forceinline__ void ldsm4(uint32_t& r0, uint32_t& r1, uint32_t& r2, uint32_t& r3,
                                      uint32_t saddr) {
    asm volatile("ldmatrix.sync.aligned.m8n8.x4.shared.b16 {%0,%1,%2,%3}, [%4];"
                 : "=r"(r0), "=r"(r1), "=r"(r2), "=r"(r3) : "r"(saddr));
}

__device__ __forceinline__ void mma_bf16(float* c, const uint32_t* a, const uint32_t* b) {
    asm volatile("mma.sync.aligned.m16n8k16.row.col.f32.bf16.bf16.f32 "
                 "{%0,%1,%2,%3}, {%4,%5,%6,%7}, {%8,%9}, {%0,%1,%2,%3};"
                 : "+f"(c[0]), "+f"(c[1]), "+f"(c[2]), "+f"(c[3])
                 : "r"(a[0]), "r"(a[1]), "r"(a[2]), "r"(a[3]), "r"(b[0]), "r"(b[1]));
}

// ---------------- mma.sync bf16-split GEMM (2-stage, 2 CTAs/SM) ------------
#define GST    40960
#define GSMEM  (2048 + 2*GST)

struct GJob { const __nv_bfloat16 *ahi, *alo, *bhi, *blo; const float* bias; float* c; };
struct G4 { GJob j[4]; };

__global__ __launch_bounds__(256, 2)
void gemm_mma4(G4 g4) {
    extern __shared__ char smem[];
    const uint32_t sb = (uint32_t)__cvta_generic_to_shared(smem);
    const int tid = threadIdx.x;
    const int lane = tid & 31, wid = tid >> 5;
    const int warpM = wid >> 2, warpN = wid & 3;
    const int row0 = blockIdx.y * 128, col0 = blockIdx.x * 128;
    GJob jb = g4.j[blockIdx.z];
    const __nv_bfloat16* __restrict__ Ahi = jb.ahi;
    const __nv_bfloat16* __restrict__ Alo = jb.alo;
    const __nv_bfloat16* __restrict__ Bhi = jb.bhi;
    const __nv_bfloat16* __restrict__ Blo = jb.blo;

    float* sbias = (float*)smem;
    if (tid < 128) sbias[tid] = jb.bias[col0 + tid];

    float acc[4][4][4];
#pragma unroll
    for (int i = 0; i < 4; i++)
#pragma unroll
        for (int j = 0; j < 4; j++)
#pragma unroll
            for (int r = 0; r < 4; r++) acc[i][j][r] = 0.f;

    const int a_row = warpM * 64 + (lane & 15);
    const int a_kb  = ((lane >> 4) * 8) * 2;
    const int b_row = warpN * 32 + (lane & 7) + ((lane >> 4) & 1) * 8;
    const int b_kb  = (((lane >> 3) & 1) * 8) * 2;

#define LOAD_CHUNK(c, s) {                                                     \
    uint32_t stb = sb + 2048 + (uint32_t)(s) * GST;                            \
    int k0 = (c) * 32;                                                         \
    _Pragma("unroll")                                                          \
    for (int j = 0; j < 8; j++) {                                              \
        int idx = tid + j * 256;                                               \
        int tile = idx >> 9, w = idx & 511;                                    \
        int r = w >> 2, cc = w & 3;                                            \
        uint32_t so = stb + (uint32_t)tile * 10240u + (uint32_t)(r * 80 + cc * 16); \
        const __nv_bfloat16* gp;                                               \
        if      (tile == 0) gp = Ahi + (size_t)(row0 + r) * DM_ + k0 + cc * 8; \
        else if (tile == 1) gp = Alo + (size_t)(row0 + r) * DM_ + k0 + cc * 8; \
        else if (tile == 2) gp = Bhi + (size_t)(col0 + r) * DM_ + k0 + cc * 8; \
        else                gp = Blo + (size_t)(col0 + r) * DM_ + k0 + cc * 8; \
        cp16s(so, gp);                                                         \
    }                                                                          \
    CP_COMMIT(); }

#define COMPUTE(s) {                                                                 \
    uint32_t stb = sb + 2048 + (uint32_t)(s) * GST;                                  \
    _Pragma("unroll")                                                                \
    for (int k16 = 0; k16 < 2; k16++) {                                             \
        uint32_t ah[4][4], al[4][4], bh[4][2], bl[4][2];                             \
        _Pragma("unroll")                                                            \
        for (int i = 0; i < 4; i++)                                                  \
            ldsm4(ah[i][0], ah[i][1], ah[i][2], ah[i][3],                            \
                  stb + (uint32_t)((a_row + i*16) * 80 + k16*32 + a_kb));            \
        _Pragma("unroll")                                                            \
        for (int n16 = 0; n16 < 2; n16++)                                            \
            ldsm4(bh[n16*2][0], bh[n16*2][1], bh[n16*2+1][0], bh[n16*2+1][1],        \
                  stb + 20480u + (uint32_t)((b_row + n16*16) * 80 + k16*32 + b_kb)); \
        _Pragma("unroll")                                                            \
        for (int i = 0; i < 4; i++)                                                  \
            _Pragma("unroll")                                                        \
            for (int j = 0; j < 4; j++) mma_bf16(acc[i][j], ah[i], bh[j]);           \
        _Pragma("unroll")                                                            \
        for (int n16 = 0; n16 < 2; n16++)                                            \
            ldsm4(bl[n16*2][0], bl[n16*2][1], bl[n16*2+1][0], bl[n16*2+1][1],        \
                  stb + 30720u + (uint32_t)((b_row + n16*16) * 80 + k16*32 + b_kb)); \
        _Pragma("unroll")                                                            \
        for (int i = 0; i < 4; i++)                                                  \
            _Pragma("unroll")                                                        \
            for (int j = 0; j < 4; j++) mma_bf16(acc[i][j], ah[i], bl[j]);           \
        _Pragma("unroll")                                                            \
        for (int i = 0; i < 4; i++)                                                  \
            ldsm4(al[i][0], al[i][1], al[i][2], al[i][3],                            \
                  stb + 10240u + (uint32_t)((a_row + i*16) * 80 + k16*32 + a_kb));   \
        _Pragma("unroll")                                                            \
        for (int i = 0; i < 4; i++)                                                  \
            _Pragma("unroll")                                                        \
            for (int j = 0; j < 4; j++) mma_bf16(acc[i][j], al[i], bh[j]);           \
    } }

    LOAD_CHUNK(0, 0);
    LOAD_CHUNK(1, 1);

    const int nIter = DM_ / 32;   // 16
#pragma unroll 1
    for (int c = 0; c < nIter; c++) {
        if (c == nIter - 1) { CP_WAIT(0); } else { CP_WAIT(1); }
        __syncthreads();
        COMPUTE(c & 1);
        __syncthreads();
        if (c + 2 < nIter) LOAD_CHUNK(c + 2, c & 1);
    }

    __syncthreads();
#pragma unroll
    for (int i = 0; i < 4; i++) {
#pragma unroll
        for (int j = 0; j < 4; j++) {
            int colg = col0 + warpN * 32 + j * 8 + (lane & 3) * 2;
            int hh = colg >> 6, d0 = colg & 63;
            float b0v = sbias[colg - col0], b1v = sbias[colg - col0 + 1];
#pragma unroll
            for (int half = 0; half < 2; half++) {
                int m = row0 + warpM * 64 + i * 16 + (lane >> 2) + half * 8;
                int b = m >> 12, l = m & 4095;
                float2 v;
                v.x = acc[i][j][half*2 + 0] + b0v;
                v.y = acc[i][j][half*2 + 1] + b1v;
                *(float2*)(jb.c + (((size_t)(b * H_ + hh) * L_) + l) * D_ + d0) = v;
            }
        }
    }
#undef LOAD_CHUNK
#undef COMPUTE
}

// ------- T GEMMs: split-K, atomic accumulate directly into g_Tkv -------
struct TW { const float* b[2]; };
__global__ __launch_bounds__(256)
void sgemm_T_part(const float* __restrict__ A, TW tw) {
    __shared__ float As[16][68];
    __shared__ float Bs[16][64];
    int tid = threadIdx.x, tx = tid & 15, ty = tid >> 4;
    int r0 = blockIdx.y * 64, c0 = blockIdx.x * 64;
    int kc = blockIdx.z & 15, which = blockIdx.z >> 4;
    const float* Bm = tw.b[which];
    float acc[4][4];
#pragma unroll
    for (int i = 0; i < 4; i++)
#pragma unroll
        for (int j = 0; j < 4; j++) acc[i][j] = 0.f;

    for (int kt = kc * 32; kt < kc * 32 + 32; kt += 16) {
        int m = tid >> 2, k4 = tid & 3;
        float4 av = *(const float4*)(A + (size_t)(r0 + m) * DM_ + kt + k4 * 4);
        As[k4*4+0][m] = av.x; As[k4*4+1][m] = av.y;
        As[k4*4+2][m] = av.z; As[k4*4+3][m] = av.w;
        int kk = tid >> 4, n4 = tid & 15;
        *(float4*)&Bs[kk][n4 * 4] = *(const float4*)(Bm + (size_t)(kt + kk) * DM_ + c0 + n4 * 4);
        __syncthreads();
#pragma unroll
        for (int k = 0; k < 16; k++) {
            float a[4], b[4];
            *(float4*)a = *(const float4*)&As[k][ty * 4];
            *(float4*)b = *(const float4*)&Bs[k][tx * 4];
#pragma unroll
            for (int i = 0; i < 4; i++)
#pragma unroll
                for (int j = 0; j < 4; j++) acc[i][j] += a[i] * b[j];
        }
        __syncthreads();
    }
    float* dst = g_Tkv + (size_t)which * DM_ * DM_ + (size_t)(r0 + ty * 4) * DM_ + c0 + tx * 4;
#pragma unroll
    for (int i = 0; i < 4; i++) {
        atomicAdd(dst + (size_t)i * DM_ + 0, acc[i][0]);
        atomicAdd(dst + (size_t)i * DM_ + 1, acc[i][1]);
        atomicAdd(dst + (size_t)i * DM_ + 2, acc[i][2]);
        atomicAdd(dst + (size_t)i * DM_ + 3, acc[i][3]);
    }
}

// ---------------- layer-0 sample_m (dense K) ----------------
__global__ __launch_bounds__(256)
void sample_m_kernel(const int* __restrict__ idx) {
    int gw = (blockIdx.x * blockDim.x + threadIdx.x) >> 5;
    int lane = threadIdx.x & 31;
    if (gw >= BH_ * L_) return;
    int bh = gw >> 12, l = gw & 4095;
    const float4* qrow = (const float4*)(g_Q + ((size_t)bh * L_ + l) * D_);
    float val = 0.f;
    bool active = lane < NS_;
    if (active) {
        int kk = idx[l * NS_ + lane];
        const float4* krow = (const float4*)(g_K + ((size_t)bh * L_ + kk) * D_);
        float s = 0.f;
#pragma unroll
        for (int d4 = 0; d4 < 16; d4++) {
            float4 q = qrow[d4], k = krow[d4];
            s += q.x*k.x + q.y*k.y + q.z*k.z + q.w*k.w;
        }
        val = s;
    }
    float mx = active ? val : -__int_as_float(0x7f800000);
    float sm = active ? val : 0.f;
#pragma unroll
    for (int off = 16; off > 0; off >>= 1) {
        mx = fmaxf(mx, __shfl_down_sync(0xffffffffu, mx, off));
        sm += __shfl_down_sync(0xffffffffu, sm, off);
    }
    if (lane == 0) g_M[gw] = mx - sm * (1.f / (float)L_);
}

// ---------------- layer-1 sample_m (low-rank K1, Q from g_Q1) --------------
__global__ __launch_bounds__(256)
void sample_m1_kernel(const int* __restrict__ idx) {
    int gw = (blockIdx.x * blockDim.x + threadIdx.x) >> 5;
    int lane = threadIdx.x & 31;
    if (gw >= BH_ * L_) return;
    int bh = gw >> 12, l = gw & 4095;
    int b = bh >> 3, h = bh & 7;
    const float4* qrow = (const float4*)(g_Q1 + ((size_t)bh * L_ + l) * D_);
    const float4* brow = (const float4*)(g_basekv + (size_t)b * DM_ + h * D_);
    bool active = lane < NS_;
    int j = -1;
    if (active) {
        int kk = idx[l * NS_ + lane];
        j = g_map[b * L_ + kk];
    }
    float s = 0.f;
#pragma unroll
    for (int d4 = 0; d4 < 16; d4++) {
        float4 q = qrow[d4], bb = brow[d4];
        s += q.x*bb.x + q.y*bb.y + q.z*bb.z + q.w*bb.w;
    }
    if (j >= 0) {
        const float4* crow = (const float4*)(g_ckK + ((size_t)(b * SLOTS + j)) * DM_ + h * D_);
#pragma unroll
        for (int d4 = 0; d4 < 16; d4++) {
            float4 q = qrow[d4], c = crow[d4];
            s += q.x*c.x + q.y*c.y + q.z*c.z + q.w*c.w;
        }
    }
    float val = s;
    float mx = active ? val : -__int_as_float(0x7f800000);
    float sm = active ? val : 0.f;
#pragma unroll
    for (int off = 16; off > 0; off >>= 1) {
        mx = fmaxf(mx, __shfl_down_sync(0xffffffffu, mx, off));
        sm += __shfl_down_sync(0xffffffffu, sm, off);
    }
    if (lane == 0) g_M[gw] = mx - sm * (1.f / (float)L_);
}

// ---------------- top-27: cached per-thread max keys ----------------
__device__ __forceinline__ unsigned ordf(float v) {
    unsigned u = __float_as_uint(v);
    return (u & 0x80000000u) ? ~u : (u | 0x80000000u);
}

__global__ __launch_bounds__(256)
void topk_kernel() {
    int bh = blockIdx.x, t = threadIdx.x;
    int lane = t & 31, wid = t >> 5;
    __shared__ float sm[L_];
    __shared__ unsigned long long wred[8];
    __shared__ unsigned long long sbest;
    for (int i = t; i < L_; i += 256) sm[i] = g_M[(size_t)bh * L_ + i];
    __syncthreads();

    const int base = t * 16;
    unsigned long long myKey = 0ull;
#pragma unroll
    for (int i = 0; i < 16; i++) {
        unsigned long long key = ((unsigned long long)ordf(sm[base + i]) << 32)
                               | (unsigned)(L_ - 1 - (base + i));
        if (key > myKey) myKey = key;
    }

    for (int it = 0; it < NS_; it++) {
        unsigned long long b = myKey;
#pragma unroll
        for (int off = 16; off > 0; off >>= 1) {
            unsigned long long o = __shfl_down_sync(0xffffffffu, b, off);
            if (o > b) b = o;
        }
        if (lane == 0) wred[wid] = b;
        __syncthreads();
        if (t == 0) {
            unsigned long long b2 = wred[0];
#pragma unroll
            for (int w = 1; w < 8; w++) if (wred[w] > b2) b2 = wred[w];
            sbest = b2;
            g_topidx[bh * NS_ + it] = L_ - 1 - (int)(b2 & 0xFFFFFFFFull);
        }
        __syncthreads();
        int gi = L_ - 1 - (int)(sbest & 0xFFFFFFFFull);
        if ((gi >> 4) == t) {
            sm[gi] = -__int_as_float(0x7f800000);
            unsigned long long nk = 0ull;
#pragma unroll
            for (int i = 0; i < 16; i++) {
                unsigned long long key = ((unsigned long long)ordf(sm[base + i]) << 32)
                                       | (unsigned)(L_ - 1 - (base + i));
                if (key > nk) nk = key;
            }
            myKey = nk;
        }
    }
}

// ---------------- layer-0 meanV: two-stage ----------------
__global__ __launch_bounds__(256)
void meanv1_kernel() {
    int bh = blockIdx.x, c = blockIdx.y, t = threadIdx.x;
    int d = t & 63, r = t >> 6;
    float s = 0.f;
    int base = c * 256;
    for (int l = base + r; l < base + 256; l += 4)
        s += g_V[((size_t)bh * L_ + l) * D_ + d];
    __shared__ float red[256];
    red[t] = s; __syncthreads();
    if (t < 64)
        g_vpart[(bh * 16 + c) * D_ + d] = red[d] + red[64+d] + red[128+d] + red[192+d];
}

__global__ __launch_bounds__(64)
void meanv2_kernel() {
    int bh = blockIdx.x, d = threadIdx.x;
    float s = 0.f;
#pragma unroll
    for (int c = 0; c < 16; c++) s += g_vpart[(bh * 16 + c) * D_ + d];
    g_meanV[bh * D_ + d] = s * (1.f / (float)L_);
}

// ---------------- layer-1 meanV (low-rank) ----------------
__global__ __launch_bounds__(64)
void meanv1b_kernel() {
    int bh = blockIdx.x, t = threadIdx.x;
    int b = bh >> 3, h = bh & 7;
    int cnt = g_cnt[b];
    float s = 0.f;
    for (int j = 0; j < cnt; j++)
        s += g_ckV[((size_t)(b * SLOTS + j)) * DM_ + h * D_ + t];
    g_meanV[bh * D_ + t] = g_basekv[(size_t)(B_ + b) * DM_ + h * D_ + t] + s * (1.f / (float)L_);
}

// ---------------- layer-0 fused scores+softmax+pv ----------------
#define ATT_SMEM ((NS_*CH + 64*129 + NS_*64 + 64) * 4)
__global__ __launch_bounds__(256, 2)
void att_fused_kernel() {
    extern __shared__ float smf[];
    float* sS   = smf;
    float* KsT  = smf + NS_ * CH;
    float* sQ   = KsT + 64 * 129;

    int bh = blockIdx.x, ch = blockIdx.y, t = threadIdx.x;
    int lane = t & 31, w = t >> 5;
    int l0 = ch * CH;

    for (int f = t; f < NS_ * 16; f += 256) {
        int u = f >> 4, d4 = f & 15;
        int l = g_topidx[bh * NS_ + u];
        *(float4*)&sQ[u * 64 + d4 * 4] =
            *(const float4*)(g_Q + ((size_t)bh * L_ + l) * D_ + d4 * 4);
    }

    const int ubeg = (t >> 7) ? 14 : 0;
    const int ucnt = (t >> 7) ? 13 : 14;
    const int kk = t & 127;
#pragma unroll 1
    for (int st = 0; st < CH / 128; st++) {
        __syncthreads();
        for (int f = t; f < 128 * 16; f += 256) {
            int kr = f >> 4, d4 = f & 15;
            float4 v = *(const float4*)(g_K + ((size_t)bh * L_ + l0 + st * 128 + kr) * D_ + d4 * 4);
            KsT[(d4*4+0) * 129 + kr] = v.x; KsT[(d4*4+1) * 129 + kr] = v.y;
            KsT[(d4*4+2) * 129 + kr] = v.z; KsT[(d4*4+3) * 129 + kr] = v.w;
        }
        __syncthreads();
        float acc[14];
#pragma unroll
        for (int i = 0; i < 14; i++) acc[i] = 0.f;
#pragma unroll
        for (int d0 = 0; d0 < 64; d0 += 4) {
            float k0 = KsT[d0*129 + kk], k1 = KsT[(d0+1)*129 + kk];
            float k2 = KsT[(d0+2)*129 + kk], k3 = KsT[(d0+3)*129 + kk];
#pragma unroll
            for (int i = 0; i < 14; i++) {
                if (i < ucnt) {
                    float4 q = *(const float4*)&sQ[(ubeg + i) * 64 + d0];
                    acc[i] += q.x*k0 + q.y*k1 + q.z*k2 + q.w*k3;
                }
            }
        }
#pragma unroll
        for (int i = 0; i < 14; i++)
            if (i < ucnt) sS[(ubeg + i) * CH + st * 128 + kk] = acc[i] * 0.125f;
    }
    __syncthreads();

    for (int u = w; u < NS_; u += 8) {
        float mx = -__int_as_float(0x7f800000);
#pragma unroll
        for (int j = 0; j < CH / 32; j++)
            mx = fmaxf(mx, sS[u * CH + lane + j * 32]);
#pragma unroll
        for (int off = 16; off > 0; off >>= 1)
            mx = fmaxf(mx, __shfl_xor_sync(0xffffffffu, mx, off));
        float ss = 0.f;
#pragma unroll
        for (int j = 0; j < CH / 32; j++) {
            float e = __expf(sS[u * CH + lane + j * 32] - mx);
            sS[u * CH + lane + j * 32] = e;
            ss += e;
        }
#pragma unroll
        for (int off = 16; off > 0; off >>= 1)
            ss += __shfl_xor_sync(0xffffffffu, ss, off);
        if (lane == 0) {
            int pi = (bh * NCH + ch) * NS_ + u;
            g_attM[pi] = mx;
            g_attS[pi] = ss;
        }
    }
    __syncthreads();

    int d = t & 63, ug = t >> 6;
    float acc[7];
#pragma unroll
    for (int j = 0; j < 7; j++) acc[j] = 0.f;
    for (int k = 0; k < CH; k += 4) {
        float v0 = g_V[((size_t)bh * L_ + l0 + k + 0) * D_ + d];
        float v1 = g_V[((size_t)bh * L_ + l0 + k + 1) * D_ + d];
        float v2 = g_V[((size_t)bh * L_ + l0 + k + 2) * D_ + d];
        float v3 = g_V[((size_t)bh * L_ + l0 + k + 3) * D_ + d];
#pragma unroll
        for (int j = 0; j < 7; j++) {
            int u = ug + j * 4;
            if (u < NS_) {
                float4 p = *(const float4*)&sS[u * CH + k];
                acc[j] += p.x*v0 + p.y*v1 + p.z*v2 + p.w*v3;
            }
        }
    }
#pragma unroll
    for (int j = 0; j < 7; j++) {
        int u = ug + j * 4;
        if (u < NS_)
            g_attO[((size_t)(bh * NCH + ch) * NS_ + u) * D_ + d] = acc[j];
    }
}

__global__ __launch_bounds__(64)
void att_combine_kernel() {
    int bu = blockIdx.x;
    int bh = bu / NS_, u = bu % NS_;
    int d = threadIdx.x;
    float m = -__int_as_float(0x7f800000);
#pragma unroll
    for (int c = 0; c < NCH; c++)
        m = fmaxf(m, g_attM[(bh * NCH + c) * NS_ + u]);
    float s = 0.f, o = 0.f;
#pragma unroll
    for (int c = 0; c < NCH; c++) {
        int pi = (bh * NCH + c) * NS_ + u;
        float wgt = __expf(g_attM[pi] - m);
        s += wgt * g_attS[pi];
        o += wgt * g_attO[(size_t)pi * D_ + d];
    }
    g_outtop[(bh * NS_ + u) * D_ + d] = o / s;
}

// ---------------- layer-1 attention over low-rank K1/V1 ----------------
__global__ __launch_bounds__(256)
void att1_fused_kernel() {
    __shared__ float sQ[64];
    __shared__ float sS[SLOTS];
    __shared__ float red[256];
    __shared__ float sstat[2];
    int bu = blockIdx.x;
    int bh = bu / NS_, u = bu % NS_;
    int b = bh >> 3, h = bh & 7;
    int t = threadIdx.x;
    int cnt = g_cnt[b];
    int lsel = g_topidx[bh * NS_ + u];
    if (t < 64) sQ[t] = g_Q1[((size_t)bh * L_ + lsel) * D_ + t];
    __syncthreads();

    if (t < 32) {
        float p = sQ[t] * g_basekv[(size_t)b * DM_ + h * D_ + t]
                + sQ[t + 32] * g_basekv[(size_t)b * DM_ + h * D_ + t + 32];
#pragma unroll
        for (int off = 16; off > 0; off >>= 1)
            p += __shfl_xor_sync(0xffffffffu, p, off);
        if (t == 0) sstat[0] = 0.125f * p;
    }
    __syncthreads();
    float qb = sstat[0];

    float sj = -__int_as_float(0x7f800000);
    if (t < cnt) {
        const float4* c = (const float4*)(g_ckK + ((size_t)(b * SLOTS + t)) * DM_ + h * D_);
        float dot = 0.f;
#pragma unroll
        for (int d4 = 0; d4 < 16; d4++) {
            float4 cv = c[d4];
            dot += sQ[d4*4]*cv.x + sQ[d4*4+1]*cv.y + sQ[d4*4+2]*cv.z + sQ[d4*4+3]*cv.w;
        }
        sj = qb + 0.125f * dot;
        sS[t] = sj;
    }
    red[t] = sj;
    __syncthreads();
    for (int s = 128; s > 0; s >>= 1) {
        if (t < s) red[t] = fmaxf(red[t], red[t + s]);
        __syncthreads();
    }
    float m = fmaxf(red[0], qb);
    __syncthreads();

    float e = 0.f;
    if (t < cnt) { e = __expf(sS[t] - m); sS[t] = e; }
    red[t] = e;
    __syncthreads();
    for (int s = 128; s > 0; s >>= 1) {
        if (t < s) red[t] += red[t + s];
        __syncthreads();
    }
    if (t == 0)
        sstat[1] = 1.f / (red[0] + (float)(L_ - cnt) * __expf(qb - m));
    __syncthreads();
    float inv = sstat[1];

    if (t < 64) {
        float o = 0.f;
        for (int j = 0; j < cnt; j++)
            o += sS[j] * g_ckV[((size_t)(b * SLOTS + j)) * DM_ + h * D_ + t];
        o = o * inv + g_basekv[(size_t)(B_ + b) * DM_ + h * D_ + t];
        g_outtop[(bh * NS_ + u) * D_ + t] = o;
    }
}

// ---------------- map build ----------------
__global__ void mark_kernel() {
    int i = threadIdx.x;
    if (i < BH_ * NS_) {
        int bh = i / NS_;
        int b = bh >> 3;
        g_map[b * L_ + g_topidx[i]] = 1;
    }
}

__global__ __launch_bounds__(256)
void slot_assign_kernel() {
    int b = blockIdx.x, t = threadIdx.x;
    __shared__ int cs[256];
    int base = t * 16;
    int c = 0;
#pragma unroll
    for (int i = 0; i < 16; i++)
        if (g_map[b * L_ + base + i] == 1) c++;
    cs[t] = c;
    __syncthreads();
    for (int off = 1; off < 256; off <<= 1) {
        int v = (t >= off) ? cs[t - off] : 0;
        __syncthreads();
        cs[t] += v;
        __syncthreads();
    }
    int slot = cs[t] - c;
#pragma unroll
    for (int i = 0; i < 16; i++) {
        if (g_map[b * L_ + base + i] == 1)
            g_map[b * L_ + base + i] = slot++;
    }
    if (t == 255) g_cnt[b] = cs[255];
}

__global__ __launch_bounds__(128)
void corr_compact_kernel() {
    int blk = blockIdx.x, z = blockIdx.y;
    int bh0 = blk / NS_, u = blk % NS_;
    int b = bh0 >> 3, h0 = bh0 & 7;
    int t = threadIdx.x;
    __shared__ float qv[64];
    if (t < 64) qv[t] = g_outtop[(bh0 * NS_ + u) * 64 + t] - g_meanV[bh0 * 64 + t];
    __syncthreads();
    const float* T = g_Tkv + (size_t)z * DM_ * DM_;
    int l = g_topidx[bh0 * NS_ + u];
    int slot = g_map[b * L_ + l];
    float a0 = 0.f, a1 = 0.f, a2 = 0.f, a3 = 0.f;
#pragma unroll 8
    for (int k = 0; k < 64; k++) {
        float q = qv[k];
        float4 wv = *(const float4*)(T + (size_t)(h0 * 64 + k) * DM_ + t * 4);
        a0 += q * wv.x; a1 += q * wv.y; a2 += q * wv.z; a3 += q * wv.w;
    }
    float* dst = (z ? g_ckV : g_ckK) + ((size_t)(b * SLOTS + slot)) * DM_ + t * 4;
    atomicAdd(dst + 0, a0); atomicAdd(dst + 1, a1);
    atomicAdd(dst + 2, a2); atomicAdd(dst + 3, a3);
}

// ---------------- generic GEMV: partials then combine ----------------
__global__ __launch_bounds__(512)
void base1g_kernel(const float* __restrict__ invec, const float* __restrict__ w) {
    int b = blockIdx.x, kc = blockIdx.y, n = threadIdx.x;
    __shared__ float mc[64];
    if (n < 64) mc[n] = invec[b * DM_ + kc * 64 + n];
    __syncthreads();
    float s = 0.f;
#pragma unroll 8
    for (int k = 0; k < 64; k++) s += mc[k] * w[(size_t)(kc * 64 + k) * DM_ + n];
    g_basep[(b * 8 + kc) * DM_ + n] = s;
}

__global__ __launch_bounds__(512)
void base2g_kernel(const float* __restrict__ bias, float* __restrict__ outv) {
    int b = blockIdx.x, n = threadIdx.x;
    float s = bias[n];
#pragma unroll
    for (int p = 0; p < 8; p++) s += g_basep[(b * 8 + p) * DM_ + n];
    outv[b * DM_ + n] = s;
}

struct KV2 { const float* w[2]; const float* bias[2]; };
__global__ __launch_bounds__(512)
void basekv1_kernel(const float* __restrict__ invec, KV2 kv) {
    int b = blockIdx.x, kc = blockIdx.y, z = blockIdx.z, n = threadIdx.x;
    __shared__ float mc[64];
    if (n < 64) mc[n] = invec[b * DM_ + kc * 64 + n];
    __syncthreads();
    const float* w = kv.w[z];
    float s = 0.f;
#pragma unroll 8
    for (int k = 0; k < 64; k++) s += mc[k] * w[(size_t)(kc * 64 + k) * DM_ + n];
    g_basep2[((z * B_ + b) * 8 + kc) * DM_ + n] = s;
}

__global__ __launch_bounds__(512)
void basekv2_kernel(KV2 kv) {
    int b = blockIdx.x, z = blockIdx.y, n = threadIdx.x;
    float s = kv.bias[z][n];
#pragma unroll
    for (int p = 0; p < 8; p++) s += g_basep2[((z * B_ + b) * 8 + p) * DM_ + n];
    g_basekv[(z * B_ + b) * DM_ + n] = s;
}

// ---------------- output broadcasts ----------------
__global__ __launch_bounds__(256)
void bcast_out_kernel(const float* __restrict__ xs, float* __restrict__ out,
                      const float* __restrict__ basev, int row_off) {
    int i4 = blockIdx.x * 256 + threadIdx.x;
    int n4 = i4 & 127;
    int l = (i4 >> 7) & 4095;
    int b = i4 / (L_ * 128);
    size_t oi = ((size_t)(b * 8192 + row_off + l)) * 128 + n4;
    float4 a = ((const float4*)xs)[oi];
    float4 s = ((const float4*)basev)[b * 128 + n4];
    a.x += s.x; a.y += s.y; a.z += s.z; a.w += s.w;
    ((float4*)out)[oi] = a;
}

__global__ __launch_bounds__(128)
void corr_kernel(const float* __restrict__ wo, float* __restrict__ dst, int row_off) {
    int blk = blockIdx.x;
    int bh = blk / NS_, u = blk % NS_;
    int b = bh >> 3, h = bh & 7;
    int t = threadIdx.x;
    __shared__ float qv[64];
    if (t < 64) qv[t] = g_outtop[(bh * NS_ + u) * 64 + t] - g_meanV[bh * 64 + t];
    __syncthreads();
    int l = g_topidx[bh * NS_ + u];
    float a0 = 0.f, a1 = 0.f, a2 = 0.f, a3 = 0.f;
#pragma unroll 8
    for (int k = 0; k < 64; k++) {
        float q = qv[k];
        float4 wv = *(const float4*)(wo + (size_t)(h * 64 + k) * DM_ + t * 4);
        a0 += q * wv.x; a1 += q * wv.y; a2 += q * wv.z; a3 += q * wv.w;
    }
    float* d = dst + ((size_t)(b * 8192 + row_off + l)) * DM_ + t * 4;
    atomicAdd(d + 0, a0); atomicAdd(d + 1, a1);
    atomicAdd(d + 2, a2); atomicAdd(d + 3, a3);
}

// ---------------- host orchestration ----------------
extern "C" void kernel_launch(void* const* d_in, const int* in_sizes, int n_in,
                              void* d_out, int out_size) {
    const float* xs  = (const float*)d_in[0];
    const float* xd  = (const float*)d_in[1];
    const float* xp  = (const float*)d_in[2];
    const float* w0q = (const float*)d_in[3];
    const float* w0k = (const float*)d_in[4];
    const float* w0v = (const float*)d_in[5];
    const float* w0o = (const float*)d_in[6];
    const float* b0q = (const float*)d_in[7];
    const float* b0k = (const float*)d_in[8];
    const float* b0v = (const float*)d_in[9];
    const float* b0o = (const float*)d_in[10];
    const float* w1q = (const float*)d_in[11];
    const float* w1k = (const float*)d_in[12];
    const float* w1v = (const float*)d_in[13];
    const float* w1o = (const float*)d_in[14];
    const float* b1q = (const float*)d_in[15];
    const float* b1k = (const float*)d_in[16];
    const float* b1v = (const float*)d_in[17];
    const float* b1o = (const float*)d_in[18];
    float* out = (float*)d_out;

    float *pQ, *pQ1, *pK, *pV, *pmv, *pb0, *pb1, *pckK, *pckV, *pTkv;
    int *pidxA, *pidxB, *pmap, *pcnt;
    __nv_bfloat16 *pAxdH, *pAxdL, *pAxpH, *pAxpL, *pWtH, *pWtL;
    cudaGetSymbolAddress((void**)&pQ, g_Q);
    cudaGetSymbolAddress((void**)&pQ1, g_Q1);
    cudaGetSymbolAddress((void**)&pK, g_K);
    cudaGetSymbolAddress((void**)&pV, g_V);
    cudaGetSymbolAddress((void**)&pmv, g_meanV);
    cudaGetSymbolAddress((void**)&pb0, g_base0);
    cudaGetSymbolAddress((void**)&pb1, g_base1);
    cudaGetSymbolAddress((void**)&pckK, g_ckK);
    cudaGetSymbolAddress((void**)&pckV, g_ckV);
    cudaGetSymbolAddress((void**)&pTkv, g_Tkv);
    cudaGetSymbolAddress((void**)&pmap, g_map);
    cudaGetSymbolAddress((void**)&pcnt, g_cnt);
    cudaGetSymbolAddress((void**)&pidxA, g_idxA);
    cudaGetSymbolAddress((void**)&pidxB, g_idxB);
    cudaGetSymbolAddress((void**)&pAxdH, g_Axd_hi);
    cudaGetSymbolAddress((void**)&pAxdL, g_Axd_lo);
    cudaGetSymbolAddress((void**)&pAxpH, g_Axp_hi);
    cudaGetSymbolAddress((void**)&pAxpL, g_Axp_lo);
    cudaGetSymbolAddress((void**)&pWtH, g_Wt_hi);
    cudaGetSymbolAddress((void**)&pWtL, g_Wt_lo);

    cudaFuncSetAttribute(gemm_mma4, cudaFuncAttributeMaxDynamicSharedMemorySize, GSMEM);
    cudaFuncSetAttribute(att_fused_kernel, cudaFuncAttributeMaxDynamicSharedMemorySize, ATT_SMEM);

    // scratch init
    cudaMemsetAsync(pmap, 0xFF, (size_t)B_ * L_ * sizeof(int));
    cudaMemsetAsync(pcnt, 0, B_ * sizeof(int));
    cudaMemsetAsync(pckK, 0, (size_t)B_ * SLOTS * DM_ * sizeof(float));
    cudaMemsetAsync(pckV, 0, (size_t)B_ * SLOTS * DM_ * sizeof(float));
    cudaMemsetAsync(pTkv, 0, (size_t)2 * DM_ * DM_ * sizeof(float));

    {
        unsigned a42, b42, a43, b43;
        tf2x32(0u, 42u, 0u, 1u, &a42, &b42);
        tf2x32(0u, 43u, 0u, 1u, &a43, &b43);
        IdxKeys ik;
        ik.k0[0] = a42; ik.k1[0] = b42; ik.out[0] = pidxA;
        ik.k0[1] = a43; ik.k1[1] = b43; ik.out[1] = pidxB;
        idx2_kernel<<<dim3((L_ * NS_ + 255) / 256, 2), 256>>>(ik);
    }

    W4 ws;
    ws.w[0] = w0q; ws.w[1] = w0k; ws.w[2] = w0v; ws.w[3] = w1q;
    wt_cvt_all_kernel<<<dim3(16, 16, 4), dim3(32, 32)>>>(ws, pWtH, pWtL);

    // T = Wo0 @ W1{k,v}: split-K with direct atomic accumulation
    TW tw; tw.b[0] = w1k; tw.b[1] = w1v;
    sgemm_T_part<<<dim3(8, 8, 32), 256>>>(w0o, tw);

    const int N4 = BL_ * DM_ / 4;     // 2097152
    const int N4Q = N4 / 4;           // 524288
    {
        Cvt2 c;
        c.src[0] = (const float4*)xd; c.src[1] = (const float4*)xp;
        c.hi[0] = (__nv_bfloat162*)pAxdH; c.hi[1] = (__nv_bfloat162*)pAxpH;
        c.lo[0] = (__nv_bfloat162*)pAxdL; c.lo[1] = (__nv_bfloat162*)pAxpL;
        cvt_pair2_kernel<<<dim3(N4Q / 256, 2), 256>>>(c, N4Q);
    }

    // ---- ALL 4 dense GEMMs in one launch (Q0, K0, V0, Q1) ----
    {
        G4 g4;
        size_t WS = (size_t)DM_ * DM_;
        g4.j[0].ahi = pAxpH; g4.j[0].alo = pAxpL; g4.j[0].bhi = pWtH + 0*WS; g4.j[0].blo = pWtL + 0*WS; g4.j[0].bias = b0q; g4.j[0].c = pQ;
        g4.j[1].ahi = pAxdH; g4.j[1].alo = pAxdL; g4.j[1].bhi = pWtH + 1*WS; g4.j[1].blo = pWtL + 1*WS; g4.j[1].bias = b0k; g4.j[1].c = pK;
        g4.j[2].ahi = pAxdH; g4.j[2].alo = pAxdL; g4.j[2].bhi = pWtH + 2*WS; g4.j[2].blo = pWtL + 2*WS; g4.j[2].bias = b0v; g4.j[2].c = pV;
        g4.j[3].ahi = pAxdH; g4.j[3].alo = pAxdL; g4.j[3].bhi = pWtH + 3*WS; g4.j[3].blo = pWtL + 3*WS; g4.j[3].bias = b1q; g4.j[3].c = pQ1;
        gemm_mma4<<<dim3(DM_ / 128, BL_ / 128, 4), 256, GSMEM>>>(g4);
    }

    // ---- layer 0 attention ----
    sample_m_kernel<<<(BH_ * L_) / 8, 256>>>(pidxA);
    topk_kernel<<<BH_, 256>>>();
    meanv1_kernel<<<dim3(BH_, 16), 256>>>();
    meanv2_kernel<<<BH_, 64>>>();
    att_fused_kernel<<<dim3(BH_, NCH), 256, ATT_SMEM>>>();
    att_combine_kernel<<<BH_ * NS_, 64>>>();

    // base0 = meanctx0 @ Wo0 + bo0
    base1g_kernel<<<dim3(B_, 8), 512>>>(pmv, w0o);
    base2g_kernel<<<B_, 512>>>(b0o, pb0);

    // output upper half (xp2)
    bcast_out_kernel<<<(B_ * L_ * 128) / 256, 256>>>(xs, out, pb0, 4096);
    corr_kernel<<<BH_ * NS_, 128>>>(w0o, out, 4096);

    // ---- compact low-rank K1/V1 ----
    mark_kernel<<<1, BH_ * NS_>>>();
    slot_assign_kernel<<<B_, 256>>>();
    corr_compact_kernel<<<dim3(BH_ * NS_, 2), 128>>>();
    {
        KV2 kv;
        kv.w[0] = w1k; kv.w[1] = w1v;
        kv.bias[0] = b1k; kv.bias[1] = b1v;
        basekv1_kernel<<<dim3(B_, 8, 2), 512>>>(pb0, kv);
        basekv2_kernel<<<dim3(B_, 2), 512>>>(kv);
    }

    // ---- layer 1 attention (low-rank K1/V1, Q from g_Q1) ----
    sample_m1_kernel<<<(BH_ * L_) / 8, 256>>>(pidxB);
    topk_kernel<<<BH_, 256>>>();
    meanv1b_kernel<<<BH_, 64>>>();
    att1_fused_kernel<<<BH_ * NS_, 256>>>();

    // base1 + output lower half (xd2)
    base1g_kernel<<<dim3(B_, 8), 512>>>(pmv, w1o);
    base2g_kernel<<<B_, 512>>>(b1o, pb1);
    bcast_out_kernel<<<(B_ * L_ * 128) / 256, 256>>>(xs, out, pb1, 0);
    corr_kernel<<<BH_ * NS_, 128>>>(w1o, out, 0);
}